// round 8
// baseline (speedup 1.0000x reference)
#include <cuda_runtime.h>
#include <cuda_fp16.h>
#include <cstdint>
#include <cstddef>

#define NPTS 65536
#define BB 4
#define CC 512
#define C3 1536
#define KK 256
#define HH 8
#define DH 64
#define NCH 256   // NPTS/KK

// ---------------- scratch (static device globals; no allocation) ----------------
__device__ float g_qkv[(size_t)NPTS * C3];     // gathered qkv, serialized order (fp32)
__device__ float g_clsqkv[BB * C3];            // cls token qkv
__device__ float g_clspart[NCH * CC];          // per-chunk cls attention row
__device__ __half g_Ah[(size_t)NPTS * CC];     // gathered feat hi (fp16)
__device__ __half g_Al[(size_t)NPTS * CC];     // gathered feat lo
__device__ __half g_att_h[(size_t)NPTS * CC];  // attention out hi (serialized)
__device__ __half g_att_l[(size_t)NPTS * CC];  // attention out lo
__device__ __half g_WqkvT[(size_t)C3 * CC];    // W^T fp16
__device__ __half g_WprojT[(size_t)CC * CC];

// =============== helpers ===============
__device__ __forceinline__ uint32_t smem_u32(const void* p) {
    uint32_t a;
    asm("{ .reg .u64 t; cvta.to.shared.u64 t, %1; cvt.u32.u64 %0, t; }" : "=r"(a) : "l"(p));
    return a;
}
__device__ __forceinline__ void ldsm_x4(uint32_t* r, uint32_t addr) {
    asm volatile("ldmatrix.sync.aligned.m8n8.x4.shared.b16 {%0,%1,%2,%3}, [%4];"
                 : "=r"(r[0]), "=r"(r[1]), "=r"(r[2]), "=r"(r[3]) : "r"(addr));
}
__device__ __forceinline__ void ldsm_x2(uint32_t* r, uint32_t addr) {
    asm volatile("ldmatrix.sync.aligned.m8n8.x2.shared.b16 {%0,%1}, [%2];"
                 : "=r"(r[0]), "=r"(r[1]) : "r"(addr));
}
__device__ __forceinline__ void ldsm_x2_t(uint32_t* r, uint32_t addr) {
    asm volatile("ldmatrix.sync.aligned.m8n8.x2.trans.shared.b16 {%0,%1}, [%2];"
                 : "=r"(r[0]), "=r"(r[1]) : "r"(addr));
}
__device__ __forceinline__ void mma_f16(float* c, const uint32_t* a, const uint32_t* b) {
    asm volatile(
        "mma.sync.aligned.m16n8k16.row.col.f32.f16.f16.f32 "
        "{%0,%1,%2,%3}, {%4,%5,%6,%7}, {%8,%9}, {%0,%1,%2,%3};"
        : "+f"(c[0]), "+f"(c[1]), "+f"(c[2]), "+f"(c[3])
        : "r"(a[0]), "r"(a[1]), "r"(a[2]), "r"(a[3]), "r"(b[0]), "r"(b[1]));
}
__device__ __forceinline__ uint32_t split_pack_h(float x, float y, uint32_t* lo) {
    __half2 hh = __floats2half2_rn(x, y);
    __half2 ll = __floats2half2_rn(x - __low2float(hh), y - __high2float(hh));
    *lo = *reinterpret_cast<uint32_t*>(&ll);
    return *reinterpret_cast<uint32_t*>(&hh);
}
__device__ __forceinline__ void cp_async16(uint32_t dst, const void* src) {
    asm volatile("cp.async.cg.shared.global [%0], [%1], 16;" :: "r"(dst), "l"(src) : "memory");
}
#define CP_COMMIT() asm volatile("cp.async.commit_group;" ::: "memory")
#define CP_WAIT1()  asm volatile("cp.async.wait_group 1;" ::: "memory")

// ---------------- W transpose to fp16 ----------------
__global__ __launch_bounds__(256)
void conv_wt_kernel(const float* __restrict__ W, __half* __restrict__ T, int K, int N)
{
    __shared__ float t[32][33];
    int n0 = blockIdx.x * 32, k0 = blockIdx.y * 32;
    int tx = threadIdx.x & 31, ty = threadIdx.x >> 5;
    #pragma unroll
    for (int j = 0; j < 32; j += 8)
        t[ty + j][tx] = W[(size_t)(k0 + ty + j) * N + n0 + tx];
    __syncthreads();
    #pragma unroll
    for (int j = 0; j < 32; j += 8) {
        int n = n0 + ty + j, k = k0 + tx;
        T[(size_t)n * K + k] = __float2half_rn(t[tx][ty + j]);
    }
}

// ---------------- feat gather + fp16 split ----------------
__global__ __launch_bounds__(256)
void conv_feat_kernel(const float* __restrict__ feat, const int* __restrict__ order)
{
    size_t idx = (size_t)blockIdx.x * 256 + threadIdx.x;
    int m = (int)(idx >> 7);
    int u = (int)(idx & 127);
    const float4 v = *(const float4*)(feat + (size_t)order[m] * CC + u * 4);
    uint32_t l01, l23;
    uint32_t h01 = split_pack_h(v.x, v.y, &l01);
    uint32_t h23 = split_pack_h(v.z, v.w, &l23);
    *(uint2*)(g_Ah + (size_t)m * CC + u * 4) = make_uint2(h01, h23);
    *(uint2*)(g_Al + (size_t)m * CC + u * 4) = make_uint2(l01, l23);
}

// ---- cp.async GEMM: 128x128 tile, Kc=64, reg-double-buffered frags, fp16 2-term ----
#define QROWB  144
#define QTILE  (128 * QROWB)       // 18432
#define QSTAGE (3 * QTILE)         // 55296 (Ah | Al | Bh)
#define SMHDR  1024
#define GSMEM  (SMHDR + 3 * QSTAGE)   // 166912

template<bool SCATTER>
__global__ __launch_bounds__(256, 1)
void gemm_async_kernel(const __half* __restrict__ Ah, const __half* __restrict__ Al,
                       const __half* __restrict__ Bh,
                       const float* __restrict__ bias, float* __restrict__ C,
                       const int* __restrict__ order, int Ntot)
{
    extern __shared__ char sm[];
    const uint32_t sb = smem_u32(sm);
    const int tid = threadIdx.x, wid = tid >> 5, lane = tid & 31;
    const int n0 = blockIdx.x * 128, m0 = blockIdx.y * 128;
    float* bias_s = (float*)sm;            // 128 floats
    int*   rowidx = (int*)(sm + 512);      // 128 ints

    auto issue_stage = [&](int c, int stage) {
        const size_t kb = (size_t)c * 128;   // byte offset into fp16 row (c*64 elems)
        const uint32_t dbase = sb + SMHDR + stage * QSTAGE;
        #pragma unroll
        for (int i = 0; i < 12; i++) {
            const int g = tid + i * 256;         // 0..3071
            const int tile = g >> 10;
            const int u = g & 1023;
            const int row = u >> 3, col8 = u & 7;
            const char* src;
            if (tile == 0)      src = (const char*)(Ah + (size_t)(m0 + row) * CC) + kb;
            else if (tile == 1) src = (const char*)(Al + (size_t)(m0 + row) * CC) + kb;
            else                src = (const char*)(Bh + (size_t)(n0 + row) * CC) + kb;
            cp_async16(dbase + tile * QTILE + row * QROWB + col8 * 16, src + col8 * 16);
        }
    };

    issue_stage(0, 0); CP_COMMIT();
    issue_stage(1, 1); CP_COMMIT();

    if (tid < 128) {
        bias_s[tid] = bias[n0 + tid];
        if (SCATTER) rowidx[tid] = order[m0 + tid];
    }
    __syncthreads();

    const int wm = (wid & 1) * 64;
    const int wn = (wid >> 1) * 32;

    float acc[4][4][4];
    #pragma unroll
    for (int nt = 0; nt < 4; nt++) {
        float b0 = bias_s[wn + nt * 8 + 2 * (lane & 3)];
        float b1 = bias_s[wn + nt * 8 + 2 * (lane & 3) + 1];
        #pragma unroll
        for (int mt = 0; mt < 4; mt++) {
            acc[mt][nt][0] = b0; acc[mt][nt][1] = b1;
            acc[mt][nt][2] = b0; acc[mt][nt][3] = b1;
        }
    }

    const uint32_t a_lm = sb + SMHDR + (wm + (lane & 15)) * QROWB + ((lane >> 4) & 1) * 16;
    const uint32_t b_lm = sb + SMHDR + 2 * QTILE + (wn + (lane & 7)) * QROWB
                          + ((lane >> 3) & 1) * 16;

    uint32_t ahf[2][4][4], alf[2][4][4], bhf[2][4][2];

    const int NC = CC / 64;   // 8
    #pragma unroll 1
    for (int c = 0; c < NC; c++) {
        CP_WAIT1();
        __syncthreads();
        if (c + 2 < NC) issue_stage(c + 2, (c + 2) % 3);
        CP_COMMIT();

        const uint32_t abase = a_lm + (c % 3) * QSTAGE;
        const uint32_t bbase = b_lm + (c % 3) * QSTAGE;

        // preload ks=0 fragments
        #pragma unroll
        for (int mt = 0; mt < 4; mt++) {
            ldsm_x4(ahf[0][mt], abase + mt * 16 * QROWB);
            ldsm_x4(alf[0][mt], abase + QTILE + mt * 16 * QROWB);
        }
        #pragma unroll
        for (int nt = 0; nt < 4; nt++)
            ldsm_x2(bhf[0][nt], bbase + nt * 8 * QROWB);

        #pragma unroll
        for (int ks = 0; ks < 4; ks++) {
            if (ks < 3) {   // issue loads for ks+1 BEFORE the MMAs of ks
                const int ko = (ks + 1) * 32;
                const int nb = (ks + 1) & 1;
                #pragma unroll
                for (int mt = 0; mt < 4; mt++) {
                    ldsm_x4(ahf[nb][mt], abase + mt * 16 * QROWB + ko);
                    ldsm_x4(alf[nb][mt], abase + QTILE + mt * 16 * QROWB + ko);
                }
                #pragma unroll
                for (int nt = 0; nt < 4; nt++)
                    ldsm_x2(bhf[nb][nt], bbase + nt * 8 * QROWB + ko);
            }
            const int buf = ks & 1;
            #pragma unroll
            for (int mt = 0; mt < 4; mt++)
                #pragma unroll
                for (int nt = 0; nt < 4; nt++) {
                    mma_f16(acc[mt][nt], ahf[buf][mt], bhf[buf][nt]);
                    mma_f16(acc[mt][nt], alf[buf][mt], bhf[buf][nt]);
                }
        }
    }

    #pragma unroll
    for (int mt = 0; mt < 4; mt++) {
        int lrow = wm + mt * 16 + (lane >> 2);
        int d0 = SCATTER ? rowidx[lrow]     : (m0 + lrow);
        int d1 = SCATTER ? rowidx[lrow + 8] : (m0 + lrow + 8);
        #pragma unroll
        for (int nt = 0; nt < 4; nt++) {
            int col = n0 + wn + nt * 8 + 2 * (lane & 3);
            *(float2*)(C + (size_t)d0 * Ntot + col) =
                make_float2(acc[mt][nt][0], acc[mt][nt][1]);
            *(float2*)(C + (size_t)d1 * Ntot + col) =
                make_float2(acc[mt][nt][2], acc[mt][nt][3]);
        }
    }
}

// ---------------- cls qkv: parallel k-split, grid 48 ----------------
__global__ __launch_bounds__(256)
void cls_qkv_kernel(const float* __restrict__ cls_tokens,
                    const float* __restrict__ Wqkv,
                    const float* __restrict__ bqkv)
{
    __shared__ float ct[BB * CC];
    __shared__ float red[8][BB][32];
    const int tid = threadIdx.x, lane = tid & 31, seg = tid >> 5;
    for (int i = tid; i < BB * CC; i += 256) ct[i] = cls_tokens[i];
    __syncthreads();
    const int n = blockIdx.x * 32 + lane;
    float acc[BB] = {0.f, 0.f, 0.f, 0.f};
    for (int k = seg * 64; k < seg * 64 + 64; k++) {
        float w = Wqkv[(size_t)k * C3 + n];
        #pragma unroll
        for (int b = 0; b < BB; b++) acc[b] += ct[b * CC + k] * w;
    }
    #pragma unroll
    for (int b = 0; b < BB; b++) red[seg][b][lane] = acc[b];
    __syncthreads();
    if (seg < BB) {
        float s = bqkv[n];
        #pragma unroll
        for (int j = 0; j < 8; j++) s += red[j][seg][lane];
        g_clsqkv[seg * C3 + n] = s;
    }
}

// ---------------- tensor-core attention (token queries), fp16 2-term ----------------
#define NP 272
#define KROWB 144
#define ATT_SMEM (2 * NP * KROWB)   // 78336

__global__ __launch_bounds__(256)
void attn_mma_kernel(const int* __restrict__ offset)
{
    extern __shared__ char sm[];
    char* KhB = sm;
    char* VhB = sm + NP * KROWB;
    const uint32_t sb = smem_u32(sm);
    const uint32_t KhU = sb;
    const uint32_t VhU = sb + NP * KROWB;

    const int ci = blockIdx.x, h = blockIdx.y, tid = threadIdx.x;
    const int wid = tid >> 5, lane = tid & 31;
    const int cs = ci * KK;
    int b = 0;
    #pragma unroll
    for (int j = 0; j < BB; j++) b += (offset[j] <= cs) ? 1 : 0;
    const float* qkvbase = g_qkv + (size_t)cs * C3;
    const float* clsrow  = g_clsqkv + b * C3;
    const int koff = CC + h * DH, voff = 2 * CC + h * DH;

    for (int idx = tid; idx < 2 * NP * 16; idx += 256) {
        int kv = idx >= NP * 16;
        int i  = kv ? idx - NP * 16 : idx;
        int t = i >> 4, d4 = (i & 15) << 2;
        int off = kv ? voff : koff;
        float4 v = make_float4(0.f, 0.f, 0.f, 0.f);
        if (t == 0)       v = *(const float4*)(clsrow + off + d4);
        else if (t <= KK) v = *(const float4*)(qkvbase + (size_t)(t - 1) * C3 + off + d4);
        __half2 h01 = __floats2half2_rn(v.x, v.y);
        __half2 h23 = __floats2half2_rn(v.z, v.w);
        char* hB = (kv ? VhB : KhB) + t * KROWB + d4 * 2;
        *(uint2*)hB = make_uint2(*(uint32_t*)&h01, *(uint32_t*)&h23);
    }
    __syncthreads();

    const int r0 = lane >> 2;
    const int qp = (lane & 3) * 2;

    #pragma unroll 1
    for (int mt = wid; mt < 16; mt += 8) {
        const float* p0 = qkvbase + (size_t)(mt * 16 + r0) * C3 + h * DH;
        const float* p1 = p0 + 8 * C3;

        float acc[34][4];
        #pragma unroll
        for (int nt = 0; nt < 34; nt++)
            acc[nt][0] = acc[nt][1] = acc[nt][2] = acc[nt][3] = 0.f;

        #pragma unroll
        for (int kt = 0; kt < 4; kt++) {
            float2 q00 = *(const float2*)(p0 + kt * 16 + qp);
            float2 q10 = *(const float2*)(p1 + kt * 16 + qp);
            float2 q01 = *(const float2*)(p0 + kt * 16 + qp + 8);
            float2 q11 = *(const float2*)(p1 + kt * 16 + qp + 8);
            uint32_t qh[4], ql[4];
            qh[0] = split_pack_h(q00.x * 0.125f, q00.y * 0.125f, &ql[0]);
            qh[1] = split_pack_h(q10.x * 0.125f, q10.y * 0.125f, &ql[1]);
            qh[2] = split_pack_h(q01.x * 0.125f, q01.y * 0.125f, &ql[2]);
            qh[3] = split_pack_h(q11.x * 0.125f, q11.y * 0.125f, &ql[3]);
            const uint32_t kaddr = KhU + (lane & 7) * KROWB + ((lane >> 3) & 1) * 16 + kt * 32;
            #pragma unroll
            for (int nt = 0; nt < 34; nt++) {
                uint32_t bh[2];
                ldsm_x2(bh, kaddr + nt * 8 * KROWB);
                mma_f16(acc[nt], qh, bh);
                mma_f16(acc[nt], ql, bh);
            }
        }

        if (qp != 0) { acc[32][0] = -1e30f; acc[32][2] = -1e30f; }
        acc[32][1] = -1e30f; acc[32][3] = -1e30f;
        acc[33][0] = acc[33][1] = acc[33][2] = acc[33][3] = -1e30f;

        float m0 = -1e30f, m1 = -1e30f;
        #pragma unroll
        for (int nt = 0; nt < 34; nt++) {
            m0 = fmaxf(m0, fmaxf(acc[nt][0], acc[nt][1]));
            m1 = fmaxf(m1, fmaxf(acc[nt][2], acc[nt][3]));
        }
        m0 = fmaxf(m0, __shfl_xor_sync(0xffffffffu, m0, 1));
        m0 = fmaxf(m0, __shfl_xor_sync(0xffffffffu, m0, 2));
        m1 = fmaxf(m1, __shfl_xor_sync(0xffffffffu, m1, 1));
        m1 = fmaxf(m1, __shfl_xor_sync(0xffffffffu, m1, 2));
        float s0 = 0.f, s1 = 0.f;
        #pragma unroll
        for (int nt = 0; nt < 34; nt++) {
            acc[nt][0] = __expf(acc[nt][0] - m0);
            acc[nt][1] = __expf(acc[nt][1] - m0);
            acc[nt][2] = __expf(acc[nt][2] - m1);
            acc[nt][3] = __expf(acc[nt][3] - m1);
            s0 += acc[nt][0] + acc[nt][1];
            s1 += acc[nt][2] + acc[nt][3];
        }
        s0 += __shfl_xor_sync(0xffffffffu, s0, 1);
        s0 += __shfl_xor_sync(0xffffffffu, s0, 2);
        s1 += __shfl_xor_sync(0xffffffffu, s1, 1);
        s1 += __shfl_xor_sync(0xffffffffu, s1, 2);
        const float inv0 = 1.f / s0, inv1 = 1.f / s1;

        float o[8][4];
        #pragma unroll
        for (int nt = 0; nt < 8; nt++)
            o[nt][0] = o[nt][1] = o[nt][2] = o[nt][3] = 0.f;

        #pragma unroll
        for (int kt = 0; kt < 17; kt++) {
            uint32_t ah[4], al[4];
            ah[0] = split_pack_h(acc[2*kt][0] * inv0,   acc[2*kt][1] * inv0,   &al[0]);
            ah[1] = split_pack_h(acc[2*kt][2] * inv1,   acc[2*kt][3] * inv1,   &al[1]);
            ah[2] = split_pack_h(acc[2*kt+1][0] * inv0, acc[2*kt+1][1] * inv0, &al[2]);
            ah[3] = split_pack_h(acc[2*kt+1][2] * inv1, acc[2*kt+1][3] * inv1, &al[3]);
            const uint32_t vaddr = VhU + (kt * 16 + (lane & 15)) * KROWB;
            #pragma unroll
            for (int nt = 0; nt < 8; nt++) {
                uint32_t bh[2];
                ldsm_x2_t(bh, vaddr + nt * 16);
                mma_f16(o[nt], ah, bh);
                mma_f16(o[nt], al, bh);
            }
        }

        const size_t row0 = (size_t)(cs + mt * 16 + r0) * CC + h * DH;
        const size_t row1 = row0 + 8 * CC;
        #pragma unroll
        for (int nt = 0; nt < 8; nt++) {
            uint32_t lo;
            uint32_t hi = split_pack_h(o[nt][0], o[nt][1], &lo);
            *(uint32_t*)(g_att_h + row0 + nt * 8 + qp) = hi;
            *(uint32_t*)(g_att_l + row0 + nt * 8 + qp) = lo;
            hi = split_pack_h(o[nt][2], o[nt][3], &lo);
            *(uint32_t*)(g_att_h + row1 + nt * 8 + qp) = hi;
            *(uint32_t*)(g_att_l + row1 + nt * 8 + qp) = lo;
        }
    }
}

// ---------------- cls-query attention ----------------
__global__ __launch_bounds__(256)
void cls_attn_kernel(const int* __restrict__ offset)
{
    __shared__ float sS[HH][257];
    const int ci = blockIdx.x, tid = threadIdx.x;
    const int h = tid >> 5, lane = tid & 31;
    const int cs = ci * KK;
    int b = 0;
    #pragma unroll
    for (int j = 0; j < BB; j++) b += (offset[j] <= cs) ? 1 : 0;
    const float* qkvbase = g_qkv + (size_t)cs * C3;
    const float* clsrow  = g_clsqkv + b * C3;
    const int koff = CC + h * DH, voff = 2 * CC + h * DH;

    const float q0 = clsrow[h * DH + lane] * 0.125f;
    const float q1 = clsrow[h * DH + lane + 32] * 0.125f;

    for (int j = 0; j < 257; j++) {
        const float* kr = (j == 0) ? (clsrow + koff)
                                   : (qkvbase + (size_t)(j - 1) * C3 + koff);
        float part = q0 * kr[lane] + q1 * kr[lane + 32];
        #pragma unroll
        for (int o = 16; o; o >>= 1) part += __shfl_xor_sync(0xffffffffu, part, o);
        if (lane == 0) sS[h][j] = part;
    }
    __syncwarp();

    float m = -1e30f;
    for (int j = lane; j < 257; j += 32) m = fmaxf(m, sS[h][j]);
    #pragma unroll
    for (int o = 16; o; o >>= 1) m = fmaxf(m, __shfl_xor_sync(0xffffffffu, m, o));
    float s = 0.f;
    for (int j = lane; j < 257; j += 32) {
        float e = __expf(sS[h][j] - m);
        sS[h][j] = e;
        s += e;
    }
    #pragma unroll
    for (int o = 16; o; o >>= 1) s += __shfl_xor_sync(0xffffffffu, s, o);
    const float inv = 1.f / s;
    __syncwarp();

    float o0 = 0.f, o1 = 0.f;
    for (int j = 0; j < 257; j++) {
        const float* vr = (j == 0) ? (clsrow + voff)
                                   : (qkvbase + (size_t)(j - 1) * C3 + voff);
        float p = sS[h][j] * inv;
        o0 += p * vr[lane];
        o1 += p * vr[lane + 32];
    }
    g_clspart[ci * CC + h * DH + lane]      = o0;
    g_clspart[ci * CC + h * DH + lane + 32] = o1;
}

// ---------------- cls reduce ----------------
__global__ __launch_bounds__(256)
void cls_reduce_kernel(const int* __restrict__ offset, float* __restrict__ out_cls)
{
    int gid = blockIdx.x * 256 + threadIdx.x;
    int b = gid >> 9;
    int c = gid & (CC - 1);
    int start = (b == 0) ? 0 : offset[b - 1];
    int end = offset[b];
    int ch0 = start / KK, ch1 = end / KK;
    float s = 0.f;
    for (int ch = ch0; ch < ch1; ch++) s += g_clspart[ch * CC + c];
    out_cls[gid] = s / (float)(ch1 - ch0);
}

// ---------------- launch ----------------
extern "C" void kernel_launch(void* const* d_in, const int* in_sizes, int n_in,
                              void* d_out, int out_size)
{
    const float* feat       = (const float*)d_in[0];
    const float* cls_tokens = (const float*)d_in[1];
    const float* Wqkv       = (const float*)d_in[2];
    const float* bqkv       = (const float*)d_in[3];
    const float* Wproj      = (const float*)d_in[4];
    const float* bproj      = (const float*)d_in[5];
    const int*   order      = (const int*)d_in[6];
    const int*   offset     = (const int*)d_in[8];

    float* out_feat = (float*)d_out;
    float* out_cls  = out_feat + (size_t)NPTS * CC;

    void *qkvp = nullptr;
    void *ah = nullptr, *al = nullptr, *ath = nullptr, *atl = nullptr;
    void *wq = nullptr, *wp = nullptr;
    cudaGetSymbolAddress(&qkvp, g_qkv);
    cudaGetSymbolAddress(&ah, g_Ah);
    cudaGetSymbolAddress(&al, g_Al);
    cudaGetSymbolAddress(&ath, g_att_h);
    cudaGetSymbolAddress(&atl, g_att_l);
    cudaGetSymbolAddress(&wq, g_WqkvT);
    cudaGetSymbolAddress(&wp, g_WprojT);

    cudaFuncSetAttribute(attn_mma_kernel, cudaFuncAttributeMaxDynamicSharedMemorySize,
                         ATT_SMEM);
    cudaFuncSetAttribute(gemm_async_kernel<false>,
                         cudaFuncAttributeMaxDynamicSharedMemorySize, GSMEM);
    cudaFuncSetAttribute(gemm_async_kernel<true>,
                         cudaFuncAttributeMaxDynamicSharedMemorySize, GSMEM);

    // 0. weight transpose (fp16), feat gather+split (fp16)
    conv_wt_kernel<<<dim3(C3 / 32, CC / 32), 256>>>(Wqkv, (__half*)wq, CC, C3);
    conv_wt_kernel<<<dim3(CC / 32, CC / 32), 256>>>(Wproj, (__half*)wp, CC, CC);
    conv_feat_kernel<<<(NPTS * (CC / 4)) / 256, 256>>>(feat, order);
    // 1. cls token qkv
    cls_qkv_kernel<<<C3 / 32, 256>>>(cls_tokens, Wqkv, bqkv);
    // 2. qkv GEMM (128x128 tiles, pipelined frags)
    gemm_async_kernel<false><<<dim3(C3 / 128, NPTS / 128), 256, GSMEM>>>(
        (const __half*)ah, (const __half*)al, (const __half*)wq,
        bqkv, (float*)qkvp, order, C3);
    // 3. attention
    attn_mma_kernel<<<dim3(NCH, HH), 256, ATT_SMEM>>>(offset);
    cls_attn_kernel<<<NCH, 256>>>(offset);
    // 4. proj GEMM with scatter
    gemm_async_kernel<true><<<dim3(CC / 128, NPTS / 128), 256, GSMEM>>>(
        (const __half*)ath, (const __half*)atl, (const __half*)wp,
        bproj, out_feat, order, CC);
    // 5. cls reduction
    cls_reduce_kernel<<<(BB * CC) / 256, 256>>>(offset, out_cls);
}

// round 9
// speedup vs baseline: 1.3754x; 1.3754x over previous
#include <cuda_runtime.h>
#include <cuda_fp16.h>
#include <cstdint>
#include <cstddef>

#define NPTS 65536
#define BB 4
#define CC 512
#define C3 1536
#define KK 256
#define HH 8
#define DH 64
#define NCH 256   // NPTS/KK

// ---------------- scratch (static device globals; no allocation) ----------------
__device__ float g_qkv[(size_t)NPTS * C3];     // gathered qkv, serialized order (fp32)
__device__ float g_clsqkv[BB * C3];            // cls token qkv
__device__ float g_clspart[NCH * CC];          // per-chunk cls attention row
__device__ __half g_Ah[(size_t)NPTS * CC];     // gathered feat (fp16)
__device__ __half g_att_h[(size_t)NPTS * CC];  // attention out (fp16, serialized)
__device__ __half g_WqkvT[(size_t)C3 * CC];    // W^T fp16
__device__ __half g_WprojT[(size_t)CC * CC];

// =============== helpers ===============
__device__ __forceinline__ uint32_t smem_u32(const void* p) {
    uint32_t a;
    asm("{ .reg .u64 t; cvta.to.shared.u64 t, %1; cvt.u32.u64 %0, t; }" : "=r"(a) : "l"(p));
    return a;
}
__device__ __forceinline__ void ldsm_x4(uint32_t* r, uint32_t addr) {
    asm volatile("ldmatrix.sync.aligned.m8n8.x4.shared.b16 {%0,%1,%2,%3}, [%4];"
                 : "=r"(r[0]), "=r"(r[1]), "=r"(r[2]), "=r"(r[3]) : "r"(addr));
}
__device__ __forceinline__ void ldsm_x2(uint32_t* r, uint32_t addr) {
    asm volatile("ldmatrix.sync.aligned.m8n8.x2.shared.b16 {%0,%1}, [%2];"
                 : "=r"(r[0]), "=r"(r[1]) : "r"(addr));
}
__device__ __forceinline__ void ldsm_x2_t(uint32_t* r, uint32_t addr) {
    asm volatile("ldmatrix.sync.aligned.m8n8.x2.trans.shared.b16 {%0,%1}, [%2];"
                 : "=r"(r[0]), "=r"(r[1]) : "r"(addr));
}
__device__ __forceinline__ void mma_f16(float* c, const uint32_t* a, const uint32_t* b) {
    asm volatile(
        "mma.sync.aligned.m16n8k16.row.col.f32.f16.f16.f32 "
        "{%0,%1,%2,%3}, {%4,%5,%6,%7}, {%8,%9}, {%0,%1,%2,%3};"
        : "+f"(c[0]), "+f"(c[1]), "+f"(c[2]), "+f"(c[3])
        : "r"(a[0]), "r"(a[1]), "r"(a[2]), "r"(a[3]), "r"(b[0]), "r"(b[1]));
}
__device__ __forceinline__ uint32_t pack_h2(float x, float y) {
    __half2 hh = __floats2half2_rn(x, y);
    return *reinterpret_cast<uint32_t*>(&hh);
}
__device__ __forceinline__ void cp_async16(uint32_t dst, const void* src) {
    asm volatile("cp.async.cg.shared.global [%0], [%1], 16;" :: "r"(dst), "l"(src) : "memory");
}
#define CP_COMMIT() asm volatile("cp.async.commit_group;" ::: "memory")
#define CP_WAIT1()  asm volatile("cp.async.wait_group 1;" ::: "memory")

// ---------------- W transpose to fp16 ----------------
__global__ __launch_bounds__(256)
void conv_wt_kernel(const float* __restrict__ W, __half* __restrict__ T, int K, int N)
{
    __shared__ float t[32][33];
    int n0 = blockIdx.x * 32, k0 = blockIdx.y * 32;
    int tx = threadIdx.x & 31, ty = threadIdx.x >> 5;
    #pragma unroll
    for (int j = 0; j < 32; j += 8)
        t[ty + j][tx] = W[(size_t)(k0 + ty + j) * N + n0 + tx];
    __syncthreads();
    #pragma unroll
    for (int j = 0; j < 32; j += 8) {
        int n = n0 + ty + j, k = k0 + tx;
        T[(size_t)n * K + k] = __float2half_rn(t[tx][ty + j]);
    }
}

// ---------------- feat gather -> fp16 ----------------
__global__ __launch_bounds__(256)
void conv_feat_kernel(const float* __restrict__ feat, const int* __restrict__ order)
{
    size_t idx = (size_t)blockIdx.x * 256 + threadIdx.x;
    int m = (int)(idx >> 7);
    int u = (int)(idx & 127);
    const float4 v = *(const float4*)(feat + (size_t)order[m] * CC + u * 4);
    *(uint2*)(g_Ah + (size_t)m * CC + u * 4) =
        make_uint2(pack_h2(v.x, v.y), pack_h2(v.z, v.w));
}

// ---- cp.async GEMM: 128x128 tile, Kc=32, 3 stages, single fp16, 2 CTAs/SM ----
#define PROWB  80
#define PTILE  (128 * PROWB)       // 10240
#define PSTAGE (2 * PTILE)         // 20480 (A | B)
#define SMHDR  1024
#define GSMEM  (SMHDR + 3 * PSTAGE)   // 62464

template<bool SCATTER>
__global__ __launch_bounds__(256, 2)
void gemm_async_kernel(const __half* __restrict__ Ah, const __half* __restrict__ Bh,
                       const float* __restrict__ bias, float* __restrict__ C,
                       const int* __restrict__ order, int Ntot)
{
    extern __shared__ char sm[];
    const uint32_t sb = smem_u32(sm);
    const int tid = threadIdx.x, wid = tid >> 5, lane = tid & 31;
    const int n0 = blockIdx.x * 128, m0 = blockIdx.y * 128;
    float* bias_s = (float*)sm;
    int*   rowidx = (int*)(sm + 512);

    const int cr = tid >> 2;        // 0..63
    const int cu = (tid & 3) * 16;  // byte offset within 64B k-chunk row

    auto issue_stage = [&](int c, int stage) {
        const int k0 = c * 32;
        const uint32_t dbase = sb + SMHDR + stage * PSTAGE;
        #pragma unroll
        for (int i = 0; i < 4; i++) {
            const int tile = i >> 1;
            const int r = (i & 1) * 64 + cr;
            const __half* src = (tile ? Bh + (size_t)(n0 + r) * CC
                                      : Ah + (size_t)(m0 + r) * CC) + k0;
            cp_async16(dbase + tile * PTILE + r * PROWB + cu, (const char*)src + cu);
        }
    };

    issue_stage(0, 0); CP_COMMIT();
    issue_stage(1, 1); CP_COMMIT();

    if (tid < 128) {
        bias_s[tid] = bias[n0 + tid];
        if (SCATTER) rowidx[tid] = order[m0 + tid];
    }
    __syncthreads();

    const int wm = (wid & 1) * 64;
    const int wn = (wid >> 1) * 32;

    float acc[4][4][4];
    #pragma unroll
    for (int nt = 0; nt < 4; nt++) {
        float b0 = bias_s[wn + nt * 8 + 2 * (lane & 3)];
        float b1 = bias_s[wn + nt * 8 + 2 * (lane & 3) + 1];
        #pragma unroll
        for (int mt = 0; mt < 4; mt++) {
            acc[mt][nt][0] = b0; acc[mt][nt][1] = b1;
            acc[mt][nt][2] = b0; acc[mt][nt][3] = b1;
        }
    }

    const uint32_t a_lm = sb + SMHDR + (wm + (lane & 15)) * PROWB + ((lane >> 4) & 1) * 16;
    const uint32_t b_lm = sb + SMHDR + PTILE + (wn + (lane & 7)) * PROWB
                          + ((lane >> 3) & 1) * 16;

    const int NC = CC / 32;   // 16
    #pragma unroll 1
    for (int c = 0; c < NC; c++) {
        CP_WAIT1();
        __syncthreads();
        if (c + 2 < NC) issue_stage(c + 2, (c + 2) % 3);
        CP_COMMIT();

        const uint32_t abase = a_lm + (c % 3) * PSTAGE;
        const uint32_t bbase = b_lm + (c % 3) * PSTAGE;
        #pragma unroll
        for (int ks = 0; ks < 2; ks++) {
            const int ko = ks * 32;
            uint32_t ah[4][4], bh[4][2];
            #pragma unroll
            for (int mt = 0; mt < 4; mt++)
                ldsm_x4(ah[mt], abase + mt * 16 * PROWB + ko);
            #pragma unroll
            for (int nt = 0; nt < 4; nt++)
                ldsm_x2(bh[nt], bbase + nt * 8 * PROWB + ko);
            #pragma unroll
            for (int mt = 0; mt < 4; mt++)
                #pragma unroll
                for (int nt = 0; nt < 4; nt++)
                    mma_f16(acc[mt][nt], ah[mt], bh[nt]);
        }
    }

    #pragma unroll
    for (int mt = 0; mt < 4; mt++) {
        int lrow = wm + mt * 16 + (lane >> 2);
        int d0 = SCATTER ? rowidx[lrow]     : (m0 + lrow);
        int d1 = SCATTER ? rowidx[lrow + 8] : (m0 + lrow + 8);
        #pragma unroll
        for (int nt = 0; nt < 4; nt++) {
            int col = n0 + wn + nt * 8 + 2 * (lane & 3);
            *(float2*)(C + (size_t)d0 * Ntot + col) =
                make_float2(acc[mt][nt][0], acc[mt][nt][1]);
            *(float2*)(C + (size_t)d1 * Ntot + col) =
                make_float2(acc[mt][nt][2], acc[mt][nt][3]);
        }
    }
}

// ---------------- cls qkv: parallel k-split, grid 48 ----------------
__global__ __launch_bounds__(256)
void cls_qkv_kernel(const float* __restrict__ cls_tokens,
                    const float* __restrict__ Wqkv,
                    const float* __restrict__ bqkv)
{
    __shared__ float ct[BB * CC];
    __shared__ float red[8][BB][32];
    const int tid = threadIdx.x, lane = tid & 31, seg = tid >> 5;
    for (int i = tid; i < BB * CC; i += 256) ct[i] = cls_tokens[i];
    __syncthreads();
    const int n = blockIdx.x * 32 + lane;
    float acc[BB] = {0.f, 0.f, 0.f, 0.f};
    for (int k = seg * 64; k < seg * 64 + 64; k++) {
        float w = Wqkv[(size_t)k * C3 + n];
        #pragma unroll
        for (int b = 0; b < BB; b++) acc[b] += ct[b * CC + k] * w;
    }
    #pragma unroll
    for (int b = 0; b < BB; b++) red[seg][b][lane] = acc[b];
    __syncthreads();
    if (seg < BB) {
        float s = bqkv[n];
        #pragma unroll
        for (int j = 0; j < 8; j++) s += red[j][seg][lane];
        g_clsqkv[seg * C3 + n] = s;
    }
}

// ---------------- tensor-core attention (token queries), single fp16 ----------------
#define NP 272
#define KROWB 144
#define ATT_SMEM (2 * NP * KROWB)   // 78336

__global__ __launch_bounds__(256)
void attn_mma_kernel(const int* __restrict__ offset)
{
    extern __shared__ char sm[];
    char* KhB = sm;
    char* VhB = sm + NP * KROWB;
    const uint32_t sb = smem_u32(sm);
    const uint32_t KhU = sb;
    const uint32_t VhU = sb + NP * KROWB;

    const int ci = blockIdx.x, h = blockIdx.y, tid = threadIdx.x;
    const int wid = tid >> 5, lane = tid & 31;
    const int cs = ci * KK;
    int b = 0;
    #pragma unroll
    for (int j = 0; j < BB; j++) b += (offset[j] <= cs) ? 1 : 0;
    const float* qkvbase = g_qkv + (size_t)cs * C3;
    const float* clsrow  = g_clsqkv + b * C3;
    const int koff = CC + h * DH, voff = 2 * CC + h * DH;

    for (int idx = tid; idx < 2 * NP * 16; idx += 256) {
        int kv = idx >= NP * 16;
        int i  = kv ? idx - NP * 16 : idx;
        int t = i >> 4, d4 = (i & 15) << 2;
        int off = kv ? voff : koff;
        float4 v = make_float4(0.f, 0.f, 0.f, 0.f);
        if (t == 0)       v = *(const float4*)(clsrow + off + d4);
        else if (t <= KK) v = *(const float4*)(qkvbase + (size_t)(t - 1) * C3 + off + d4);
        char* hB = (kv ? VhB : KhB) + t * KROWB + d4 * 2;
        *(uint2*)hB = make_uint2(pack_h2(v.x, v.y), pack_h2(v.z, v.w));
    }
    __syncthreads();

    const int r0 = lane >> 2;
    const int qp = (lane & 3) * 2;

    #pragma unroll 1
    for (int mt = wid; mt < 16; mt += 8) {
        const float* p0 = qkvbase + (size_t)(mt * 16 + r0) * C3 + h * DH;
        const float* p1 = p0 + 8 * C3;

        float acc[34][4];
        #pragma unroll
        for (int nt = 0; nt < 34; nt++)
            acc[nt][0] = acc[nt][1] = acc[nt][2] = acc[nt][3] = 0.f;

        // ---- S = Q K^T (single fp16 both sides) ----
        #pragma unroll
        for (int kt = 0; kt < 4; kt++) {
            float2 q00 = *(const float2*)(p0 + kt * 16 + qp);
            float2 q10 = *(const float2*)(p1 + kt * 16 + qp);
            float2 q01 = *(const float2*)(p0 + kt * 16 + qp + 8);
            float2 q11 = *(const float2*)(p1 + kt * 16 + qp + 8);
            uint32_t qh[4];
            qh[0] = pack_h2(q00.x * 0.125f, q00.y * 0.125f);
            qh[1] = pack_h2(q10.x * 0.125f, q10.y * 0.125f);
            qh[2] = pack_h2(q01.x * 0.125f, q01.y * 0.125f);
            qh[3] = pack_h2(q11.x * 0.125f, q11.y * 0.125f);
            const uint32_t kaddr = KhU + (lane & 7) * KROWB + ((lane >> 3) & 1) * 16 + kt * 32;
            #pragma unroll
            for (int nt = 0; nt < 34; nt++) {
                uint32_t bh[2];
                ldsm_x2(bh, kaddr + nt * 8 * KROWB);
                mma_f16(acc[nt], qh, bh);
            }
        }

        if (qp != 0) { acc[32][0] = -1e30f; acc[32][2] = -1e30f; }
        acc[32][1] = -1e30f; acc[32][3] = -1e30f;
        acc[33][0] = acc[33][1] = acc[33][2] = acc[33][3] = -1e30f;

        float m0 = -1e30f, m1 = -1e30f;
        #pragma unroll
        for (int nt = 0; nt < 34; nt++) {
            m0 = fmaxf(m0, fmaxf(acc[nt][0], acc[nt][1]));
            m1 = fmaxf(m1, fmaxf(acc[nt][2], acc[nt][3]));
        }
        m0 = fmaxf(m0, __shfl_xor_sync(0xffffffffu, m0, 1));
        m0 = fmaxf(m0, __shfl_xor_sync(0xffffffffu, m0, 2));
        m1 = fmaxf(m1, __shfl_xor_sync(0xffffffffu, m1, 1));
        m1 = fmaxf(m1, __shfl_xor_sync(0xffffffffu, m1, 2));
        float s0 = 0.f, s1 = 0.f;
        #pragma unroll
        for (int nt = 0; nt < 34; nt++) {
            acc[nt][0] = __expf(acc[nt][0] - m0);
            acc[nt][1] = __expf(acc[nt][1] - m0);
            acc[nt][2] = __expf(acc[nt][2] - m1);
            acc[nt][3] = __expf(acc[nt][3] - m1);
            s0 += acc[nt][0] + acc[nt][1];
            s1 += acc[nt][2] + acc[nt][3];
        }
        s0 += __shfl_xor_sync(0xffffffffu, s0, 1);
        s0 += __shfl_xor_sync(0xffffffffu, s0, 2);
        s1 += __shfl_xor_sync(0xffffffffu, s1, 1);
        s1 += __shfl_xor_sync(0xffffffffu, s1, 2);
        const float inv0 = 1.f / s0, inv1 = 1.f / s1;

        // ---- O = P V (single fp16 P) ----
        float o[8][4];
        #pragma unroll
        for (int nt = 0; nt < 8; nt++)
            o[nt][0] = o[nt][1] = o[nt][2] = o[nt][3] = 0.f;

        #pragma unroll
        for (int kt = 0; kt < 17; kt++) {
            uint32_t ah[4];
            ah[0] = pack_h2(acc[2*kt][0] * inv0,   acc[2*kt][1] * inv0);
            ah[1] = pack_h2(acc[2*kt][2] * inv1,   acc[2*kt][3] * inv1);
            ah[2] = pack_h2(acc[2*kt+1][0] * inv0, acc[2*kt+1][1] * inv0);
            ah[3] = pack_h2(acc[2*kt+1][2] * inv1, acc[2*kt+1][3] * inv1);
            const uint32_t vaddr = VhU + (kt * 16 + (lane & 15)) * KROWB;
            #pragma unroll
            for (int nt = 0; nt < 8; nt++) {
                uint32_t bh[2];
                ldsm_x2_t(bh, vaddr + nt * 16);
                mma_f16(o[nt], ah, bh);
            }
        }

        // store fp16 attention output
        const size_t row0 = (size_t)(cs + mt * 16 + r0) * CC + h * DH;
        const size_t row1 = row0 + 8 * CC;
        #pragma unroll
        for (int nt = 0; nt < 8; nt++) {
            *(uint32_t*)(g_att_h + row0 + nt * 8 + qp) = pack_h2(o[nt][0], o[nt][1]);
            *(uint32_t*)(g_att_h + row1 + nt * 8 + qp) = pack_h2(o[nt][2], o[nt][3]);
        }
    }
}

// ---------------- cls-query attention ----------------
__global__ __launch_bounds__(256)
void cls_attn_kernel(const int* __restrict__ offset)
{
    __shared__ float sS[HH][257];
    const int ci = blockIdx.x, tid = threadIdx.x;
    const int h = tid >> 5, lane = tid & 31;
    const int cs = ci * KK;
    int b = 0;
    #pragma unroll
    for (int j = 0; j < BB; j++) b += (offset[j] <= cs) ? 1 : 0;
    const float* qkvbase = g_qkv + (size_t)cs * C3;
    const float* clsrow  = g_clsqkv + b * C3;
    const int koff = CC + h * DH, voff = 2 * CC + h * DH;

    const float q0 = clsrow[h * DH + lane] * 0.125f;
    const float q1 = clsrow[h * DH + lane + 32] * 0.125f;

    for (int j = 0; j < 257; j++) {
        const float* kr = (j == 0) ? (clsrow + koff)
                                   : (qkvbase + (size_t)(j - 1) * C3 + koff);
        float part = q0 * kr[lane] + q1 * kr[lane + 32];
        #pragma unroll
        for (int o = 16; o; o >>= 1) part += __shfl_xor_sync(0xffffffffu, part, o);
        if (lane == 0) sS[h][j] = part;
    }
    __syncwarp();

    float m = -1e30f;
    for (int j = lane; j < 257; j += 32) m = fmaxf(m, sS[h][j]);
    #pragma unroll
    for (int o = 16; o; o >>= 1) m = fmaxf(m, __shfl_xor_sync(0xffffffffu, m, o));
    float s = 0.f;
    for (int j = lane; j < 257; j += 32) {
        float e = __expf(sS[h][j] - m);
        sS[h][j] = e;
        s += e;
    }
    #pragma unroll
    for (int o = 16; o; o >>= 1) s += __shfl_xor_sync(0xffffffffu, s, o);
    const float inv = 1.f / s;
    __syncwarp();

    float o0 = 0.f, o1 = 0.f;
    for (int j = 0; j < 257; j++) {
        const float* vr = (j == 0) ? (clsrow + voff)
                                   : (qkvbase + (size_t)(j - 1) * C3 + voff);
        float p = sS[h][j] * inv;
        o0 += p * vr[lane];
        o1 += p * vr[lane + 32];
    }
    g_clspart[ci * CC + h * DH + lane]      = o0;
    g_clspart[ci * CC + h * DH + lane + 32] = o1;
}

// ---------------- cls reduce ----------------
__global__ __launch_bounds__(256)
void cls_reduce_kernel(const int* __restrict__ offset, float* __restrict__ out_cls)
{
    int gid = blockIdx.x * 256 + threadIdx.x;
    int b = gid >> 9;
    int c = gid & (CC - 1);
    int start = (b == 0) ? 0 : offset[b - 1];
    int end = offset[b];
    int ch0 = start / KK, ch1 = end / KK;
    float s = 0.f;
    for (int ch = ch0; ch < ch1; ch++) s += g_clspart[ch * CC + c];
    out_cls[gid] = s / (float)(ch1 - ch0);
}

// ---------------- launch ----------------
extern "C" void kernel_launch(void* const* d_in, const int* in_sizes, int n_in,
                              void* d_out, int out_size)
{
    const float* feat       = (const float*)d_in[0];
    const float* cls_tokens = (const float*)d_in[1];
    const float* Wqkv       = (const float*)d_in[2];
    const float* bqkv       = (const float*)d_in[3];
    const float* Wproj      = (const float*)d_in[4];
    const float* bproj      = (const float*)d_in[5];
    const int*   order      = (const int*)d_in[6];
    const int*   offset     = (const int*)d_in[8];

    float* out_feat = (float*)d_out;
    float* out_cls  = out_feat + (size_t)NPTS * CC;

    void *qkvp = nullptr;
    void *ah = nullptr, *ath = nullptr;
    void *wq = nullptr, *wp = nullptr;
    cudaGetSymbolAddress(&qkvp, g_qkv);
    cudaGetSymbolAddress(&ah, g_Ah);
    cudaGetSymbolAddress(&ath, g_att_h);
    cudaGetSymbolAddress(&wq, g_WqkvT);
    cudaGetSymbolAddress(&wp, g_WprojT);

    cudaFuncSetAttribute(attn_mma_kernel, cudaFuncAttributeMaxDynamicSharedMemorySize,
                         ATT_SMEM);
    cudaFuncSetAttribute(gemm_async_kernel<false>,
                         cudaFuncAttributeMaxDynamicSharedMemorySize, GSMEM);
    cudaFuncSetAttribute(gemm_async_kernel<true>,
                         cudaFuncAttributeMaxDynamicSharedMemorySize, GSMEM);

    // 0. weight transpose (fp16), feat gather (fp16)
    conv_wt_kernel<<<dim3(C3 / 32, CC / 32), 256>>>(Wqkv, (__half*)wq, CC, C3);
    conv_wt_kernel<<<dim3(CC / 32, CC / 32), 256>>>(Wproj, (__half*)wp, CC, CC);
    conv_feat_kernel<<<(NPTS * (CC / 4)) / 256, 256>>>(feat, order);
    // 1. cls token qkv
    cls_qkv_kernel<<<C3 / 32, 256>>>(cls_tokens, Wqkv, bqkv);
    // 2. qkv GEMM (single fp16, 2 CTAs/SM)
    gemm_async_kernel<false><<<dim3(C3 / 128, NPTS / 128), 256, GSMEM>>>(
        (const __half*)ah, (const __half*)wq, bqkv, (float*)qkvp, order, C3);
    // 3. attention
    attn_mma_kernel<<<dim3(NCH, HH), 256, ATT_SMEM>>>(offset);
    cls_attn_kernel<<<NCH, 256>>>(offset);
    // 4. proj GEMM with scatter
    gemm_async_kernel<true><<<dim3(CC / 128, NPTS / 128), 256, GSMEM>>>(
        (const __half*)ath, (const __half*)wp, bproj, out_feat, order, CC);
    // 5. cls reduction
    cls_reduce_kernel<<<(BB * CC) / 256, 256>>>(offset, out_cls);
}

// round 10
// speedup vs baseline: 1.5048x; 1.0940x over previous
#include <cuda_runtime.h>
#include <cuda_fp16.h>
#include <cstdint>
#include <cstddef>

#define NPTS 65536
#define BB 4
#define CC 512
#define C3 1536
#define KK 256
#define HH 8
#define DH 64
#define NCH 256   // NPTS/KK

// ---------------- scratch (static device globals; no allocation) ----------------
__device__ __half g_qkv_h[(size_t)NPTS * C3]; // gathered qkv, serialized order (fp16)
__device__ float g_clsqkv[BB * C3];            // cls token qkv (fp32)
__device__ float g_clspart[NCH * CC];          // per-chunk cls attention row
__device__ __half g_Ah[(size_t)NPTS * CC];     // gathered feat (fp16)
__device__ __half g_att_h[(size_t)NPTS * CC];  // attention out (fp16, serialized)
__device__ __half g_WqkvT[(size_t)C3 * CC];    // W^T fp16
__device__ __half g_WprojT[(size_t)CC * CC];

// =============== helpers ===============
__device__ __forceinline__ uint32_t smem_u32(const void* p) {
    uint32_t a;
    asm("{ .reg .u64 t; cvta.to.shared.u64 t, %1; cvt.u32.u64 %0, t; }" : "=r"(a) : "l"(p));
    return a;
}
__device__ __forceinline__ void ldsm_x4(uint32_t* r, uint32_t addr) {
    asm volatile("ldmatrix.sync.aligned.m8n8.x4.shared.b16 {%0,%1,%2,%3}, [%4];"
                 : "=r"(r[0]), "=r"(r[1]), "=r"(r[2]), "=r"(r[3]) : "r"(addr));
}
__device__ __forceinline__ void ldsm_x2(uint32_t* r, uint32_t addr) {
    asm volatile("ldmatrix.sync.aligned.m8n8.x2.shared.b16 {%0,%1}, [%2];"
                 : "=r"(r[0]), "=r"(r[1]) : "r"(addr));
}
__device__ __forceinline__ void ldsm_x2_t(uint32_t* r, uint32_t addr) {
    asm volatile("ldmatrix.sync.aligned.m8n8.x2.trans.shared.b16 {%0,%1}, [%2];"
                 : "=r"(r[0]), "=r"(r[1]) : "r"(addr));
}
__device__ __forceinline__ void mma_f16(float* c, const uint32_t* a, const uint32_t* b) {
    asm volatile(
        "mma.sync.aligned.m16n8k16.row.col.f32.f16.f16.f32 "
        "{%0,%1,%2,%3}, {%4,%5,%6,%7}, {%8,%9}, {%0,%1,%2,%3};"
        : "+f"(c[0]), "+f"(c[1]), "+f"(c[2]), "+f"(c[3])
        : "r"(a[0]), "r"(a[1]), "r"(a[2]), "r"(a[3]), "r"(b[0]), "r"(b[1]));
}
__device__ __forceinline__ uint32_t pack_h2(float x, float y) {
    __half2 hh = __floats2half2_rn(x, y);
    return *reinterpret_cast<uint32_t*>(&hh);
}
__device__ __forceinline__ void cp_async16(uint32_t dst, const void* src) {
    asm volatile("cp.async.cg.shared.global [%0], [%1], 16;" :: "r"(dst), "l"(src) : "memory");
}
#define CP_COMMIT() asm volatile("cp.async.commit_group;" ::: "memory")
#define CP_WAIT1()  asm volatile("cp.async.wait_group 1;" ::: "memory")

// ---------------- W transpose to fp16 ----------------
__global__ __launch_bounds__(256)
void conv_wt_kernel(const float* __restrict__ W, __half* __restrict__ T, int K, int N)
{
    __shared__ float t[32][33];
    int n0 = blockIdx.x * 32, k0 = blockIdx.y * 32;
    int tx = threadIdx.x & 31, ty = threadIdx.x >> 5;
    #pragma unroll
    for (int j = 0; j < 32; j += 8)
        t[ty + j][tx] = W[(size_t)(k0 + ty + j) * N + n0 + tx];
    __syncthreads();
    #pragma unroll
    for (int j = 0; j < 32; j += 8) {
        int n = n0 + ty + j, k = k0 + tx;
        T[(size_t)n * K + k] = __float2half_rn(t[tx][ty + j]);
    }
}

// ---------------- feat gather -> fp16 ----------------
__global__ __launch_bounds__(256)
void conv_feat_kernel(const float* __restrict__ feat, const int* __restrict__ order)
{
    size_t idx = (size_t)blockIdx.x * 256 + threadIdx.x;
    int m = (int)(idx >> 7);
    int u = (int)(idx & 127);
    const float4 v = *(const float4*)(feat + (size_t)order[m] * CC + u * 4);
    *(uint2*)(g_Ah + (size_t)m * CC + u * 4) =
        make_uint2(pack_h2(v.x, v.y), pack_h2(v.z, v.w));
}

// ---- cp.async GEMM: 128x128 tile, Kc=32, 3 stages, single fp16, 2 CTAs/SM ----
#define PROWB  80
#define PTILE  (128 * PROWB)       // 10240
#define PSTAGE (2 * PTILE)         // 20480 (A | B)
#define SMHDR  1024
#define GSMEM  (SMHDR + 3 * PSTAGE)   // 62464

template<bool SCATTER, bool OUTHALF>
__global__ __launch_bounds__(256, 2)
void gemm_async_kernel(const __half* __restrict__ Ah, const __half* __restrict__ Bh,
                       const float* __restrict__ bias, void* __restrict__ Cv,
                       const int* __restrict__ order, int Ntot)
{
    extern __shared__ char sm[];
    const uint32_t sb = smem_u32(sm);
    const int tid = threadIdx.x, wid = tid >> 5, lane = tid & 31;
    const int n0 = blockIdx.x * 128, m0 = blockIdx.y * 128;
    float* bias_s = (float*)sm;
    int*   rowidx = (int*)(sm + 512);

    const int cr = tid >> 2;        // 0..63
    const int cu = (tid & 3) * 16;  // byte offset within 64B k-chunk row

    auto issue_stage = [&](int c, int stage) {
        const int k0 = c * 32;
        const uint32_t dbase = sb + SMHDR + stage * PSTAGE;
        #pragma unroll
        for (int i = 0; i < 4; i++) {
            const int tile = i >> 1;
            const int r = (i & 1) * 64 + cr;
            const __half* src = (tile ? Bh + (size_t)(n0 + r) * CC
                                      : Ah + (size_t)(m0 + r) * CC) + k0;
            cp_async16(dbase + tile * PTILE + r * PROWB + cu, (const char*)src + cu);
        }
    };

    issue_stage(0, 0); CP_COMMIT();
    issue_stage(1, 1); CP_COMMIT();

    if (tid < 128) {
        bias_s[tid] = bias[n0 + tid];
        if (SCATTER) rowidx[tid] = order[m0 + tid];
    }
    __syncthreads();

    const int wm = (wid & 1) * 64;
    const int wn = (wid >> 1) * 32;

    float acc[4][4][4];
    #pragma unroll
    for (int nt = 0; nt < 4; nt++) {
        float b0 = bias_s[wn + nt * 8 + 2 * (lane & 3)];
        float b1 = bias_s[wn + nt * 8 + 2 * (lane & 3) + 1];
        #pragma unroll
        for (int mt = 0; mt < 4; mt++) {
            acc[mt][nt][0] = b0; acc[mt][nt][1] = b1;
            acc[mt][nt][2] = b0; acc[mt][nt][3] = b1;
        }
    }

    const uint32_t a_lm = sb + SMHDR + (wm + (lane & 15)) * PROWB + ((lane >> 4) & 1) * 16;
    const uint32_t b_lm = sb + SMHDR + PTILE + (wn + (lane & 7)) * PROWB
                          + ((lane >> 3) & 1) * 16;

    const int NC = CC / 32;   // 16
    #pragma unroll 1
    for (int c = 0; c < NC; c++) {
        CP_WAIT1();
        __syncthreads();
        if (c + 2 < NC) issue_stage(c + 2, (c + 2) % 3);
        CP_COMMIT();

        const uint32_t abase = a_lm + (c % 3) * PSTAGE;
        const uint32_t bbase = b_lm + (c % 3) * PSTAGE;
        #pragma unroll
        for (int ks = 0; ks < 2; ks++) {
            const int ko = ks * 32;
            uint32_t ah[4][4], bh[4][2];
            #pragma unroll
            for (int mt = 0; mt < 4; mt++)
                ldsm_x4(ah[mt], abase + mt * 16 * PROWB + ko);
            #pragma unroll
            for (int nt = 0; nt < 4; nt++)
                ldsm_x2(bh[nt], bbase + nt * 8 * PROWB + ko);
            #pragma unroll
            for (int mt = 0; mt < 4; mt++)
                #pragma unroll
                for (int nt = 0; nt < 4; nt++)
                    mma_f16(acc[mt][nt], ah[mt], bh[nt]);
        }
    }

    #pragma unroll
    for (int mt = 0; mt < 4; mt++) {
        int lrow = wm + mt * 16 + (lane >> 2);
        int d0 = SCATTER ? rowidx[lrow]     : (m0 + lrow);
        int d1 = SCATTER ? rowidx[lrow + 8] : (m0 + lrow + 8);
        #pragma unroll
        for (int nt = 0; nt < 4; nt++) {
            int col = n0 + wn + nt * 8 + 2 * (lane & 3);
            if (OUTHALF) {
                __half* C = (__half*)Cv;
                *(uint32_t*)(C + (size_t)d0 * Ntot + col) =
                    pack_h2(acc[mt][nt][0], acc[mt][nt][1]);
                *(uint32_t*)(C + (size_t)d1 * Ntot + col) =
                    pack_h2(acc[mt][nt][2], acc[mt][nt][3]);
            } else {
                float* C = (float*)Cv;
                *(float2*)(C + (size_t)d0 * Ntot + col) =
                    make_float2(acc[mt][nt][0], acc[mt][nt][1]);
                *(float2*)(C + (size_t)d1 * Ntot + col) =
                    make_float2(acc[mt][nt][2], acc[mt][nt][3]);
            }
        }
    }
}

// ---------------- cls qkv: parallel k-split, grid 48 ----------------
__global__ __launch_bounds__(256)
void cls_qkv_kernel(const float* __restrict__ cls_tokens,
                    const float* __restrict__ Wqkv,
                    const float* __restrict__ bqkv)
{
    __shared__ float ct[BB * CC];
    __shared__ float red[8][BB][32];
    const int tid = threadIdx.x, lane = tid & 31, seg = tid >> 5;
    for (int i = tid; i < BB * CC; i += 256) ct[i] = cls_tokens[i];
    __syncthreads();
    const int n = blockIdx.x * 32 + lane;
    float acc[BB] = {0.f, 0.f, 0.f, 0.f};
    for (int k = seg * 64; k < seg * 64 + 64; k++) {
        float w = Wqkv[(size_t)k * C3 + n];
        #pragma unroll
        for (int b = 0; b < BB; b++) acc[b] += ct[b * CC + k] * w;
    }
    #pragma unroll
    for (int b = 0; b < BB; b++) red[seg][b][lane] = acc[b];
    __syncthreads();
    if (seg < BB) {
        float s = bqkv[n];
        #pragma unroll
        for (int j = 0; j < 8; j++) s += red[j][seg][lane];
        g_clsqkv[seg * C3 + n] = s;
    }
}

// ---------------- tensor-core attention (token queries), single fp16 ----------------
#define NP 272
#define KROWB 144
#define ATT_SMEM (2 * NP * KROWB)   // 78336

__global__ __launch_bounds__(256)
void attn_mma_kernel(const int* __restrict__ offset)
{
    extern __shared__ char sm[];
    char* KhB = sm;
    char* VhB = sm + NP * KROWB;
    const uint32_t sb = smem_u32(sm);
    const uint32_t KhU = sb;
    const uint32_t VhU = sb + NP * KROWB;

    const int ci = blockIdx.x, h = blockIdx.y, tid = threadIdx.x;
    const int wid = tid >> 5, lane = tid & 31;
    const int cs = ci * KK;
    int b = 0;
    #pragma unroll
    for (int j = 0; j < BB; j++) b += (offset[j] <= cs) ? 1 : 0;
    const __half* qkvh   = g_qkv_h + (size_t)cs * C3;
    const float*  clsrow = g_clsqkv + b * C3;
    const int koff = CC + h * DH, voff = 2 * CC + h * DH;

    // load K,V rows -> smem fp16 (pure 16B copies; cls row converted)
    for (int idx = tid; idx < 2 * NP * 8; idx += 256) {
        int kv = idx >= NP * 8;
        int i  = kv ? idx - NP * 8 : idx;
        int t = i >> 3, u = i & 7;     // u: 16-byte unit (8 halfs)
        int off = kv ? voff : koff;
        uint4 val = make_uint4(0u, 0u, 0u, 0u);
        if (t == 0) {
            const float* src = clsrow + off + u * 8;
            val.x = pack_h2(src[0], src[1]);
            val.y = pack_h2(src[2], src[3]);
            val.z = pack_h2(src[4], src[5]);
            val.w = pack_h2(src[6], src[7]);
        } else if (t <= KK) {
            val = *(const uint4*)(qkvh + (size_t)(t - 1) * C3 + off + u * 8);
        }
        *(uint4*)((kv ? VhB : KhB) + t * KROWB + u * 16) = val;
    }
    __syncthreads();

    const int r0 = lane >> 2;
    const int qp = (lane & 3) * 2;
    const __half2 qscale = __float2half2_rn(0.125f);

    #pragma unroll 1
    for (int mt = wid; mt < 16; mt += 8) {
        const __half* p0 = qkvh + (size_t)(mt * 16 + r0) * C3 + h * DH;
        const __half* p1 = p0 + 8 * C3;

        float acc[34][4];
        #pragma unroll
        for (int nt = 0; nt < 34; nt++)
            acc[nt][0] = acc[nt][1] = acc[nt][2] = acc[nt][3] = 0.f;

        // ---- S = Q K^T ----
        #pragma unroll
        for (int kt = 0; kt < 4; kt++) {
            uint32_t qh[4];
            {
                __half2 v0 = __hmul2(*(const __half2*)(p0 + kt * 16 + qp),     qscale);
                __half2 v1 = __hmul2(*(const __half2*)(p1 + kt * 16 + qp),     qscale);
                __half2 v2 = __hmul2(*(const __half2*)(p0 + kt * 16 + qp + 8), qscale);
                __half2 v3 = __hmul2(*(const __half2*)(p1 + kt * 16 + qp + 8), qscale);
                qh[0] = *(uint32_t*)&v0; qh[1] = *(uint32_t*)&v1;
                qh[2] = *(uint32_t*)&v2; qh[3] = *(uint32_t*)&v3;
            }
            const uint32_t kaddr = KhU + (lane & 7) * KROWB + ((lane >> 3) & 1) * 16 + kt * 32;
            #pragma unroll
            for (int nt = 0; nt < 34; nt++) {
                uint32_t bh[2];
                ldsm_x2(bh, kaddr + nt * 8 * KROWB);
                mma_f16(acc[nt], qh, bh);
            }
        }

        if (qp != 0) { acc[32][0] = -1e30f; acc[32][2] = -1e30f; }
        acc[32][1] = -1e30f; acc[32][3] = -1e30f;
        acc[33][0] = acc[33][1] = acc[33][2] = acc[33][3] = -1e30f;

        float m0 = -1e30f, m1 = -1e30f;
        #pragma unroll
        for (int nt = 0; nt < 34; nt++) {
            m0 = fmaxf(m0, fmaxf(acc[nt][0], acc[nt][1]));
            m1 = fmaxf(m1, fmaxf(acc[nt][2], acc[nt][3]));
        }
        m0 = fmaxf(m0, __shfl_xor_sync(0xffffffffu, m0, 1));
        m0 = fmaxf(m0, __shfl_xor_sync(0xffffffffu, m0, 2));
        m1 = fmaxf(m1, __shfl_xor_sync(0xffffffffu, m1, 1));
        m1 = fmaxf(m1, __shfl_xor_sync(0xffffffffu, m1, 2));
        float s0 = 0.f, s1 = 0.f;
        #pragma unroll
        for (int nt = 0; nt < 34; nt++) {
            acc[nt][0] = __expf(acc[nt][0] - m0);
            acc[nt][1] = __expf(acc[nt][1] - m0);
            acc[nt][2] = __expf(acc[nt][2] - m1);
            acc[nt][3] = __expf(acc[nt][3] - m1);
            s0 += acc[nt][0] + acc[nt][1];
            s1 += acc[nt][2] + acc[nt][3];
        }
        s0 += __shfl_xor_sync(0xffffffffu, s0, 1);
        s0 += __shfl_xor_sync(0xffffffffu, s0, 2);
        s1 += __shfl_xor_sync(0xffffffffu, s1, 1);
        s1 += __shfl_xor_sync(0xffffffffu, s1, 2);
        const float inv0 = 1.f / s0, inv1 = 1.f / s1;

        // ---- O = P V ----
        float o[8][4];
        #pragma unroll
        for (int nt = 0; nt < 8; nt++)
            o[nt][0] = o[nt][1] = o[nt][2] = o[nt][3] = 0.f;

        #pragma unroll
        for (int kt = 0; kt < 17; kt++) {
            uint32_t ah[4];
            ah[0] = pack_h2(acc[2*kt][0] * inv0,   acc[2*kt][1] * inv0);
            ah[1] = pack_h2(acc[2*kt][2] * inv1,   acc[2*kt][3] * inv1);
            ah[2] = pack_h2(acc[2*kt+1][0] * inv0, acc[2*kt+1][1] * inv0);
            ah[3] = pack_h2(acc[2*kt+1][2] * inv1, acc[2*kt+1][3] * inv1);
            const uint32_t vaddr = VhU + (kt * 16 + (lane & 15)) * KROWB;
            #pragma unroll
            for (int nt = 0; nt < 8; nt++) {
                uint32_t bh[2];
                ldsm_x2_t(bh, vaddr + nt * 16);
                mma_f16(o[nt], ah, bh);
            }
        }

        const size_t row0 = (size_t)(cs + mt * 16 + r0) * CC + h * DH;
        const size_t row1 = row0 + 8 * CC;
        #pragma unroll
        for (int nt = 0; nt < 8; nt++) {
            *(uint32_t*)(g_att_h + row0 + nt * 8 + qp) = pack_h2(o[nt][0], o[nt][1]);
            *(uint32_t*)(g_att_h + row1 + nt * 8 + qp) = pack_h2(o[nt][2], o[nt][3]);
        }
    }
}

// ---------------- cls-query attention (fp16 K/V) ----------------
__global__ __launch_bounds__(256)
void cls_attn_kernel(const int* __restrict__ offset)
{
    __shared__ float sS[HH][257];
    const int ci = blockIdx.x, tid = threadIdx.x;
    const int h = tid >> 5, lane = tid & 31;
    const int cs = ci * KK;
    int b = 0;
    #pragma unroll
    for (int j = 0; j < BB; j++) b += (offset[j] <= cs) ? 1 : 0;
    const __half* qkvh   = g_qkv_h + (size_t)cs * C3;
    const float*  clsrow = g_clsqkv + b * C3;
    const int koff = CC + h * DH, voff = 2 * CC + h * DH;

    const float q0 = clsrow[h * DH + lane] * 0.125f;
    const float q1 = clsrow[h * DH + lane + 32] * 0.125f;

    for (int j = 0; j < 257; j++) {
        float k0, k1;
        if (j == 0) {
            k0 = __float2half_rn(clsrow[koff + lane]);       // match fp16 rounding
            k1 = __float2half_rn(clsrow[koff + lane + 32]);
        } else {
            const __half* kr = qkvh + (size_t)(j - 1) * C3 + koff;
            k0 = __half2float(kr[lane]);
            k1 = __half2float(kr[lane + 32]);
        }
        float part = q0 * k0 + q1 * k1;
        #pragma unroll
        for (int o = 16; o; o >>= 1) part += __shfl_xor_sync(0xffffffffu, part, o);
        if (lane == 0) sS[h][j] = part;
    }
    __syncwarp();

    float m = -1e30f;
    for (int j = lane; j < 257; j += 32) m = fmaxf(m, sS[h][j]);
    #pragma unroll
    for (int o = 16; o; o >>= 1) m = fmaxf(m, __shfl_xor_sync(0xffffffffu, m, o));
    float s = 0.f;
    for (int j = lane; j < 257; j += 32) {
        float e = __expf(sS[h][j] - m);
        sS[h][j] = e;
        s += e;
    }
    #pragma unroll
    for (int o = 16; o; o >>= 1) s += __shfl_xor_sync(0xffffffffu, s, o);
    const float inv = 1.f / s;
    __syncwarp();

    float o0 = 0.f, o1 = 0.f;
    for (int j = 0; j < 257; j++) {
        float v0, v1;
        if (j == 0) {
            v0 = clsrow[voff + lane];
            v1 = clsrow[voff + lane + 32];
        } else {
            const __half* vr = qkvh + (size_t)(j - 1) * C3 + voff;
            v0 = __half2float(vr[lane]);
            v1 = __half2float(vr[lane + 32]);
        }
        float p = sS[h][j] * inv;
        o0 += p * v0;
        o1 += p * v1;
    }
    g_clspart[ci * CC + h * DH + lane]      = o0;
    g_clspart[ci * CC + h * DH + lane + 32] = o1;
}

// ---------------- cls reduce ----------------
__global__ __launch_bounds__(256)
void cls_reduce_kernel(const int* __restrict__ offset, float* __restrict__ out_cls)
{
    int gid = blockIdx.x * 256 + threadIdx.x;
    int b = gid >> 9;
    int c = gid & (CC - 1);
    int start = (b == 0) ? 0 : offset[b - 1];
    int end = offset[b];
    int ch0 = start / KK, ch1 = end / KK;
    float s = 0.f;
    for (int ch = ch0; ch < ch1; ch++) s += g_clspart[ch * CC + c];
    out_cls[gid] = s / (float)(ch1 - ch0);
}

// ---------------- launch ----------------
extern "C" void kernel_launch(void* const* d_in, const int* in_sizes, int n_in,
                              void* d_out, int out_size)
{
    const float* feat       = (const float*)d_in[0];
    const float* cls_tokens = (const float*)d_in[1];
    const float* Wqkv       = (const float*)d_in[2];
    const float* bqkv       = (const float*)d_in[3];
    const float* Wproj      = (const float*)d_in[4];
    const float* bproj      = (const float*)d_in[5];
    const int*   order      = (const int*)d_in[6];
    const int*   offset     = (const int*)d_in[8];

    float* out_feat = (float*)d_out;
    float* out_cls  = out_feat + (size_t)NPTS * CC;

    void *qkvp = nullptr;
    void *ah = nullptr, *ath = nullptr;
    void *wq = nullptr, *wp = nullptr;
    cudaGetSymbolAddress(&qkvp, g_qkv_h);
    cudaGetSymbolAddress(&ah, g_Ah);
    cudaGetSymbolAddress(&ath, g_att_h);
    cudaGetSymbolAddress(&wq, g_WqkvT);
    cudaGetSymbolAddress(&wp, g_WprojT);

    cudaFuncSetAttribute(attn_mma_kernel, cudaFuncAttributeMaxDynamicSharedMemorySize,
                         ATT_SMEM);
    cudaFuncSetAttribute(gemm_async_kernel<false, true>,
                         cudaFuncAttributeMaxDynamicSharedMemorySize, GSMEM);
    cudaFuncSetAttribute(gemm_async_kernel<true, false>,
                         cudaFuncAttributeMaxDynamicSharedMemorySize, GSMEM);

    // 0. weight transpose (fp16), feat gather (fp16)
    conv_wt_kernel<<<dim3(C3 / 32, CC / 32), 256>>>(Wqkv, (__half*)wq, CC, C3);
    conv_wt_kernel<<<dim3(CC / 32, CC / 32), 256>>>(Wproj, (__half*)wp, CC, CC);
    conv_feat_kernel<<<(NPTS * (CC / 4)) / 256, 256>>>(feat, order);
    // 1. cls token qkv
    cls_qkv_kernel<<<C3 / 32, 256>>>(cls_tokens, Wqkv, bqkv);
    // 2. qkv GEMM -> fp16 output
    gemm_async_kernel<false, true><<<dim3(C3 / 128, NPTS / 128), 256, GSMEM>>>(
        (const __half*)ah, (const __half*)wq, bqkv, qkvp, order, C3);
    // 3. attention
    attn_mma_kernel<<<dim3(NCH, HH), 256, ATT_SMEM>>>(offset);
    cls_attn_kernel<<<NCH, 256>>>(offset);
    // 4. proj GEMM with scatter -> fp32 output
    gemm_async_kernel<true, false><<<dim3(CC / 128, NPTS / 128), 256, GSMEM>>>(
        (const __half*)ath, (const __half*)wp, bproj, (void*)out_feat, order, CC);
    // 5. cls reduction
    cls_reduce_kernel<<<(BB * CC) / 256, 256>>>(offset, out_cls);
}

// round 11
// speedup vs baseline: 1.6637x; 1.1056x over previous
#include <cuda_runtime.h>
#include <cuda_fp16.h>
#include <cstdint>
#include <cstddef>

#define NPTS 65536
#define BB 4
#define CC 512
#define C3 1536
#define KK 256
#define HH 8
#define DH 64
#define NCH 256   // NPTS/KK

// ---------------- scratch (static device globals; no allocation) ----------------
__device__ __half g_qkv_h[(size_t)NPTS * C3]; // gathered qkv, serialized order (fp16)
__device__ float g_clsqkv[BB * C3];            // cls token qkv (fp32)
__device__ float g_clspart[NCH * CC];          // per-chunk cls attention row
__device__ __half g_Ah[(size_t)NPTS * CC];     // gathered feat (fp16)
__device__ __half g_att_h[(size_t)NPTS * CC];  // attention out (fp16, serialized)
__device__ __half g_WqkvT[(size_t)C3 * CC];    // W^T fp16
__device__ __half g_WprojT[(size_t)CC * CC];

// =============== helpers ===============
__device__ __forceinline__ uint32_t smem_u32(const void* p) {
    uint32_t a;
    asm("{ .reg .u64 t; cvta.to.shared.u64 t, %1; cvt.u32.u64 %0, t; }" : "=r"(a) : "l"(p));
    return a;
}
__device__ __forceinline__ void ldsm_x4(uint32_t* r, uint32_t addr) {
    asm volatile("ldmatrix.sync.aligned.m8n8.x4.shared.b16 {%0,%1,%2,%3}, [%4];"
                 : "=r"(r[0]), "=r"(r[1]), "=r"(r[2]), "=r"(r[3]) : "r"(addr));
}
__device__ __forceinline__ void ldsm_x4_t(uint32_t* r, uint32_t addr) {
    asm volatile("ldmatrix.sync.aligned.m8n8.x4.trans.shared.b16 {%0,%1,%2,%3}, [%4];"
                 : "=r"(r[0]), "=r"(r[1]), "=r"(r[2]), "=r"(r[3]) : "r"(addr));
}
__device__ __forceinline__ void mma_f16(float* c, const uint32_t* a, const uint32_t* b) {
    asm volatile(
        "mma.sync.aligned.m16n8k16.row.col.f32.f16.f16.f32 "
        "{%0,%1,%2,%3}, {%4,%5,%6,%7}, {%8,%9}, {%0,%1,%2,%3};"
        : "+f"(c[0]), "+f"(c[1]), "+f"(c[2]), "+f"(c[3])
        : "r"(a[0]), "r"(a[1]), "r"(a[2]), "r"(a[3]), "r"(b[0]), "r"(b[1]));
}
__device__ __forceinline__ uint32_t pack_h2(float x, float y) {
    __half2 hh = __floats2half2_rn(x, y);
    return *reinterpret_cast<uint32_t*>(&hh);
}
__device__ __forceinline__ void cp_async16(uint32_t dst, const void* src) {
    asm volatile("cp.async.cg.shared.global [%0], [%1], 16;" :: "r"(dst), "l"(src) : "memory");
}
#define CP_COMMIT() asm volatile("cp.async.commit_group;" ::: "memory")
#define CP_WAIT1()  asm volatile("cp.async.wait_group 1;" ::: "memory")

// ---------------- W transpose to fp16 ----------------
__global__ __launch_bounds__(256)
void conv_wt_kernel(const float* __restrict__ W, __half* __restrict__ T, int K, int N)
{
    __shared__ float t[32][33];
    int n0 = blockIdx.x * 32, k0 = blockIdx.y * 32;
    int tx = threadIdx.x & 31, ty = threadIdx.x >> 5;
    #pragma unroll
    for (int j = 0; j < 32; j += 8)
        t[ty + j][tx] = W[(size_t)(k0 + ty + j) * N + n0 + tx];
    __syncthreads();
    #pragma unroll
    for (int j = 0; j < 32; j += 8) {
        int n = n0 + ty + j, k = k0 + tx;
        T[(size_t)n * K + k] = __float2half_rn(t[tx][ty + j]);
    }
}

// ---------------- feat gather -> fp16 ----------------
__global__ __launch_bounds__(256)
void conv_feat_kernel(const float* __restrict__ feat, const int* __restrict__ order)
{
    size_t idx = (size_t)blockIdx.x * 256 + threadIdx.x;
    int m = (int)(idx >> 7);
    int u = (int)(idx & 127);
    const float4 v = *(const float4*)(feat + (size_t)order[m] * CC + u * 4);
    *(uint2*)(g_Ah + (size_t)m * CC + u * 4) =
        make_uint2(pack_h2(v.x, v.y), pack_h2(v.z, v.w));
}

// ---- cp.async GEMM: 128x128 tile, Kc=64, 3 stages, single fp16, 2 CTAs/SM ----
#define QROWB  144
#define QTILE  (128 * QROWB)       // 18432
#define QSTAGE (2 * QTILE)         // 36864 (A | B)
#define SMHDR  1024
#define GSMEM  (SMHDR + 3 * QSTAGE)   // 111616

template<bool SCATTER, bool OUTHALF>
__global__ __launch_bounds__(256, 2)
void gemm_async_kernel(const __half* __restrict__ Ah, const __half* __restrict__ Bh,
                       const float* __restrict__ bias, void* __restrict__ Cv,
                       const int* __restrict__ order, int Ntot)
{
    extern __shared__ char sm[];
    const uint32_t sb = smem_u32(sm);
    const int tid = threadIdx.x, wid = tid >> 5, lane = tid & 31;
    const int n0 = blockIdx.x * 128, m0 = blockIdx.y * 128;
    float* bias_s = (float*)sm;
    int*   rowidx = (int*)(sm + 512);

    auto issue_stage = [&](int c, int stage) {
        const size_t kb = (size_t)c * 128;   // byte offset (c*64 fp16)
        const uint32_t dbase = sb + SMHDR + stage * QSTAGE;
        #pragma unroll
        for (int i = 0; i < 8; i++) {
            const int g = tid + i * 256;         // 0..2047
            const int tile = g >> 10;
            const int u = g & 1023;
            const int row = u >> 3, col8 = u & 7;
            const char* src = (const char*)(tile ? Bh + (size_t)(n0 + row) * CC
                                                 : Ah + (size_t)(m0 + row) * CC) + kb;
            cp_async16(dbase + tile * QTILE + row * QROWB + col8 * 16, src + col8 * 16);
        }
    };

    issue_stage(0, 0); CP_COMMIT();
    issue_stage(1, 1); CP_COMMIT();

    if (tid < 128) {
        bias_s[tid] = bias[n0 + tid];
        if (SCATTER) rowidx[tid] = order[m0 + tid];
    }
    __syncthreads();

    const int wm = (wid & 1) * 64;
    const int wn = (wid >> 1) * 32;

    float acc[4][4][4];
    #pragma unroll
    for (int nt = 0; nt < 4; nt++) {
        float b0 = bias_s[wn + nt * 8 + 2 * (lane & 3)];
        float b1 = bias_s[wn + nt * 8 + 2 * (lane & 3) + 1];
        #pragma unroll
        for (int mt = 0; mt < 4; mt++) {
            acc[mt][nt][0] = b0; acc[mt][nt][1] = b1;
            acc[mt][nt][2] = b0; acc[mt][nt][3] = b1;
        }
    }

    const uint32_t a_lm  = sb + SMHDR + (wm + (lane & 15)) * QROWB + ((lane >> 4) & 1) * 16;
    const uint32_t b_lm4 = sb + SMHDR + QTILE
                           + (wn + (lane & 7) + ((lane >> 4) & 1) * 8) * QROWB
                           + ((lane >> 3) & 1) * 16;

    const int NC = CC / 64;   // 8
    #pragma unroll 1
    for (int c = 0; c < NC; c++) {
        CP_WAIT1();
        __syncthreads();
        if (c + 2 < NC) issue_stage(c + 2, (c + 2) % 3);
        CP_COMMIT();

        const uint32_t abase = a_lm  + (c % 3) * QSTAGE;
        const uint32_t bbase = b_lm4 + (c % 3) * QSTAGE;
        #pragma unroll
        for (int ks = 0; ks < 4; ks++) {
            const int ko = ks * 32;
            uint32_t ah[4][4], bh[2][4];
            #pragma unroll
            for (int mt = 0; mt < 4; mt++)
                ldsm_x4(ah[mt], abase + mt * 16 * QROWB + ko);
            #pragma unroll
            for (int p = 0; p < 2; p++)
                ldsm_x4(bh[p], bbase + p * 16 * QROWB + ko);
            #pragma unroll
            for (int mt = 0; mt < 4; mt++)
                #pragma unroll
                for (int nt = 0; nt < 4; nt++)
                    mma_f16(acc[mt][nt], ah[mt], &bh[nt >> 1][(nt & 1) * 2]);
        }
    }

    #pragma unroll
    for (int mt = 0; mt < 4; mt++) {
        int lrow = wm + mt * 16 + (lane >> 2);
        int d0 = SCATTER ? rowidx[lrow]     : (m0 + lrow);
        int d1 = SCATTER ? rowidx[lrow + 8] : (m0 + lrow + 8);
        #pragma unroll
        for (int nt = 0; nt < 4; nt++) {
            int col = n0 + wn + nt * 8 + 2 * (lane & 3);
            if (OUTHALF) {
                __half* C = (__half*)Cv;
                *(uint32_t*)(C + (size_t)d0 * Ntot + col) =
                    pack_h2(acc[mt][nt][0], acc[mt][nt][1]);
                *(uint32_t*)(C + (size_t)d1 * Ntot + col) =
                    pack_h2(acc[mt][nt][2], acc[mt][nt][3]);
            } else {
                float* C = (float*)Cv;
                *(float2*)(C + (size_t)d0 * Ntot + col) =
                    make_float2(acc[mt][nt][0], acc[mt][nt][1]);
                *(float2*)(C + (size_t)d1 * Ntot + col) =
                    make_float2(acc[mt][nt][2], acc[mt][nt][3]);
            }
        }
    }
}

// ---------------- cls qkv: parallel k-split, grid 48 ----------------
__global__ __launch_bounds__(256)
void cls_qkv_kernel(const float* __restrict__ cls_tokens,
                    const float* __restrict__ Wqkv,
                    const float* __restrict__ bqkv)
{
    __shared__ float ct[BB * CC];
    __shared__ float red[8][BB][32];
    const int tid = threadIdx.x, lane = tid & 31, seg = tid >> 5;
    for (int i = tid; i < BB * CC; i += 256) ct[i] = cls_tokens[i];
    __syncthreads();
    const int n = blockIdx.x * 32 + lane;
    float acc[BB] = {0.f, 0.f, 0.f, 0.f};
    for (int k = seg * 64; k < seg * 64 + 64; k++) {
        float w = Wqkv[(size_t)k * C3 + n];
        #pragma unroll
        for (int b = 0; b < BB; b++) acc[b] += ct[b * CC + k] * w;
    }
    #pragma unroll
    for (int b = 0; b < BB; b++) red[seg][b][lane] = acc[b];
    __syncthreads();
    if (seg < BB) {
        float s = bqkv[n];
        #pragma unroll
        for (int j = 0; j < 8; j++) s += red[j][seg][lane];
        g_clsqkv[seg * C3 + n] = s;
    }
}

// ---------------- tensor-core attention (token queries), single fp16 ----------------
#define NP 272
#define KROWB 144
#define ATT_SMEM (2 * NP * KROWB)   // 78336

__global__ __launch_bounds__(256)
void attn_mma_kernel(const int* __restrict__ offset)
{
    extern __shared__ char sm[];
    char* KhB = sm;
    char* VhB = sm + NP * KROWB;
    const uint32_t sb = smem_u32(sm);
    const uint32_t KhU = sb;
    const uint32_t VhU = sb + NP * KROWB;

    const int ci = blockIdx.x, h = blockIdx.y, tid = threadIdx.x;
    const int wid = tid >> 5, lane = tid & 31;
    const int cs = ci * KK;
    int b = 0;
    #pragma unroll
    for (int j = 0; j < BB; j++) b += (offset[j] <= cs) ? 1 : 0;
    const __half* qkvh   = g_qkv_h + (size_t)cs * C3;
    const float*  clsrow = g_clsqkv + b * C3;
    const int koff = CC + h * DH, voff = 2 * CC + h * DH;

    // load K,V rows -> smem fp16 (pure 16B copies; cls row converted)
    for (int idx = tid; idx < 2 * NP * 8; idx += 256) {
        int kv = idx >= NP * 8;
        int i  = kv ? idx - NP * 8 : idx;
        int t = i >> 3, u = i & 7;
        int off = kv ? voff : koff;
        uint4 val = make_uint4(0u, 0u, 0u, 0u);
        if (t == 0) {
            const float* src = clsrow + off + u * 8;
            val.x = pack_h2(src[0], src[1]);
            val.y = pack_h2(src[2], src[3]);
            val.z = pack_h2(src[4], src[5]);
            val.w = pack_h2(src[6], src[7]);
        } else if (t <= KK) {
            val = *(const uint4*)(qkvh + (size_t)(t - 1) * C3 + off + u * 8);
        }
        *(uint4*)((kv ? VhB : KhB) + t * KROWB + u * 16) = val;
    }
    __syncthreads();

    const int r0 = lane >> 2;
    const int qp = (lane & 3) * 2;
    const __half2 qscale = __float2half2_rn(0.125f);

    #pragma unroll 1
    for (int mt = wid; mt < 16; mt += 8) {
        const __half* p0 = qkvh + (size_t)(mt * 16 + r0) * C3 + h * DH;
        const __half* p1 = p0 + 8 * C3;

        float acc[34][4];
        #pragma unroll
        for (int nt = 0; nt < 34; nt++)
            acc[nt][0] = acc[nt][1] = acc[nt][2] = acc[nt][3] = 0.f;

        // ---- S = Q K^T (paired ldsm_x4 over n-tiles) ----
        #pragma unroll
        for (int kt = 0; kt < 4; kt++) {
            uint32_t qh[4];
            {
                __half2 v0 = __hmul2(*(const __half2*)(p0 + kt * 16 + qp),     qscale);
                __half2 v1 = __hmul2(*(const __half2*)(p1 + kt * 16 + qp),     qscale);
                __half2 v2 = __hmul2(*(const __half2*)(p0 + kt * 16 + qp + 8), qscale);
                __half2 v3 = __hmul2(*(const __half2*)(p1 + kt * 16 + qp + 8), qscale);
                qh[0] = *(uint32_t*)&v0; qh[1] = *(uint32_t*)&v1;
                qh[2] = *(uint32_t*)&v2; qh[3] = *(uint32_t*)&v3;
            }
            const uint32_t kaddr4 = KhU
                + ((lane & 7) + ((lane >> 4) & 1) * 8) * KROWB
                + ((lane >> 3) & 1) * 16 + kt * 32;
            #pragma unroll
            for (int p = 0; p < 17; p++) {
                uint32_t b4[4];
                ldsm_x4(b4, kaddr4 + p * 16 * KROWB);
                mma_f16(acc[2 * p],     qh, &b4[0]);
                mma_f16(acc[2 * p + 1], qh, &b4[2]);
            }
        }

        if (qp != 0) { acc[32][0] = -1e30f; acc[32][2] = -1e30f; }
        acc[32][1] = -1e30f; acc[32][3] = -1e30f;
        acc[33][0] = acc[33][1] = acc[33][2] = acc[33][3] = -1e30f;

        float m0 = -1e30f, m1 = -1e30f;
        #pragma unroll
        for (int nt = 0; nt < 34; nt++) {
            m0 = fmaxf(m0, fmaxf(acc[nt][0], acc[nt][1]));
            m1 = fmaxf(m1, fmaxf(acc[nt][2], acc[nt][3]));
        }
        m0 = fmaxf(m0, __shfl_xor_sync(0xffffffffu, m0, 1));
        m0 = fmaxf(m0, __shfl_xor_sync(0xffffffffu, m0, 2));
        m1 = fmaxf(m1, __shfl_xor_sync(0xffffffffu, m1, 1));
        m1 = fmaxf(m1, __shfl_xor_sync(0xffffffffu, m1, 2));
        float s0 = 0.f, s1 = 0.f;
        #pragma unroll
        for (int nt = 0; nt < 34; nt++) {
            acc[nt][0] = __expf(acc[nt][0] - m0);
            acc[nt][1] = __expf(acc[nt][1] - m0);
            acc[nt][2] = __expf(acc[nt][2] - m1);
            acc[nt][3] = __expf(acc[nt][3] - m1);
            s0 += acc[nt][0] + acc[nt][1];
            s1 += acc[nt][2] + acc[nt][3];
        }
        s0 += __shfl_xor_sync(0xffffffffu, s0, 1);
        s0 += __shfl_xor_sync(0xffffffffu, s0, 2);
        s1 += __shfl_xor_sync(0xffffffffu, s1, 1);
        s1 += __shfl_xor_sync(0xffffffffu, s1, 2);
        const float inv0 = 1.f / s0, inv1 = 1.f / s1;

        // ---- O = P V (paired ldsm_x4.trans) ----
        float o[8][4];
        #pragma unroll
        for (int nt = 0; nt < 8; nt++)
            o[nt][0] = o[nt][1] = o[nt][2] = o[nt][3] = 0.f;

        #pragma unroll
        for (int kt = 0; kt < 17; kt++) {
            uint32_t ah[4];
            ah[0] = pack_h2(acc[2*kt][0] * inv0,   acc[2*kt][1] * inv0);
            ah[1] = pack_h2(acc[2*kt][2] * inv1,   acc[2*kt][3] * inv1);
            ah[2] = pack_h2(acc[2*kt+1][0] * inv0, acc[2*kt+1][1] * inv0);
            ah[3] = pack_h2(acc[2*kt+1][2] * inv1, acc[2*kt+1][3] * inv1);
            const uint32_t vaddr4 = VhU + (kt * 16 + (lane & 15)) * KROWB
                                    + ((lane >> 4) & 1) * 16;
            #pragma unroll
            for (int p = 0; p < 4; p++) {
                uint32_t b4[4];
                ldsm_x4_t(b4, vaddr4 + p * 32);
                mma_f16(o[2 * p],     ah, &b4[0]);
                mma_f16(o[2 * p + 1], ah, &b4[2]);
            }
        }

        const size_t row0 = (size_t)(cs + mt * 16 + r0) * CC + h * DH;
        const size_t row1 = row0 + 8 * CC;
        #pragma unroll
        for (int nt = 0; nt < 8; nt++) {
            *(uint32_t*)(g_att_h + row0 + nt * 8 + qp) = pack_h2(o[nt][0], o[nt][1]);
            *(uint32_t*)(g_att_h + row1 + nt * 8 + qp) = pack_h2(o[nt][2], o[nt][3]);
        }
    }
}

// ---------------- cls-query attention (fp16 K/V) ----------------
__global__ __launch_bounds__(256)
void cls_attn_kernel(const int* __restrict__ offset)
{
    __shared__ float sS[HH][257];
    const int ci = blockIdx.x, tid = threadIdx.x;
    const int h = tid >> 5, lane = tid & 31;
    const int cs = ci * KK;
    int b = 0;
    #pragma unroll
    for (int j = 0; j < BB; j++) b += (offset[j] <= cs) ? 1 : 0;
    const __half* qkvh   = g_qkv_h + (size_t)cs * C3;
    const float*  clsrow = g_clsqkv + b * C3;
    const int koff = CC + h * DH, voff = 2 * CC + h * DH;

    const float q0 = clsrow[h * DH + lane] * 0.125f;
    const float q1 = clsrow[h * DH + lane + 32] * 0.125f;

    for (int j = 0; j < 257; j++) {
        float k0, k1;
        if (j == 0) {
            k0 = __float2half_rn(clsrow[koff + lane]);
            k1 = __float2half_rn(clsrow[koff + lane + 32]);
        } else {
            const __half* kr = qkvh + (size_t)(j - 1) * C3 + koff;
            k0 = __half2float(kr[lane]);
            k1 = __half2float(kr[lane + 32]);
        }
        float part = q0 * k0 + q1 * k1;
        #pragma unroll
        for (int o = 16; o; o >>= 1) part += __shfl_xor_sync(0xffffffffu, part, o);
        if (lane == 0) sS[h][j] = part;
    }
    __syncwarp();

    float m = -1e30f;
    for (int j = lane; j < 257; j += 32) m = fmaxf(m, sS[h][j]);
    #pragma unroll
    for (int o = 16; o; o >>= 1) m = fmaxf(m, __shfl_xor_sync(0xffffffffu, m, o));
    float s = 0.f;
    for (int j = lane; j < 257; j += 32) {
        float e = __expf(sS[h][j] - m);
        sS[h][j] = e;
        s += e;
    }
    #pragma unroll
    for (int o = 16; o; o >>= 1) s += __shfl_xor_sync(0xffffffffu, s, o);
    const float inv = 1.f / s;
    __syncwarp();

    float o0 = 0.f, o1 = 0.f;
    for (int j = 0; j < 257; j++) {
        float v0, v1;
        if (j == 0) {
            v0 = clsrow[voff + lane];
            v1 = clsrow[voff + lane + 32];
        } else {
            const __half* vr = qkvh + (size_t)(j - 1) * C3 + voff;
            v0 = __half2float(vr[lane]);
            v1 = __half2float(vr[lane + 32]);
        }
        float p = sS[h][j] * inv;
        o0 += p * v0;
        o1 += p * v1;
    }
    g_clspart[ci * CC + h * DH + lane]      = o0;
    g_clspart[ci * CC + h * DH + lane + 32] = o1;
}

// ---------------- cls reduce ----------------
__global__ __launch_bounds__(256)
void cls_reduce_kernel(const int* __restrict__ offset, float* __restrict__ out_cls)
{
    int gid = blockIdx.x * 256 + threadIdx.x;
    int b = gid >> 9;
    int c = gid & (CC - 1);
    int start = (b == 0) ? 0 : offset[b - 1];
    int end = offset[b];
    int ch0 = start / KK, ch1 = end / KK;
    float s = 0.f;
    for (int ch = ch0; ch < ch1; ch++) s += g_clspart[ch * CC + c];
    out_cls[gid] = s / (float)(ch1 - ch0);
}

// ---------------- launch ----------------
extern "C" void kernel_launch(void* const* d_in, const int* in_sizes, int n_in,
                              void* d_out, int out_size)
{
    const float* feat       = (const float*)d_in[0];
    const float* cls_tokens = (const float*)d_in[1];
    const float* Wqkv       = (const float*)d_in[2];
    const float* bqkv       = (const float*)d_in[3];
    const float* Wproj      = (const float*)d_in[4];
    const float* bproj      = (const float*)d_in[5];
    const int*   order      = (const int*)d_in[6];
    const int*   offset     = (const int*)d_in[8];

    float* out_feat = (float*)d_out;
    float* out_cls  = out_feat + (size_t)NPTS * CC;

    void *qkvp = nullptr;
    void *ah = nullptr, *ath = nullptr;
    void *wq = nullptr, *wp = nullptr;
    cudaGetSymbolAddress(&qkvp, g_qkv_h);
    cudaGetSymbolAddress(&ah, g_Ah);
    cudaGetSymbolAddress(&ath, g_att_h);
    cudaGetSymbolAddress(&wq, g_WqkvT);
    cudaGetSymbolAddress(&wp, g_WprojT);

    cudaFuncSetAttribute(attn_mma_kernel, cudaFuncAttributeMaxDynamicSharedMemorySize,
                         ATT_SMEM);
    cudaFuncSetAttribute(gemm_async_kernel<false, true>,
                         cudaFuncAttributeMaxDynamicSharedMemorySize, GSMEM);
    cudaFuncSetAttribute(gemm_async_kernel<true, false>,
                         cudaFuncAttributeMaxDynamicSharedMemorySize, GSMEM);

    // 0. weight transpose (fp16), feat gather (fp16)
    conv_wt_kernel<<<dim3(C3 / 32, CC / 32), 256>>>(Wqkv, (__half*)wq, CC, C3);
    conv_wt_kernel<<<dim3(CC / 32, CC / 32), 256>>>(Wproj, (__half*)wp, CC, CC);
    conv_feat_kernel<<<(NPTS * (CC / 4)) / 256, 256>>>(feat, order);
    // 1. cls token qkv
    cls_qkv_kernel<<<C3 / 32, 256>>>(cls_tokens, Wqkv, bqkv);
    // 2. qkv GEMM -> fp16 output
    gemm_async_kernel<false, true><<<dim3(C3 / 128, NPTS / 128), 256, GSMEM>>>(
        (const __half*)ah, (const __half*)wq, bqkv, qkvp, order, C3);
    // 3. attention
    attn_mma_kernel<<<dim3(NCH, HH), 256, ATT_SMEM>>>(offset);
    cls_attn_kernel<<<NCH, 256>>>(offset);
    // 4. proj GEMM with scatter -> fp32 output
    gemm_async_kernel<true, false><<<dim3(CC / 128, NPTS / 128), 256, GSMEM>>>(
        (const __half*)ath, (const __half*)wp, bproj, (void*)out_feat, order, CC);
    // 5. cls reduction
    cls_reduce_kernel<<<(BB * CC) / 256, 256>>>(offset, out_cls);
}

// round 12
// speedup vs baseline: 1.9082x; 1.1469x over previous
#include <cuda_runtime.h>
#include <cuda_fp16.h>
#include <cstdint>
#include <cstddef>

#define NPTS 65536
#define BB 4
#define CC 512
#define C3 1536
#define KK 256
#define HH 8
#define DH 64
#define NCH 256   // NPTS/KK

// ---------------- scratch (static device globals; no allocation) ----------------
__device__ __half g_qkv_h[(size_t)NPTS * C3]; // gathered qkv, serialized order (fp16)
__device__ float g_clsqkv[BB * C3];            // cls token qkv (fp32)
__device__ float g_clspart[NCH * CC];          // per-chunk cls attention row
__device__ __half g_Ah[(size_t)NPTS * CC];     // gathered feat (fp16)
__device__ __half g_att_h[(size_t)NPTS * CC];  // attention out (fp16, serialized)
__device__ __half g_WqkvT[(size_t)C3 * CC];    // W^T fp16
__device__ __half g_WprojT[(size_t)CC * CC];

// =============== helpers ===============
__device__ __forceinline__ uint32_t smem_u32(const void* p) {
    uint32_t a;
    asm("{ .reg .u64 t; cvta.to.shared.u64 t, %1; cvt.u32.u64 %0, t; }" : "=r"(a) : "l"(p));
    return a;
}
__device__ __forceinline__ void ldsm_x4(uint32_t* r, uint32_t addr) {
    asm volatile("ldmatrix.sync.aligned.m8n8.x4.shared.b16 {%0,%1,%2,%3}, [%4];"
                 : "=r"(r[0]), "=r"(r[1]), "=r"(r[2]), "=r"(r[3]) : "r"(addr));
}
__device__ __forceinline__ void ldsm_x4_t(uint32_t* r, uint32_t addr) {
    asm volatile("ldmatrix.sync.aligned.m8n8.x4.trans.shared.b16 {%0,%1,%2,%3}, [%4];"
                 : "=r"(r[0]), "=r"(r[1]), "=r"(r[2]), "=r"(r[3]) : "r"(addr));
}
__device__ __forceinline__ void mma_f16(float* c, const uint32_t* a, const uint32_t* b) {
    asm volatile(
        "mma.sync.aligned.m16n8k16.row.col.f32.f16.f16.f32 "
        "{%0,%1,%2,%3}, {%4,%5,%6,%7}, {%8,%9}, {%0,%1,%2,%3};"
        : "+f"(c[0]), "+f"(c[1]), "+f"(c[2]), "+f"(c[3])
        : "r"(a[0]), "r"(a[1]), "r"(a[2]), "r"(a[3]), "r"(b[0]), "r"(b[1]));
}
__device__ __forceinline__ uint32_t pack_h2(float x, float y) {
    __half2 hh = __floats2half2_rn(x, y);
    return *reinterpret_cast<uint32_t*>(&hh);
}
__device__ __forceinline__ void cp_async16(uint32_t dst, const void* src) {
    asm volatile("cp.async.cg.shared.global [%0], [%1], 16;" :: "r"(dst), "l"(src) : "memory");
}
#define CP_COMMIT() asm volatile("cp.async.commit_group;" ::: "memory")
#define CP_WAIT1()  asm volatile("cp.async.wait_group 1;" ::: "memory")

// ---------------- W transpose to fp16 ----------------
__global__ __launch_bounds__(256)
void conv_wt_kernel(const float* __restrict__ W, __half* __restrict__ T, int K, int N)
{
    __shared__ float t[32][33];
    int n0 = blockIdx.x * 32, k0 = blockIdx.y * 32;
    int tx = threadIdx.x & 31, ty = threadIdx.x >> 5;
    #pragma unroll
    for (int j = 0; j < 32; j += 8)
        t[ty + j][tx] = W[(size_t)(k0 + ty + j) * N + n0 + tx];
    __syncthreads();
    #pragma unroll
    for (int j = 0; j < 32; j += 8) {
        int n = n0 + ty + j, k = k0 + tx;
        T[(size_t)n * K + k] = __float2half_rn(t[tx][ty + j]);
    }
}

// ---------------- feat gather -> fp16 ----------------
__global__ __launch_bounds__(256)
void conv_feat_kernel(const float* __restrict__ feat, const int* __restrict__ order)
{
    size_t idx = (size_t)blockIdx.x * 256 + threadIdx.x;
    int m = (int)(idx >> 7);
    int u = (int)(idx & 127);
    const float4 v = *(const float4*)(feat + (size_t)order[m] * CC + u * 4);
    *(uint2*)(g_Ah + (size_t)m * CC + u * 4) =
        make_uint2(pack_h2(v.x, v.y), pack_h2(v.z, v.w));
}

// ---- cp.async GEMM: 128x128 tile, Kc=64, 3 stages, single fp16, 2 CTAs/SM ----
#define QROWB  144
#define QTILE  (128 * QROWB)       // 18432
#define QSTAGE (2 * QTILE)         // 36864 (A | B)
#define SMHDR  1024
#define GSMEM  (SMHDR + 3 * QSTAGE)   // 111616

template<bool SCATTER, bool OUTHALF>
__global__ __launch_bounds__(256, 2)
void gemm_async_kernel(const __half* __restrict__ Ah, const __half* __restrict__ Bh,
                       const float* __restrict__ bias, void* __restrict__ Cv,
                       const int* __restrict__ order, int Ntot)
{
    extern __shared__ char sm[];
    const uint32_t sb = smem_u32(sm);
    const int tid = threadIdx.x, wid = tid >> 5, lane = tid & 31;
    const int n0 = blockIdx.x * 128, m0 = blockIdx.y * 128;
    float* bias_s = (float*)sm;
    int*   rowidx = (int*)(sm + 512);

    auto issue_stage = [&](int c, int stage) {
        const size_t kb = (size_t)c * 128;
        const uint32_t dbase = sb + SMHDR + stage * QSTAGE;
        #pragma unroll
        for (int i = 0; i < 8; i++) {
            const int g = tid + i * 256;
            const int tile = g >> 10;
            const int u = g & 1023;
            const int row = u >> 3, col8 = u & 7;
            const char* src = (const char*)(tile ? Bh + (size_t)(n0 + row) * CC
                                                 : Ah + (size_t)(m0 + row) * CC) + kb;
            cp_async16(dbase + tile * QTILE + row * QROWB + col8 * 16, src + col8 * 16);
        }
    };

    issue_stage(0, 0); CP_COMMIT();
    issue_stage(1, 1); CP_COMMIT();

    if (tid < 128) {
        bias_s[tid] = bias[n0 + tid];
        if (SCATTER) rowidx[tid] = order[m0 + tid];
    }
    __syncthreads();

    const int wm = (wid & 1) * 64;
    const int wn = (wid >> 1) * 32;

    float acc[4][4][4];
    #pragma unroll
    for (int nt = 0; nt < 4; nt++) {
        float b0 = bias_s[wn + nt * 8 + 2 * (lane & 3)];
        float b1 = bias_s[wn + nt * 8 + 2 * (lane & 3) + 1];
        #pragma unroll
        for (int mt = 0; mt < 4; mt++) {
            acc[mt][nt][0] = b0; acc[mt][nt][1] = b1;
            acc[mt][nt][2] = b0; acc[mt][nt][3] = b1;
        }
    }

    const uint32_t a_lm  = sb + SMHDR + (wm + (lane & 15)) * QROWB + ((lane >> 4) & 1) * 16;
    const uint32_t b_lm4 = sb + SMHDR + QTILE
                           + (wn + (lane & 7) + ((lane >> 4) & 1) * 8) * QROWB
                           + ((lane >> 3) & 1) * 16;

    const int NC = CC / 64;   // 8
    #pragma unroll 1
    for (int c = 0; c < NC; c++) {
        CP_WAIT1();
        __syncthreads();
        if (c + 2 < NC) issue_stage(c + 2, (c + 2) % 3);
        CP_COMMIT();

        const uint32_t abase = a_lm  + (c % 3) * QSTAGE;
        const uint32_t bbase = b_lm4 + (c % 3) * QSTAGE;
        #pragma unroll
        for (int ks = 0; ks < 4; ks++) {
            const int ko = ks * 32;
            uint32_t ah[4][4], bh[2][4];
            #pragma unroll
            for (int mt = 0; mt < 4; mt++)
                ldsm_x4(ah[mt], abase + mt * 16 * QROWB + ko);
            #pragma unroll
            for (int p = 0; p < 2; p++)
                ldsm_x4(bh[p], bbase + p * 16 * QROWB + ko);
            #pragma unroll
            for (int mt = 0; mt < 4; mt++)
                #pragma unroll
                for (int nt = 0; nt < 4; nt++)
                    mma_f16(acc[mt][nt], ah[mt], &bh[nt >> 1][(nt & 1) * 2]);
        }
    }

    #pragma unroll
    for (int mt = 0; mt < 4; mt++) {
        int lrow = wm + mt * 16 + (lane >> 2);
        int d0 = SCATTER ? rowidx[lrow]     : (m0 + lrow);
        int d1 = SCATTER ? rowidx[lrow + 8] : (m0 + lrow + 8);
        #pragma unroll
        for (int nt = 0; nt < 4; nt++) {
            int col = n0 + wn + nt * 8 + 2 * (lane & 3);
            if (OUTHALF) {
                __half* C = (__half*)Cv;
                *(uint32_t*)(C + (size_t)d0 * Ntot + col) =
                    pack_h2(acc[mt][nt][0], acc[mt][nt][1]);
                *(uint32_t*)(C + (size_t)d1 * Ntot + col) =
                    pack_h2(acc[mt][nt][2], acc[mt][nt][3]);
            } else {
                float* C = (float*)Cv;
                *(float2*)(C + (size_t)d0 * Ntot + col) =
                    make_float2(acc[mt][nt][0], acc[mt][nt][1]);
                *(float2*)(C + (size_t)d1 * Ntot + col) =
                    make_float2(acc[mt][nt][2], acc[mt][nt][3]);
            }
        }
    }
}

// ---------------- cls qkv: parallel k-split, grid 48 ----------------
__global__ __launch_bounds__(256)
void cls_qkv_kernel(const float* __restrict__ cls_tokens,
                    const float* __restrict__ Wqkv,
                    const float* __restrict__ bqkv)
{
    __shared__ float ct[BB * CC];
    __shared__ float red[8][BB][32];
    const int tid = threadIdx.x, lane = tid & 31, seg = tid >> 5;
    for (int i = tid; i < BB * CC; i += 256) ct[i] = cls_tokens[i];
    __syncthreads();
    const int n = blockIdx.x * 32 + lane;
    float acc[BB] = {0.f, 0.f, 0.f, 0.f};
    for (int k = seg * 64; k < seg * 64 + 64; k++) {
        float w = Wqkv[(size_t)k * C3 + n];
        #pragma unroll
        for (int b = 0; b < BB; b++) acc[b] += ct[b * CC + k] * w;
    }
    #pragma unroll
    for (int b = 0; b < BB; b++) red[seg][b][lane] = acc[b];
    __syncthreads();
    if (seg < BB) {
        float s = bqkv[n];
        #pragma unroll
        for (int j = 0; j < 8; j++) s += red[j][seg][lane];
        g_clsqkv[seg * C3 + n] = s;
    }
}

// ---------------- tensor-core attention + fused cls-query attention ----------------
#define NP 272
#define KROWB 144
#define SM_KV   (2 * NP * KROWB)          // 78336
#define SM_QCS  SM_KV                      // 64 floats (cls query, scaled)
#define SM_SC   (SM_QCS + 256)             // 260 floats (cls scores / probs + inv)
#define SM_RED  (SM_SC + 1040)             // 256 floats (PV partials)
#define ATT_SMEM (SM_RED + 1024)           // 80656

__global__ __launch_bounds__(256)
void attn_mma_kernel(const int* __restrict__ offset)
{
    extern __shared__ char sm[];
    char* KhB = sm;
    char* VhB = sm + NP * KROWB;
    float* qcs = (float*)(sm + SM_QCS);
    float* sc  = (float*)(sm + SM_SC);
    float* red = (float*)(sm + SM_RED);
    const uint32_t sb = smem_u32(sm);
    const uint32_t KhU = sb;
    const uint32_t VhU = sb + NP * KROWB;

    const int ci = blockIdx.x, h = blockIdx.y, tid = threadIdx.x;
    const int wid = tid >> 5, lane = tid & 31;
    const int cs = ci * KK;
    int b = 0;
    #pragma unroll
    for (int j = 0; j < BB; j++) b += (offset[j] <= cs) ? 1 : 0;
    const __half* qkvh   = g_qkv_h + (size_t)cs * C3;
    const float*  clsrow = g_clsqkv + b * C3;
    const int koff = CC + h * DH, voff = 2 * CC + h * DH;

    // load K,V rows -> smem fp16 (pure 16B copies; cls row converted)
    for (int idx = tid; idx < 2 * NP * 8; idx += 256) {
        int kv = idx >= NP * 8;
        int i  = kv ? idx - NP * 8 : idx;
        int t = i >> 3, u = i & 7;
        int off = kv ? voff : koff;
        uint4 val = make_uint4(0u, 0u, 0u, 0u);
        if (t == 0) {
            const float* src = clsrow + off + u * 8;
            val.x = pack_h2(src[0], src[1]);
            val.y = pack_h2(src[2], src[3]);
            val.z = pack_h2(src[4], src[5]);
            val.w = pack_h2(src[6], src[7]);
        } else if (t <= KK) {
            val = *(const uint4*)(qkvh + (size_t)(t - 1) * C3 + off + u * 8);
        }
        *(uint4*)((kv ? VhB : KhB) + t * KROWB + u * 16) = val;
    }
    if (tid < 64) qcs[tid] = clsrow[h * DH + tid] * 0.125f;
    __syncthreads();

    // ===== fused cls-query attention (uses smem K/V) =====
    // S: one key per thread (tid 0 also does key 256)
    for (int j = tid; j < 257; j += 256) {
        float s = 0.f;
        #pragma unroll
        for (int u = 0; u < 8; u++) {
            uint4 k4 = *(const uint4*)(KhB + j * KROWB + u * 16);
            const __half2* h2 = (const __half2*)&k4;
            #pragma unroll
            for (int e = 0; e < 4; e++) {
                float2 kf = __half22float2(h2[e]);
                s += qcs[u * 8 + e * 2] * kf.x + qcs[u * 8 + e * 2 + 1] * kf.y;
            }
        }
        sc[j] = s;
    }
    __syncthreads();
    if (wid == 0) {
        float m = -1e30f;
        for (int j = lane; j < 257; j += 32) m = fmaxf(m, sc[j]);
        #pragma unroll
        for (int o = 16; o; o >>= 1) m = fmaxf(m, __shfl_xor_sync(0xffffffffu, m, o));
        float ssum = 0.f;
        for (int j = lane; j < 257; j += 32) {
            float e = __expf(sc[j] - m);
            sc[j] = e;
            ssum += e;
        }
        #pragma unroll
        for (int o = 16; o; o >>= 1) ssum += __shfl_xor_sync(0xffffffffu, ssum, o);
        if (lane == 0) sc[258] = 1.f / ssum;
    }
    __syncthreads();
    {   // PV: 4 key-groups x 64 dims
        const int g = tid >> 6, d = tid & 63;
        const int j0 = g * 64, cnt = (g == 3) ? 65 : 64;
        float acc = 0.f;
        for (int jj = 0; jj < cnt; jj++) {
            int j = j0 + jj;
            acc += sc[j] * __half2float(*(const __half*)(VhB + j * KROWB + d * 2));
        }
        red[g * 64 + d] = acc;
    }
    __syncthreads();
    if (tid < 64) {
        float inv = sc[258];
        float r = (red[tid] + red[64 + tid] + red[128 + tid] + red[192 + tid]) * inv;
        g_clspart[ci * CC + h * DH + tid] = r;
    }
    // (no extra sync needed: smem sc/red/qcs not reused below)

    // ===== token-query attention =====
    const int r0 = lane >> 2;
    const int qp = (lane & 3) * 2;
    const __half2 qscale = __float2half2_rn(0.125f);

    #pragma unroll 1
    for (int mt = wid; mt < 16; mt += 8) {
        const __half* p0 = qkvh + (size_t)(mt * 16 + r0) * C3 + h * DH;
        const __half* p1 = p0 + 8 * C3;

        float acc[34][4];
        #pragma unroll
        for (int nt = 0; nt < 33; nt++)
            acc[nt][0] = acc[nt][1] = acc[nt][2] = acc[nt][3] = 0.f;
        acc[33][0] = acc[33][1] = acc[33][2] = acc[33][3] = -1e30f;

        // ---- S = Q K^T (tiles 0..32; tile 33 fully masked, never computed) ----
        #pragma unroll
        for (int kt = 0; kt < 4; kt++) {
            uint32_t qh[4];
            {
                __half2 v0 = __hmul2(*(const __half2*)(p0 + kt * 16 + qp),     qscale);
                __half2 v1 = __hmul2(*(const __half2*)(p1 + kt * 16 + qp),     qscale);
                __half2 v2 = __hmul2(*(const __half2*)(p0 + kt * 16 + qp + 8), qscale);
                __half2 v3 = __hmul2(*(const __half2*)(p1 + kt * 16 + qp + 8), qscale);
                qh[0] = *(uint32_t*)&v0; qh[1] = *(uint32_t*)&v1;
                qh[2] = *(uint32_t*)&v2; qh[3] = *(uint32_t*)&v3;
            }
            const uint32_t kaddr4 = KhU
                + ((lane & 7) + ((lane >> 4) & 1) * 8) * KROWB
                + ((lane >> 3) & 1) * 16 + kt * 32;
            #pragma unroll
            for (int p = 0; p < 16; p++) {
                uint32_t b4[4];
                ldsm_x4(b4, kaddr4 + p * 16 * KROWB);
                mma_f16(acc[2 * p],     qh, &b4[0]);
                mma_f16(acc[2 * p + 1], qh, &b4[2]);
            }
            {
                uint32_t b4[4];
                ldsm_x4(b4, kaddr4 + 16 * 16 * KROWB);
                mma_f16(acc[32], qh, &b4[0]);
            }
        }

        if (qp != 0) { acc[32][0] = -1e30f; acc[32][2] = -1e30f; }
        acc[32][1] = -1e30f; acc[32][3] = -1e30f;

        float m0 = -1e30f, m1 = -1e30f;
        #pragma unroll
        for (int nt = 0; nt < 33; nt++) {
            m0 = fmaxf(m0, fmaxf(acc[nt][0], acc[nt][1]));
            m1 = fmaxf(m1, fmaxf(acc[nt][2], acc[nt][3]));
        }
        m0 = fmaxf(m0, __shfl_xor_sync(0xffffffffu, m0, 1));
        m0 = fmaxf(m0, __shfl_xor_sync(0xffffffffu, m0, 2));
        m1 = fmaxf(m1, __shfl_xor_sync(0xffffffffu, m1, 1));
        m1 = fmaxf(m1, __shfl_xor_sync(0xffffffffu, m1, 2));
        float s0 = 0.f, s1 = 0.f;
        #pragma unroll
        for (int nt = 0; nt < 34; nt++) {
            acc[nt][0] = __expf(acc[nt][0] - m0);
            acc[nt][1] = __expf(acc[nt][1] - m0);
            acc[nt][2] = __expf(acc[nt][2] - m1);
            acc[nt][3] = __expf(acc[nt][3] - m1);
            s0 += acc[nt][0] + acc[nt][1];
            s1 += acc[nt][2] + acc[nt][3];
        }
        s0 += __shfl_xor_sync(0xffffffffu, s0, 1);
        s0 += __shfl_xor_sync(0xffffffffu, s0, 2);
        s1 += __shfl_xor_sync(0xffffffffu, s1, 1);
        s1 += __shfl_xor_sync(0xffffffffu, s1, 2);
        const float inv0 = 1.f / s0, inv1 = 1.f / s1;

        // ---- O = P V (paired ldsm_x4.trans) ----
        float o[8][4];
        #pragma unroll
        for (int nt = 0; nt < 8; nt++)
            o[nt][0] = o[nt][1] = o[nt][2] = o[nt][3] = 0.f;

        #pragma unroll
        for (int kt = 0; kt < 17; kt++) {
            uint32_t ah[4];
            ah[0] = pack_h2(acc[2*kt][0] * inv0,   acc[2*kt][1] * inv0);
            ah[1] = pack_h2(acc[2*kt][2] * inv1,   acc[2*kt][3] * inv1);
            ah[2] = pack_h2(acc[2*kt+1][0] * inv0, acc[2*kt+1][1] * inv0);
            ah[3] = pack_h2(acc[2*kt+1][2] * inv1, acc[2*kt+1][3] * inv1);
            const uint32_t vaddr4 = VhU + (kt * 16 + (lane & 15)) * KROWB
                                    + ((lane >> 4) & 1) * 16;
            #pragma unroll
            for (int p = 0; p < 4; p++) {
                uint32_t b4[4];
                ldsm_x4_t(b4, vaddr4 + p * 32);
                mma_f16(o[2 * p],     ah, &b4[0]);
                mma_f16(o[2 * p + 1], ah, &b4[2]);
            }
        }

        const size_t row0 = (size_t)(cs + mt * 16 + r0) * CC + h * DH;
        const size_t row1 = row0 + 8 * CC;
        #pragma unroll
        for (int nt = 0; nt < 8; nt++) {
            *(uint32_t*)(g_att_h + row0 + nt * 8 + qp) = pack_h2(o[nt][0], o[nt][1]);
            *(uint32_t*)(g_att_h + row1 + nt * 8 + qp) = pack_h2(o[nt][2], o[nt][3]);
        }
    }
}

// ---------------- cls reduce ----------------
__global__ __launch_bounds__(256)
void cls_reduce_kernel(const int* __restrict__ offset, float* __restrict__ out_cls)
{
    int gid = blockIdx.x * 256 + threadIdx.x;
    int b = gid >> 9;
    int c = gid & (CC - 1);
    int start = (b == 0) ? 0 : offset[b - 1];
    int end = offset[b];
    int ch0 = start / KK, ch1 = end / KK;
    float s = 0.f;
    for (int ch = ch0; ch < ch1; ch++) s += g_clspart[ch * CC + c];
    out_cls[gid] = s / (float)(ch1 - ch0);
}

// ---------------- launch ----------------
extern "C" void kernel_launch(void* const* d_in, const int* in_sizes, int n_in,
                              void* d_out, int out_size)
{
    const float* feat       = (const float*)d_in[0];
    const float* cls_tokens = (const float*)d_in[1];
    const float* Wqkv       = (const float*)d_in[2];
    const float* bqkv       = (const float*)d_in[3];
    const float* Wproj      = (const float*)d_in[4];
    const float* bproj      = (const float*)d_in[5];
    const int*   order      = (const int*)d_in[6];
    const int*   offset     = (const int*)d_in[8];

    float* out_feat = (float*)d_out;
    float* out_cls  = out_feat + (size_t)NPTS * CC;

    void *qkvp = nullptr;
    void *ah = nullptr, *ath = nullptr;
    void *wq = nullptr, *wp = nullptr;
    cudaGetSymbolAddress(&qkvp, g_qkv_h);
    cudaGetSymbolAddress(&ah, g_Ah);
    cudaGetSymbolAddress(&ath, g_att_h);
    cudaGetSymbolAddress(&wq, g_WqkvT);
    cudaGetSymbolAddress(&wp, g_WprojT);

    cudaFuncSetAttribute(attn_mma_kernel, cudaFuncAttributeMaxDynamicSharedMemorySize,
                         ATT_SMEM);
    cudaFuncSetAttribute(gemm_async_kernel<false, true>,
                         cudaFuncAttributeMaxDynamicSharedMemorySize, GSMEM);
    cudaFuncSetAttribute(gemm_async_kernel<true, false>,
                         cudaFuncAttributeMaxDynamicSharedMemorySize, GSMEM);

    // 0. weight transpose (fp16), feat gather (fp16)
    conv_wt_kernel<<<dim3(C3 / 32, CC / 32), 256>>>(Wqkv, (__half*)wq, CC, C3);
    conv_wt_kernel<<<dim3(CC / 32, CC / 32), 256>>>(Wproj, (__half*)wp, CC, CC);
    conv_feat_kernel<<<(NPTS * (CC / 4)) / 256, 256>>>(feat, order);
    // 1. cls token qkv
    cls_qkv_kernel<<<C3 / 32, 256>>>(cls_tokens, Wqkv, bqkv);
    // 2. qkv GEMM -> fp16 output
    gemm_async_kernel<false, true><<<dim3(C3 / 128, NPTS / 128), 256, GSMEM>>>(
        (const __half*)ah, (const __half*)wq, bqkv, qkvp, order, C3);
    // 3. attention (token queries + fused cls query)
    attn_mma_kernel<<<dim3(NCH, HH), 256, ATT_SMEM>>>(offset);
    // 4. proj GEMM with scatter -> fp32 output
    gemm_async_kernel<true, false><<<dim3(CC / 128, NPTS / 128), 256, GSMEM>>>(
        (const __half*)ath, (const __half*)wp, bproj, (void*)out_feat, order, CC);
    // 5. cls reduction
    cls_reduce_kernel<<<(BB * CC) / 256, 256>>>(offset, out_cls);
}

// round 13
// speedup vs baseline: 1.9092x; 1.0006x over previous
#include <cuda_runtime.h>
#include <cuda_fp16.h>
#include <cstdint>
#include <cstddef>

#define NPTS 65536
#define BB 4
#define CC 512
#define C3 1536
#define KK 256
#define HH 8
#define DH 64
#define NCH 256   // NPTS/KK

// ---------------- scratch (static device globals; no allocation) ----------------
__device__ __half g_qkv_h[(size_t)NPTS * C3]; // gathered qkv, serialized order (fp16)
__device__ float g_clsqkv[BB * C3];            // cls token qkv (fp32)
__device__ float g_clspart[NCH * CC];          // per-chunk cls attention row
__device__ __half g_Ah[(size_t)NPTS * CC];     // gathered feat (fp16)
__device__ __half g_att_h[(size_t)NPTS * CC];  // attention out (fp16, serialized)
__device__ __half g_WqkvT[(size_t)C3 * CC];    // W^T fp16
__device__ __half g_WprojT[(size_t)CC * CC];

// =============== helpers ===============
__device__ __forceinline__ uint32_t smem_u32(const void* p) {
    uint32_t a;
    asm("{ .reg .u64 t; cvta.to.shared.u64 t, %1; cvt.u32.u64 %0, t; }" : "=r"(a) : "l"(p));
    return a;
}
__device__ __forceinline__ void ldsm_x4(uint32_t* r, uint32_t addr) {
    asm volatile("ldmatrix.sync.aligned.m8n8.x4.shared.b16 {%0,%1,%2,%3}, [%4];"
                 : "=r"(r[0]), "=r"(r[1]), "=r"(r[2]), "=r"(r[3]) : "r"(addr));
}
__device__ __forceinline__ void ldsm_x4_t(uint32_t* r, uint32_t addr) {
    asm volatile("ldmatrix.sync.aligned.m8n8.x4.trans.shared.b16 {%0,%1,%2,%3}, [%4];"
                 : "=r"(r[0]), "=r"(r[1]), "=r"(r[2]), "=r"(r[3]) : "r"(addr));
}
__device__ __forceinline__ void mma_f16(float* c, const uint32_t* a, const uint32_t* b) {
    asm volatile(
        "mma.sync.aligned.m16n8k16.row.col.f32.f16.f16.f32 "
        "{%0,%1,%2,%3}, {%4,%5,%6,%7}, {%8,%9}, {%0,%1,%2,%3};"
        : "+f"(c[0]), "+f"(c[1]), "+f"(c[2]), "+f"(c[3])
        : "r"(a[0]), "r"(a[1]), "r"(a[2]), "r"(a[3]), "r"(b[0]), "r"(b[1]));
}
__device__ __forceinline__ uint32_t pack_h2(float x, float y) {
    __half2 hh = __floats2half2_rn(x, y);
    return *reinterpret_cast<uint32_t*>(&hh);
}
__device__ __forceinline__ void cp_async16(uint32_t dst, const void* src) {
    asm volatile("cp.async.cg.shared.global [%0], [%1], 16;" :: "r"(dst), "l"(src) : "memory");
}
#define CP_COMMIT() asm volatile("cp.async.commit_group;" ::: "memory")
#define CP_WAIT1()  asm volatile("cp.async.wait_group 1;" ::: "memory")

// ---------------- W transpose to fp16 ----------------
__global__ __launch_bounds__(256)
void conv_wt_kernel(const float* __restrict__ W, __half* __restrict__ T, int K, int N)
{
    __shared__ float t[32][33];
    int n0 = blockIdx.x * 32, k0 = blockIdx.y * 32;
    int tx = threadIdx.x & 31, ty = threadIdx.x >> 5;
    #pragma unroll
    for (int j = 0; j < 32; j += 8)
        t[ty + j][tx] = W[(size_t)(k0 + ty + j) * N + n0 + tx];
    __syncthreads();
    #pragma unroll
    for (int j = 0; j < 32; j += 8) {
        int n = n0 + ty + j, k = k0 + tx;
        T[(size_t)n * K + k] = __float2half_rn(t[tx][ty + j]);
    }
}

// ---------------- feat gather -> fp16 ----------------
__global__ __launch_bounds__(256)
void conv_feat_kernel(const float* __restrict__ feat, const int* __restrict__ order)
{
    size_t idx = (size_t)blockIdx.x * 256 + threadIdx.x;
    int m = (int)(idx >> 7);
    int u = (int)(idx & 127);
    const float4 v = *(const float4*)(feat + (size_t)order[m] * CC + u * 4);
    *(uint2*)(g_Ah + (size_t)m * CC + u * 4) =
        make_uint2(pack_h2(v.x, v.y), pack_h2(v.z, v.w));
}

// ---- cp.async GEMM: 128x128 tile, Kc=64, 3 stages, single fp16, 2 CTAs/SM ----
#define QROWB  144
#define QTILE  (128 * QROWB)       // 18432
#define QSTAGE (2 * QTILE)         // 36864 (A | B)
#define SMHDR  1024
#define GSMEM  (SMHDR + 3 * QSTAGE)   // 111616

template<bool SCATTER, bool OUTHALF>
__global__ __launch_bounds__(256, 2)
void gemm_async_kernel(const __half* __restrict__ Ah, const __half* __restrict__ Bh,
                       const float* __restrict__ bias, void* __restrict__ Cv,
                       const int* __restrict__ order, int Ntot)
{
    extern __shared__ char sm[];
    const uint32_t sb = smem_u32(sm);
    const int tid = threadIdx.x, wid = tid >> 5, lane = tid & 31;
    const int n0 = blockIdx.x * 128, m0 = blockIdx.y * 128;
    float* bias_s = (float*)sm;
    int*   rowidx = (int*)(sm + 512);

    auto issue_stage = [&](int c, int stage) {
        const size_t kb = (size_t)c * 128;
        const uint32_t dbase = sb + SMHDR + stage * QSTAGE;
        #pragma unroll
        for (int i = 0; i < 8; i++) {
            const int g = tid + i * 256;
            const int tile = g >> 10;
            const int u = g & 1023;
            const int row = u >> 3, col8 = u & 7;
            const char* src = (const char*)(tile ? Bh + (size_t)(n0 + row) * CC
                                                 : Ah + (size_t)(m0 + row) * CC) + kb;
            cp_async16(dbase + tile * QTILE + row * QROWB + col8 * 16, src + col8 * 16);
        }
    };

    issue_stage(0, 0); CP_COMMIT();
    issue_stage(1, 1); CP_COMMIT();

    if (tid < 128) {
        bias_s[tid] = bias[n0 + tid];
        if (SCATTER) rowidx[tid] = order[m0 + tid];
    }
    __syncthreads();

    const int wm = (wid & 1) * 64;
    const int wn = (wid >> 1) * 32;

    float acc[4][4][4];
    #pragma unroll
    for (int nt = 0; nt < 4; nt++) {
        float b0 = bias_s[wn + nt * 8 + 2 * (lane & 3)];
        float b1 = bias_s[wn + nt * 8 + 2 * (lane & 3) + 1];
        #pragma unroll
        for (int mt = 0; mt < 4; mt++) {
            acc[mt][nt][0] = b0; acc[mt][nt][1] = b1;
            acc[mt][nt][2] = b0; acc[mt][nt][3] = b1;
        }
    }

    const uint32_t a_lm  = sb + SMHDR + (wm + (lane & 15)) * QROWB + ((lane >> 4) & 1) * 16;
    const uint32_t b_lm4 = sb + SMHDR + QTILE
                           + (wn + (lane & 7) + ((lane >> 4) & 1) * 8) * QROWB
                           + ((lane >> 3) & 1) * 16;

    const int NC = CC / 64;   // 8
    #pragma unroll 1
    for (int c = 0; c < NC; c++) {
        CP_WAIT1();
        __syncthreads();
        if (c + 2 < NC) issue_stage(c + 2, (c + 2) % 3);
        CP_COMMIT();

        const uint32_t abase = a_lm  + (c % 3) * QSTAGE;
        const uint32_t bbase = b_lm4 + (c % 3) * QSTAGE;
        #pragma unroll
        for (int ks = 0; ks < 4; ks++) {
            const int ko = ks * 32;
            uint32_t ah[4][4], bh[2][4];
            #pragma unroll
            for (int mt = 0; mt < 4; mt++)
                ldsm_x4(ah[mt], abase + mt * 16 * QROWB + ko);
            #pragma unroll
            for (int p = 0; p < 2; p++)
                ldsm_x4(bh[p], bbase + p * 16 * QROWB + ko);
            #pragma unroll
            for (int mt = 0; mt < 4; mt++)
                #pragma unroll
                for (int nt = 0; nt < 4; nt++)
                    mma_f16(acc[mt][nt], ah[mt], &bh[nt >> 1][(nt & 1) * 2]);
        }
    }

    #pragma unroll
    for (int mt = 0; mt < 4; mt++) {
        int lrow = wm + mt * 16 + (lane >> 2);
        int d0 = SCATTER ? rowidx[lrow]     : (m0 + lrow);
        int d1 = SCATTER ? rowidx[lrow + 8] : (m0 + lrow + 8);
        #pragma unroll
        for (int nt = 0; nt < 4; nt++) {
            int col = n0 + wn + nt * 8 + 2 * (lane & 3);
            if (OUTHALF) {
                __half* C = (__half*)Cv;
                *(uint32_t*)(C + (size_t)d0 * Ntot + col) =
                    pack_h2(acc[mt][nt][0], acc[mt][nt][1]);
                *(uint32_t*)(C + (size_t)d1 * Ntot + col) =
                    pack_h2(acc[mt][nt][2], acc[mt][nt][3]);
            } else {
                float* C = (float*)Cv;
                *(float2*)(C + (size_t)d0 * Ntot + col) =
                    make_float2(acc[mt][nt][0], acc[mt][nt][1]);
                *(float2*)(C + (size_t)d1 * Ntot + col) =
                    make_float2(acc[mt][nt][2], acc[mt][nt][3]);
            }
        }
    }
}

// ---------------- cls qkv: parallel k-split, grid 48 ----------------
__global__ __launch_bounds__(256)
void cls_qkv_kernel(const float* __restrict__ cls_tokens,
                    const float* __restrict__ Wqkv,
                    const float* __restrict__ bqkv)
{
    __shared__ float ct[BB * CC];
    __shared__ float red[8][BB][32];
    const int tid = threadIdx.x, lane = tid & 31, seg = tid >> 5;
    for (int i = tid; i < BB * CC; i += 256) ct[i] = cls_tokens[i];
    __syncthreads();
    const int n = blockIdx.x * 32 + lane;
    float acc[BB] = {0.f, 0.f, 0.f, 0.f};
    for (int k = seg * 64; k < seg * 64 + 64; k++) {
        float w = Wqkv[(size_t)k * C3 + n];
        #pragma unroll
        for (int b = 0; b < BB; b++) acc[b] += ct[b * CC + k] * w;
    }
    #pragma unroll
    for (int b = 0; b < BB; b++) red[seg][b][lane] = acc[b];
    __syncthreads();
    if (seg < BB) {
        float s = bqkv[n];
        #pragma unroll
        for (int j = 0; j < 8; j++) s += red[j][seg][lane];
        g_clsqkv[seg * C3 + n] = s;
    }
}

// ---------------- tensor-core attention + fused cls-query attention ----------------
#define NP 272
#define KROWB 144
#define SM_KV   (2 * NP * KROWB)          // 78336
#define SM_QCS  SM_KV                      // 64 floats (cls query, scaled)
#define SM_SC   (SM_QCS + 256)             // 260 floats (cls scores / probs + inv)
#define SM_RED  (SM_SC + 1040)             // 256 floats (PV partials)
#define SM_QST  (SM_RED + 1024)            // 8 warps x 16 rows x 144B Q staging
#define ATT_SMEM (SM_QST + 8 * 16 * KROWB) // 99088

__global__ __launch_bounds__(256)
void attn_mma_kernel(const int* __restrict__ offset)
{
    extern __shared__ char sm[];
    char* KhB = sm;
    char* VhB = sm + NP * KROWB;
    float* qcs = (float*)(sm + SM_QCS);
    float* sc  = (float*)(sm + SM_SC);
    float* red = (float*)(sm + SM_RED);
    const uint32_t sb = smem_u32(sm);
    const uint32_t KhU = sb;
    const uint32_t VhU = sb + NP * KROWB;

    const int ci = blockIdx.x, h = blockIdx.y, tid = threadIdx.x;
    const int wid = tid >> 5, lane = tid & 31;
    const int cs = ci * KK;
    int b = 0;
    #pragma unroll
    for (int j = 0; j < BB; j++) b += (offset[j] <= cs) ? 1 : 0;
    const __half* qkvh   = g_qkv_h + (size_t)cs * C3;
    const float*  clsrow = g_clsqkv + b * C3;
    const int koff = CC + h * DH, voff = 2 * CC + h * DH;

    // load K,V rows -> smem fp16 (pure 16B copies; cls row converted)
    for (int idx = tid; idx < 2 * NP * 8; idx += 256) {
        int kv = idx >= NP * 8;
        int i  = kv ? idx - NP * 8 : idx;
        int t = i >> 3, u = i & 7;
        int off = kv ? voff : koff;
        uint4 val = make_uint4(0u, 0u, 0u, 0u);
        if (t == 0) {
            const float* src = clsrow + off + u * 8;
            val.x = pack_h2(src[0], src[1]);
            val.y = pack_h2(src[2], src[3]);
            val.z = pack_h2(src[4], src[5]);
            val.w = pack_h2(src[6], src[7]);
        } else if (t <= KK) {
            val = *(const uint4*)(qkvh + (size_t)(t - 1) * C3 + off + u * 8);
        }
        *(uint4*)((kv ? VhB : KhB) + t * KROWB + u * 16) = val;
    }
    if (tid < 64) qcs[tid] = clsrow[h * DH + tid] * 0.125f;
    __syncthreads();

    // ===== fused cls-query attention (uses smem K/V) =====
    for (int j = tid; j < 257; j += 256) {
        float s = 0.f;
        #pragma unroll
        for (int u = 0; u < 8; u++) {
            uint4 k4 = *(const uint4*)(KhB + j * KROWB + u * 16);
            const __half2* h2 = (const __half2*)&k4;
            #pragma unroll
            for (int e = 0; e < 4; e++) {
                float2 kf = __half22float2(h2[e]);
                s += qcs[u * 8 + e * 2] * kf.x + qcs[u * 8 + e * 2 + 1] * kf.y;
            }
        }
        sc[j] = s;
    }
    __syncthreads();
    if (wid == 0) {
        float m = -1e30f;
        for (int j = lane; j < 257; j += 32) m = fmaxf(m, sc[j]);
        #pragma unroll
        for (int o = 16; o; o >>= 1) m = fmaxf(m, __shfl_xor_sync(0xffffffffu, m, o));
        float ssum = 0.f;
        for (int j = lane; j < 257; j += 32) {
            float e = __expf(sc[j] - m);
            sc[j] = e;
            ssum += e;
        }
        #pragma unroll
        for (int o = 16; o; o >>= 1) ssum += __shfl_xor_sync(0xffffffffu, ssum, o);
        if (lane == 0) sc[258] = 1.f / ssum;
    }
    __syncthreads();
    {   // PV: 4 key-groups x 64 dims
        const int g = tid >> 6, d = tid & 63;
        const int j0 = g * 64, cnt = (g == 3) ? 65 : 64;
        float acc = 0.f;
        for (int jj = 0; jj < cnt; jj++) {
            int j = j0 + jj;
            acc += sc[j] * __half2float(*(const __half*)(VhB + j * KROWB + d * 2));
        }
        red[g * 64 + d] = acc;
    }
    __syncthreads();
    if (tid < 64) {
        float inv = sc[258];
        float r = (red[tid] + red[64 + tid] + red[128 + tid] + red[192 + tid]) * inv;
        g_clspart[ci * CC + h * DH + tid] = r;
    }

    // ===== token-query attention =====
    const int r0 = lane >> 2;
    const int qp = (lane & 3) * 2;
    char* qstB = sm + SM_QST + wid * (16 * KROWB);
    const uint32_t qstU = sb + SM_QST + wid * (16 * KROWB);
    const uint32_t q_lm = qstU + (lane & 15) * KROWB + ((lane >> 4) & 1) * 16;

    #pragma unroll 1
    for (int mt = wid; mt < 16; mt += 8) {
        // stage this warp's Q tile (16 rows x 64 fp16) into smem, unscaled
        const __half* qbase = qkvh + (size_t)(mt * 16) * C3 + h * DH;
        __syncwarp();
        #pragma unroll
        for (int u = 0; u < 4; u++) {
            int g = lane + u * 32;            // 0..127
            int row = g >> 3, c8 = g & 7;
            *(uint4*)(qstB + row * KROWB + c8 * 16) =
                *(const uint4*)(qbase + (size_t)row * C3 + c8 * 8);
        }
        __syncwarp();

        float acc[34][4];
        #pragma unroll
        for (int nt = 0; nt < 33; nt++)
            acc[nt][0] = acc[nt][1] = acc[nt][2] = acc[nt][3] = 0.f;

        // ---- S = Q K^T (unscaled; tiles 0..32) ----
        #pragma unroll
        for (int kt = 0; kt < 4; kt++) {
            uint32_t qh[4];
            ldsm_x4(qh, q_lm + kt * 32);
            const uint32_t kaddr4 = KhU
                + ((lane & 7) + ((lane >> 4) & 1) * 8) * KROWB
                + ((lane >> 3) & 1) * 16 + kt * 32;
            #pragma unroll
            for (int p = 0; p < 16; p++) {
                uint32_t b4[4];
                ldsm_x4(b4, kaddr4 + p * 16 * KROWB);
                mma_f16(acc[2 * p],     qh, &b4[0]);
                mma_f16(acc[2 * p + 1], qh, &b4[2]);
            }
            {
                uint32_t b4[4];
                ldsm_x4(b4, kaddr4 + 16 * 16 * KROWB);
                mma_f16(acc[32], qh, &b4[0]);
            }
        }

        if (qp != 0) { acc[32][0] = -1e30f; acc[32][2] = -1e30f; }
        acc[32][1] = -1e30f; acc[32][3] = -1e30f;

        // ---- softmax (scale 0.125 folded into exp; P left unnormalized) ----
        float m0 = -1e30f, m1 = -1e30f;
        #pragma unroll
        for (int nt = 0; nt < 33; nt++) {
            m0 = fmaxf(m0, fmaxf(acc[nt][0], acc[nt][1]));
            m1 = fmaxf(m1, fmaxf(acc[nt][2], acc[nt][3]));
        }
        m0 = fmaxf(m0, __shfl_xor_sync(0xffffffffu, m0, 1));
        m0 = fmaxf(m0, __shfl_xor_sync(0xffffffffu, m0, 2));
        m1 = fmaxf(m1, __shfl_xor_sync(0xffffffffu, m1, 1));
        m1 = fmaxf(m1, __shfl_xor_sync(0xffffffffu, m1, 2));
        const float mm0 = m0 * 0.125f, mm1 = m1 * 0.125f;
        float s0 = 0.f, s1 = 0.f;
        #pragma unroll
        for (int nt = 0; nt < 33; nt++) {
            acc[nt][0] = __expf(fmaf(acc[nt][0], 0.125f, -mm0));
            acc[nt][1] = __expf(fmaf(acc[nt][1], 0.125f, -mm0));
            acc[nt][2] = __expf(fmaf(acc[nt][2], 0.125f, -mm1));
            acc[nt][3] = __expf(fmaf(acc[nt][3], 0.125f, -mm1));
            s0 += acc[nt][0] + acc[nt][1];
            s1 += acc[nt][2] + acc[nt][3];
        }
        acc[33][0] = acc[33][1] = acc[33][2] = acc[33][3] = 0.f;
        s0 += __shfl_xor_sync(0xffffffffu, s0, 1);
        s0 += __shfl_xor_sync(0xffffffffu, s0, 2);
        s1 += __shfl_xor_sync(0xffffffffu, s1, 1);
        s1 += __shfl_xor_sync(0xffffffffu, s1, 2);
        const float inv0 = 1.f / s0, inv1 = 1.f / s1;

        // ---- O = P V (P unnormalized; normalize at store) ----
        float o[8][4];
        #pragma unroll
        for (int nt = 0; nt < 8; nt++)
            o[nt][0] = o[nt][1] = o[nt][2] = o[nt][3] = 0.f;

        #pragma unroll
        for (int kt = 0; kt < 17; kt++) {
            uint32_t ah[4];
            ah[0] = pack_h2(acc[2*kt][0],   acc[2*kt][1]);
            ah[1] = pack_h2(acc[2*kt][2],   acc[2*kt][3]);
            ah[2] = pack_h2(acc[2*kt+1][0], acc[2*kt+1][1]);
            ah[3] = pack_h2(acc[2*kt+1][2], acc[2*kt+1][3]);
            const uint32_t vaddr4 = VhU + (kt * 16 + (lane & 15)) * KROWB
                                    + ((lane >> 4) & 1) * 16;
            #pragma unroll
            for (int p = 0; p < 4; p++) {
                uint32_t b4[4];
                ldsm_x4_t(b4, vaddr4 + p * 32);
                mma_f16(o[2 * p],     ah, &b4[0]);
                mma_f16(o[2 * p + 1], ah, &b4[2]);
            }
        }

        const size_t row0 = (size_t)(cs + mt * 16 + r0) * CC + h * DH;
        const size_t row1 = row0 + 8 * CC;
        #pragma unroll
        for (int nt = 0; nt < 8; nt++) {
            *(uint32_t*)(g_att_h + row0 + nt * 8 + qp) =
                pack_h2(o[nt][0] * inv0, o[nt][1] * inv0);
            *(uint32_t*)(g_att_h + row1 + nt * 8 + qp) =
                pack_h2(o[nt][2] * inv1, o[nt][3] * inv1);
        }
    }
}

// ---------------- cls reduce ----------------
__global__ __launch_bounds__(256)
void cls_reduce_kernel(const int* __restrict__ offset, float* __restrict__ out_cls)
{
    int gid = blockIdx.x * 256 + threadIdx.x;
    int b = gid >> 9;
    int c = gid & (CC - 1);
    int start = (b == 0) ? 0 : offset[b - 1];
    int end = offset[b];
    int ch0 = start / KK, ch1 = end / KK;
    float s = 0.f;
    for (int ch = ch0; ch < ch1; ch++) s += g_clspart[ch * CC + c];
    out_cls[gid] = s / (float)(ch1 - ch0);
}

// ---------------- launch ----------------
extern "C" void kernel_launch(void* const* d_in, const int* in_sizes, int n_in,
                              void* d_out, int out_size)
{
    const float* feat       = (const float*)d_in[0];
    const float* cls_tokens = (const float*)d_in[1];
    const float* Wqkv       = (const float*)d_in[2];
    const float* bqkv       = (const float*)d_in[3];
    const float* Wproj      = (const float*)d_in[4];
    const float* bproj      = (const float*)d_in[5];
    const int*   order      = (const int*)d_in[6];
    const int*   offset     = (const int*)d_in[8];

    float* out_feat = (float*)d_out;
    float* out_cls  = out_feat + (size_t)NPTS * CC;

    void *qkvp = nullptr;
    void *ah = nullptr, *ath = nullptr;
    void *wq = nullptr, *wp = nullptr;
    cudaGetSymbolAddress(&qkvp, g_qkv_h);
    cudaGetSymbolAddress(&ah, g_Ah);
    cudaGetSymbolAddress(&ath, g_att_h);
    cudaGetSymbolAddress(&wq, g_WqkvT);
    cudaGetSymbolAddress(&wp, g_WprojT);

    cudaFuncSetAttribute(attn_mma_kernel, cudaFuncAttributeMaxDynamicSharedMemorySize,
                         ATT_SMEM);
    cudaFuncSetAttribute(gemm_async_kernel<false, true>,
                         cudaFuncAttributeMaxDynamicSharedMemorySize, GSMEM);
    cudaFuncSetAttribute(gemm_async_kernel<true, false>,
                         cudaFuncAttributeMaxDynamicSharedMemorySize, GSMEM);

    // 0. weight transpose (fp16), feat gather (fp16)
    conv_wt_kernel<<<dim3(C3 / 32, CC / 32), 256>>>(Wqkv, (__half*)wq, CC, C3);
    conv_wt_kernel<<<dim3(CC / 32, CC / 32), 256>>>(Wproj, (__half*)wp, CC, CC);
    conv_feat_kernel<<<(NPTS * (CC / 4)) / 256, 256>>>(feat, order);
    // 1. cls token qkv
    cls_qkv_kernel<<<C3 / 32, 256>>>(cls_tokens, Wqkv, bqkv);
    // 2. qkv GEMM -> fp16 output
    gemm_async_kernel<false, true><<<dim3(C3 / 128, NPTS / 128), 256, GSMEM>>>(
        (const __half*)ah, (const __half*)wq, bqkv, qkvp, order, C3);
    // 3. attention (token queries + fused cls query)
    attn_mma_kernel<<<dim3(NCH, HH), 256, ATT_SMEM>>>(offset);
    // 4. proj GEMM with scatter -> fp32 output
    gemm_async_kernel<true, false><<<dim3(CC / 128, NPTS / 128), 256, GSMEM>>>(
        (const __half*)ath, (const __half*)wp, bproj, (void*)out_feat, order, CC);
    // 5. cls reduction
    cls_reduce_kernel<<<(BB * CC) / 256, 256>>>(offset, out_cls);
}

// round 14
// speedup vs baseline: 2.1840x; 1.1439x over previous
#include <cuda_runtime.h>
#include <cuda_fp16.h>
#include <cstdint>
#include <cstddef>

#define NPTS 65536
#define BB 4
#define CC 512
#define C3 1536
#define KK 256
#define HH 8
#define DH 64
#define NCH 256   // NPTS/KK

// ---------------- scratch (static device globals; no allocation) ----------------
__device__ __half g_qkv_h[(size_t)NPTS * C3]; // gathered qkv, serialized order (fp16)
__device__ float g_clsqkv[BB * C3];            // cls token qkv (fp32)
__device__ float g_clspart[NCH * CC];          // per-chunk cls attention row
__device__ __half g_Ah[(size_t)NPTS * CC];     // gathered feat (fp16)
__device__ __half g_att_h[(size_t)NPTS * CC];  // attention out (fp16, serialized)
__device__ __half g_WqkvT[(size_t)C3 * CC];    // W^T fp16
__device__ __half g_WprojT[(size_t)CC * CC];

// =============== helpers ===============
__device__ __forceinline__ uint32_t smem_u32(const void* p) {
    uint32_t a;
    asm("{ .reg .u64 t; cvta.to.shared.u64 t, %1; cvt.u32.u64 %0, t; }" : "=r"(a) : "l"(p));
    return a;
}
__device__ __forceinline__ void ldsm_x4(uint32_t* r, uint32_t addr) {
    asm volatile("ldmatrix.sync.aligned.m8n8.x4.shared.b16 {%0,%1,%2,%3}, [%4];"
                 : "=r"(r[0]), "=r"(r[1]), "=r"(r[2]), "=r"(r[3]) : "r"(addr));
}
__device__ __forceinline__ void ldsm_x4_t(uint32_t* r, uint32_t addr) {
    asm volatile("ldmatrix.sync.aligned.m8n8.x4.trans.shared.b16 {%0,%1,%2,%3}, [%4];"
                 : "=r"(r[0]), "=r"(r[1]), "=r"(r[2]), "=r"(r[3]) : "r"(addr));
}
__device__ __forceinline__ void mma_f16(float* c, const uint32_t* a, const uint32_t* b) {
    asm volatile(
        "mma.sync.aligned.m16n8k16.row.col.f32.f16.f16.f32 "
        "{%0,%1,%2,%3}, {%4,%5,%6,%7}, {%8,%9}, {%0,%1,%2,%3};"
        : "+f"(c[0]), "+f"(c[1]), "+f"(c[2]), "+f"(c[3])
        : "r"(a[0]), "r"(a[1]), "r"(a[2]), "r"(a[3]), "r"(b[0]), "r"(b[1]));
}
__device__ __forceinline__ uint32_t pack_h2(float x, float y) {
    __half2 hh = __floats2half2_rn(x, y);
    return *reinterpret_cast<uint32_t*>(&hh);
}
__device__ __forceinline__ void cp_async16(uint32_t dst, const void* src) {
    asm volatile("cp.async.cg.shared.global [%0], [%1], 16;" :: "r"(dst), "l"(src) : "memory");
}
#define CP_COMMIT() asm volatile("cp.async.commit_group;" ::: "memory")
#define CP_WAIT1()  asm volatile("cp.async.wait_group 1;" ::: "memory")

// ---------------- W transpose to fp16 ----------------
__global__ __launch_bounds__(256)
void conv_wt_kernel(const float* __restrict__ W, __half* __restrict__ T, int K, int N)
{
    __shared__ float t[32][33];
    int n0 = blockIdx.x * 32, k0 = blockIdx.y * 32;
    int tx = threadIdx.x & 31, ty = threadIdx.x >> 5;
    #pragma unroll
    for (int j = 0; j < 32; j += 8)
        t[ty + j][tx] = W[(size_t)(k0 + ty + j) * N + n0 + tx];
    __syncthreads();
    #pragma unroll
    for (int j = 0; j < 32; j += 8) {
        int n = n0 + ty + j, k = k0 + tx;
        T[(size_t)n * K + k] = __float2half_rn(t[tx][ty + j]);
    }
}

// ---------------- feat gather -> fp16 ----------------
__global__ __launch_bounds__(256)
void conv_feat_kernel(const float* __restrict__ feat, const int* __restrict__ order)
{
    size_t idx = (size_t)blockIdx.x * 256 + threadIdx.x;
    int m = (int)(idx >> 7);
    int u = (int)(idx & 127);
    const float4 v = *(const float4*)(feat + (size_t)order[m] * CC + u * 4);
    *(uint2*)(g_Ah + (size_t)m * CC + u * 4) =
        make_uint2(pack_h2(v.x, v.y), pack_h2(v.z, v.w));
}

// ---- cp.async GEMM: 128x128 tile, Kc=64, 3 stages, single fp16, 2 CTAs/SM ----
#define QROWB  144
#define QTILE  (128 * QROWB)       // 18432
#define QSTAGE (2 * QTILE)         // 36864 (A | B)
#define SMHDR  1024
#define GSMEM  (SMHDR + 3 * QSTAGE)   // 111616

template<bool SCATTER, bool OUTHALF>
__global__ __launch_bounds__(256, 2)
void gemm_async_kernel(const __half* __restrict__ Ah, const __half* __restrict__ Bh,
                       const float* __restrict__ bias, void* __restrict__ Cv,
                       const int* __restrict__ order, int Ntot)
{
    extern __shared__ char sm[];
    const uint32_t sb = smem_u32(sm);
    const int tid = threadIdx.x, wid = tid >> 5, lane = tid & 31;
    const int n0 = blockIdx.x * 128, m0 = blockIdx.y * 128;
    float* bias_s = (float*)sm;
    int*   rowidx = (int*)(sm + 512);

    auto issue_stage = [&](int c, int stage) {
        const size_t kb = (size_t)c * 128;
        const uint32_t dbase = sb + SMHDR + stage * QSTAGE;
        #pragma unroll
        for (int i = 0; i < 8; i++) {
            const int g = tid + i * 256;
            const int tile = g >> 10;
            const int u = g & 1023;
            const int row = u >> 3, col8 = u & 7;
            const char* src = (const char*)(tile ? Bh + (size_t)(n0 + row) * CC
                                                 : Ah + (size_t)(m0 + row) * CC) + kb;
            cp_async16(dbase + tile * QTILE + row * QROWB + col8 * 16, src + col8 * 16);
        }
    };

    issue_stage(0, 0); CP_COMMIT();
    issue_stage(1, 1); CP_COMMIT();

    if (tid < 128) {
        bias_s[tid] = bias[n0 + tid];
        if (SCATTER) rowidx[tid] = order[m0 + tid];
    }
    __syncthreads();

    const int wm = (wid & 1) * 64;
    const int wn = (wid >> 1) * 32;

    float acc[4][4][4];
    #pragma unroll
    for (int nt = 0; nt < 4; nt++) {
        float b0 = bias_s[wn + nt * 8 + 2 * (lane & 3)];
        float b1 = bias_s[wn + nt * 8 + 2 * (lane & 3) + 1];
        #pragma unroll
        for (int mt = 0; mt < 4; mt++) {
            acc[mt][nt][0] = b0; acc[mt][nt][1] = b1;
            acc[mt][nt][2] = b0; acc[mt][nt][3] = b1;
        }
    }

    const uint32_t a_lm  = sb + SMHDR + (wm + (lane & 15)) * QROWB + ((lane >> 4) & 1) * 16;
    const uint32_t b_lm4 = sb + SMHDR + QTILE
                           + (wn + (lane & 7) + ((lane >> 4) & 1) * 8) * QROWB
                           + ((lane >> 3) & 1) * 16;

    const int NC = CC / 64;   // 8
    #pragma unroll 1
    for (int c = 0; c < NC; c++) {
        CP_WAIT1();
        __syncthreads();
        if (c + 2 < NC) issue_stage(c + 2, (c + 2) % 3);
        CP_COMMIT();

        const uint32_t abase = a_lm  + (c % 3) * QSTAGE;
        const uint32_t bbase = b_lm4 + (c % 3) * QSTAGE;
        #pragma unroll
        for (int ks = 0; ks < 4; ks++) {
            const int ko = ks * 32;
            uint32_t ah[4][4], bh[2][4];
            #pragma unroll
            for (int mt = 0; mt < 4; mt++)
                ldsm_x4(ah[mt], abase + mt * 16 * QROWB + ko);
            #pragma unroll
            for (int p = 0; p < 2; p++)
                ldsm_x4(bh[p], bbase + p * 16 * QROWB + ko);
            #pragma unroll
            for (int mt = 0; mt < 4; mt++)
                #pragma unroll
                for (int nt = 0; nt < 4; nt++)
                    mma_f16(acc[mt][nt], ah[mt], &bh[nt >> 1][(nt & 1) * 2]);
        }
    }

    #pragma unroll
    for (int mt = 0; mt < 4; mt++) {
        int lrow = wm + mt * 16 + (lane >> 2);
        int d0 = SCATTER ? rowidx[lrow]     : (m0 + lrow);
        int d1 = SCATTER ? rowidx[lrow + 8] : (m0 + lrow + 8);
        #pragma unroll
        for (int nt = 0; nt < 4; nt++) {
            int col = n0 + wn + nt * 8 + 2 * (lane & 3);
            if (OUTHALF) {
                __half* C = (__half*)Cv;
                *(uint32_t*)(C + (size_t)d0 * Ntot + col) =
                    pack_h2(acc[mt][nt][0], acc[mt][nt][1]);
                *(uint32_t*)(C + (size_t)d1 * Ntot + col) =
                    pack_h2(acc[mt][nt][2], acc[mt][nt][3]);
            } else {
                float* C = (float*)Cv;
                *(float2*)(C + (size_t)d0 * Ntot + col) =
                    make_float2(acc[mt][nt][0], acc[mt][nt][1]);
                *(float2*)(C + (size_t)d1 * Ntot + col) =
                    make_float2(acc[mt][nt][2], acc[mt][nt][3]);
            }
        }
    }
}

// ---------------- cls qkv: parallel k-split, grid 48 ----------------
__global__ __launch_bounds__(256)
void cls_qkv_kernel(const float* __restrict__ cls_tokens,
                    const float* __restrict__ Wqkv,
                    const float* __restrict__ bqkv)
{
    __shared__ float ct[BB * CC];
    __shared__ float red[8][BB][32];
    const int tid = threadIdx.x, lane = tid & 31, seg = tid >> 5;
    for (int i = tid; i < BB * CC; i += 256) ct[i] = cls_tokens[i];
    __syncthreads();
    const int n = blockIdx.x * 32 + lane;
    float acc[BB] = {0.f, 0.f, 0.f, 0.f};
    for (int k = seg * 64; k < seg * 64 + 64; k++) {
        float w = Wqkv[(size_t)k * C3 + n];
        #pragma unroll
        for (int b = 0; b < BB; b++) acc[b] += ct[b * CC + k] * w;
    }
    #pragma unroll
    for (int b = 0; b < BB; b++) red[seg][b][lane] = acc[b];
    __syncthreads();
    if (seg < BB) {
        float s = bqkv[n];
        #pragma unroll
        for (int j = 0; j < 8; j++) s += red[j][seg][lane];
        g_clsqkv[seg * C3 + n] = s;
    }
}

// ------- tensor-core attention (online softmax, 2 KV halves) + fused cls -------
#define NP 272
#define KROWB 144
#define SM_KV   (2 * NP * KROWB)          // 78336
#define SM_QCS  SM_KV                      // 64 floats (cls query, scaled)
#define SM_SC   (SM_QCS + 256)             // 260 floats (cls scores / probs + inv)
#define SM_RED  (SM_SC + 1040)             // 256 floats (PV partials)
#define SM_QST  (SM_RED + 1024)            // 8 warps x 16 rows x 144B Q staging
#define ATT_SMEM (SM_QST + 8 * 16 * KROWB) // 99088

__global__ __launch_bounds__(256, 2)
void attn_mma_kernel(const int* __restrict__ offset)
{
    extern __shared__ char sm[];
    char* KhB = sm;
    char* VhB = sm + NP * KROWB;
    float* qcs = (float*)(sm + SM_QCS);
    float* sc  = (float*)(sm + SM_SC);
    float* red = (float*)(sm + SM_RED);
    const uint32_t sb = smem_u32(sm);
    const uint32_t KhU = sb;
    const uint32_t VhU = sb + NP * KROWB;

    const int ci = blockIdx.x, h = blockIdx.y, tid = threadIdx.x;
    const int wid = tid >> 5, lane = tid & 31;
    const int cs = ci * KK;
    int b = 0;
    #pragma unroll
    for (int j = 0; j < BB; j++) b += (offset[j] <= cs) ? 1 : 0;
    const __half* qkvh   = g_qkv_h + (size_t)cs * C3;
    const float*  clsrow = g_clsqkv + b * C3;
    const int koff = CC + h * DH, voff = 2 * CC + h * DH;

    // load K,V rows -> smem fp16 (pure 16B copies; cls row converted)
    for (int idx = tid; idx < 2 * NP * 8; idx += 256) {
        int kv = idx >= NP * 8;
        int i  = kv ? idx - NP * 8 : idx;
        int t = i >> 3, u = i & 7;
        int off = kv ? voff : koff;
        uint4 val = make_uint4(0u, 0u, 0u, 0u);
        if (t == 0) {
            const float* src = clsrow + off + u * 8;
            val.x = pack_h2(src[0], src[1]);
            val.y = pack_h2(src[2], src[3]);
            val.z = pack_h2(src[4], src[5]);
            val.w = pack_h2(src[6], src[7]);
        } else if (t <= KK) {
            val = *(const uint4*)(qkvh + (size_t)(t - 1) * C3 + off + u * 8);
        }
        *(uint4*)((kv ? VhB : KhB) + t * KROWB + u * 16) = val;
    }
    if (tid < 64) qcs[tid] = clsrow[h * DH + tid] * 0.125f;
    __syncthreads();

    // ===== fused cls-query attention (uses smem K/V) =====
    for (int j = tid; j < 257; j += 256) {
        float s = 0.f;
        #pragma unroll
        for (int u = 0; u < 8; u++) {
            uint4 k4 = *(const uint4*)(KhB + j * KROWB + u * 16);
            const __half2* h2 = (const __half2*)&k4;
            #pragma unroll
            for (int e = 0; e < 4; e++) {
                float2 kf = __half22float2(h2[e]);
                s += qcs[u * 8 + e * 2] * kf.x + qcs[u * 8 + e * 2 + 1] * kf.y;
            }
        }
        sc[j] = s;
    }
    __syncthreads();
    if (wid == 0) {
        float m = -1e30f;
        for (int j = lane; j < 257; j += 32) m = fmaxf(m, sc[j]);
        #pragma unroll
        for (int o = 16; o; o >>= 1) m = fmaxf(m, __shfl_xor_sync(0xffffffffu, m, o));
        float ssum = 0.f;
        for (int j = lane; j < 257; j += 32) {
            float e = __expf(sc[j] - m);
            sc[j] = e;
            ssum += e;
        }
        #pragma unroll
        for (int o = 16; o; o >>= 1) ssum += __shfl_xor_sync(0xffffffffu, ssum, o);
        if (lane == 0) sc[258] = 1.f / ssum;
    }
    __syncthreads();
    {   // PV: 4 key-groups x 64 dims
        const int g = tid >> 6, d = tid & 63;
        const int j0 = g * 64, cnt = (g == 3) ? 65 : 64;
        float acc = 0.f;
        for (int jj = 0; jj < cnt; jj++) {
            int j = j0 + jj;
            acc += sc[j] * __half2float(*(const __half*)(VhB + j * KROWB + d * 2));
        }
        red[g * 64 + d] = acc;
    }
    __syncthreads();
    if (tid < 64) {
        float inv = sc[258];
        float r = (red[tid] + red[64 + tid] + red[128 + tid] + red[192 + tid]) * inv;
        g_clspart[ci * CC + h * DH + tid] = r;
    }

    // ===== token-query attention (online softmax over 2 KV halves) =====
    const int r0 = lane >> 2;
    const int qp = (lane & 3) * 2;
    char* qstB = sm + SM_QST + wid * (16 * KROWB);
    const uint32_t qstU = sb + SM_QST + wid * (16 * KROWB);
    const uint32_t q_lm = qstU + (lane & 15) * KROWB + ((lane >> 4) & 1) * 16;

    #pragma unroll 1
    for (int mt = wid; mt < 16; mt += 8) {
        // stage this warp's Q tile (16 rows x 64 fp16) into smem, unscaled
        const __half* qbase = qkvh + (size_t)(mt * 16) * C3 + h * DH;
        __syncwarp();
        #pragma unroll
        for (int u = 0; u < 4; u++) {
            int g = lane + u * 32;
            int row = g >> 3, c8 = g & 7;
            *(uint4*)(qstB + row * KROWB + c8 * 16) =
                *(const uint4*)(qbase + (size_t)row * C3 + c8 * 8);
        }
        __syncwarp();

        float o[8][4];
        #pragma unroll
        for (int nt = 0; nt < 8; nt++)
            o[nt][0] = o[nt][1] = o[nt][2] = o[nt][3] = 0.f;
        float mr0 = -1e30f, mr1 = -1e30f, sr0 = 0.f, sr1 = 0.f;

        #pragma unroll 1
        for (int half = 0; half < 2; half++) {
            float acc[18][4];
            #pragma unroll
            for (int nt = 0; nt < 18; nt++)
                acc[nt][0] = acc[nt][1] = acc[nt][2] = acc[nt][3] = 0.f;

            // ---- S = Q K^T for this half ----
            #pragma unroll
            for (int kt = 0; kt < 4; kt++) {
                uint32_t qh[4];
                ldsm_x4(qh, q_lm + kt * 32);
                const uint32_t kaddr4 = KhU
                    + ((lane & 7) + ((lane >> 4) & 1) * 8) * KROWB
                    + ((lane >> 3) & 1) * 16 + kt * 32
                    + half * (8 * 16 * KROWB);
                #pragma unroll
                for (int p = 0; p < 8; p++) {
                    uint32_t b4[4];
                    ldsm_x4(b4, kaddr4 + p * 16 * KROWB);
                    mma_f16(acc[2 * p],     qh, &b4[0]);
                    mma_f16(acc[2 * p + 1], qh, &b4[2]);
                }
                if (half == 1) {   // tile 32 (keys 256..263)
                    uint32_t b4[4];
                    ldsm_x4(b4, kaddr4 + 8 * 16 * KROWB);
                    mma_f16(acc[16], qh, &b4[0]);
                }
            }

            const int NT = half ? 17 : 16;
            if (half == 1) {   // mask: only key 256 valid in tile 32
                if (qp != 0) { acc[16][0] = -1e30f; acc[16][2] = -1e30f; }
                acc[16][1] = -1e30f; acc[16][3] = -1e30f;
            }

            // ---- online softmax merge ----
            float lm0 = -1e30f, lm1 = -1e30f;
            #pragma unroll
            for (int nt = 0; nt < 17; nt++) {
                if (nt >= NT) break;
                lm0 = fmaxf(lm0, fmaxf(acc[nt][0], acc[nt][1]));
                lm1 = fmaxf(lm1, fmaxf(acc[nt][2], acc[nt][3]));
            }
            lm0 = fmaxf(lm0, __shfl_xor_sync(0xffffffffu, lm0, 1));
            lm0 = fmaxf(lm0, __shfl_xor_sync(0xffffffffu, lm0, 2));
            lm1 = fmaxf(lm1, __shfl_xor_sync(0xffffffffu, lm1, 1));
            lm1 = fmaxf(lm1, __shfl_xor_sync(0xffffffffu, lm1, 2));
            const float nm0 = fmaxf(mr0, lm0), nm1 = fmaxf(mr1, lm1);
            const float f0 = __expf(0.125f * (mr0 - nm0));
            const float f1 = __expf(0.125f * (mr1 - nm1));
            mr0 = nm0; mr1 = nm1;
            const float mm0 = nm0 * 0.125f, mm1 = nm1 * 0.125f;
            float ls0 = 0.f, ls1 = 0.f;
            #pragma unroll
            for (int nt = 0; nt < 17; nt++) {
                if (nt >= NT) break;
                acc[nt][0] = __expf(fmaf(acc[nt][0], 0.125f, -mm0));
                acc[nt][1] = __expf(fmaf(acc[nt][1], 0.125f, -mm0));
                acc[nt][2] = __expf(fmaf(acc[nt][2], 0.125f, -mm1));
                acc[nt][3] = __expf(fmaf(acc[nt][3], 0.125f, -mm1));
                ls0 += acc[nt][0] + acc[nt][1];
                ls1 += acc[nt][2] + acc[nt][3];
            }
            acc[17][0] = acc[17][1] = acc[17][2] = acc[17][3] = 0.f;
            if (half == 0) {
                acc[16][0] = acc[16][1] = acc[16][2] = acc[16][3] = 0.f;
            }
            ls0 += __shfl_xor_sync(0xffffffffu, ls0, 1);
            ls0 += __shfl_xor_sync(0xffffffffu, ls0, 2);
            ls1 += __shfl_xor_sync(0xffffffffu, ls1, 1);
            ls1 += __shfl_xor_sync(0xffffffffu, ls1, 2);
            sr0 = sr0 * f0 + ls0;
            sr1 = sr1 * f1 + ls1;
            #pragma unroll
            for (int nt = 0; nt < 8; nt++) {
                o[nt][0] *= f0; o[nt][1] *= f0;
                o[nt][2] *= f1; o[nt][3] *= f1;
            }

            // ---- O += P V for this half ----
            const int NKT = half ? 9 : 8;
            #pragma unroll
            for (int ktl = 0; ktl < 9; ktl++) {
                if (ktl >= NKT) break;
                uint32_t ah[4];
                ah[0] = pack_h2(acc[2*ktl][0],   acc[2*ktl][1]);
                ah[1] = pack_h2(acc[2*ktl][2],   acc[2*ktl][3]);
                ah[2] = pack_h2(acc[2*ktl+1][0], acc[2*ktl+1][1]);
                ah[3] = pack_h2(acc[2*ktl+1][2], acc[2*ktl+1][3]);
                const uint32_t vaddr4 = VhU
                    + ((half * 8 + ktl) * 16 + (lane & 15)) * KROWB
                    + ((lane >> 4) & 1) * 16;
                #pragma unroll
                for (int p = 0; p < 4; p++) {
                    uint32_t b4[4];
                    ldsm_x4_t(b4, vaddr4 + p * 32);
                    mma_f16(o[2 * p],     ah, &b4[0]);
                    mma_f16(o[2 * p + 1], ah, &b4[2]);
                }
            }
        }

        const float inv0 = 1.f / sr0, inv1 = 1.f / sr1;
        const size_t row0 = (size_t)(cs + mt * 16 + r0) * CC + h * DH;
        const size_t row1 = row0 + 8 * CC;
        #pragma unroll
        for (int nt = 0; nt < 8; nt++) {
            *(uint32_t*)(g_att_h + row0 + nt * 8 + qp) =
                pack_h2(o[nt][0] * inv0, o[nt][1] * inv0);
            *(uint32_t*)(g_att_h + row1 + nt * 8 + qp) =
                pack_h2(o[nt][2] * inv1, o[nt][3] * inv1);
        }
    }
}

// ---------------- cls reduce ----------------
__global__ __launch_bounds__(256)
void cls_reduce_kernel(const int* __restrict__ offset, float* __restrict__ out_cls)
{
    int gid = blockIdx.x * 256 + threadIdx.x;
    int b = gid >> 9;
    int c = gid & (CC - 1);
    int start = (b == 0) ? 0 : offset[b - 1];
    int end = offset[b];
    int ch0 = start / KK, ch1 = end / KK;
    float s = 0.f;
    for (int ch = ch0; ch < ch1; ch++) s += g_clspart[ch * CC + c];
    out_cls[gid] = s / (float)(ch1 - ch0);
}

// ---------------- launch ----------------
extern "C" void kernel_launch(void* const* d_in, const int* in_sizes, int n_in,
                              void* d_out, int out_size)
{
    const float* feat       = (const float*)d_in[0];
    const float* cls_tokens = (const float*)d_in[1];
    const float* Wqkv       = (const float*)d_in[2];
    const float* bqkv       = (const float*)d_in[3];
    const float* Wproj      = (const float*)d_in[4];
    const float* bproj      = (const float*)d_in[5];
    const int*   order      = (const int*)d_in[6];
    const int*   offset     = (const int*)d_in[8];

    float* out_feat = (float*)d_out;
    float* out_cls  = out_feat + (size_t)NPTS * CC;

    void *qkvp = nullptr;
    void *ah = nullptr, *ath = nullptr;
    void *wq = nullptr, *wp = nullptr;
    cudaGetSymbolAddress(&qkvp, g_qkv_h);
    cudaGetSymbolAddress(&ah, g_Ah);
    cudaGetSymbolAddress(&ath, g_att_h);
    cudaGetSymbolAddress(&wq, g_WqkvT);
    cudaGetSymbolAddress(&wp, g_WprojT);

    cudaFuncSetAttribute(attn_mma_kernel, cudaFuncAttributeMaxDynamicSharedMemorySize,
                         ATT_SMEM);
    cudaFuncSetAttribute(gemm_async_kernel<false, true>,
                         cudaFuncAttributeMaxDynamicSharedMemorySize, GSMEM);
    cudaFuncSetAttribute(gemm_async_kernel<true, false>,
                         cudaFuncAttributeMaxDynamicSharedMemorySize, GSMEM);

    // 0. weight transpose (fp16), feat gather (fp16)
    conv_wt_kernel<<<dim3(C3 / 32, CC / 32), 256>>>(Wqkv, (__half*)wq, CC, C3);
    conv_wt_kernel<<<dim3(CC / 32, CC / 32), 256>>>(Wproj, (__half*)wp, CC, CC);
    conv_feat_kernel<<<(NPTS * (CC / 4)) / 256, 256>>>(feat, order);
    // 1. cls token qkv
    cls_qkv_kernel<<<C3 / 32, 256>>>(cls_tokens, Wqkv, bqkv);
    // 2. qkv GEMM -> fp16 output
    gemm_async_kernel<false, true><<<dim3(C3 / 128, NPTS / 128), 256, GSMEM>>>(
        (const __half*)ah, (const __half*)wq, bqkv, qkvp, order, C3);
    // 3. attention (token queries, online softmax + fused cls query)
    attn_mma_kernel<<<dim3(NCH, HH), 256, ATT_SMEM>>>(offset);
    // 4. proj GEMM with scatter -> fp32 output
    gemm_async_kernel<true, false><<<dim3(CC / 128, NPTS / 128), 256, GSMEM>>>(
        (const __half*)ath, (const __half*)wp, bproj, (void*)out_feat, order, CC);
    // 5. cls reduction
    cls_reduce_kernel<<<(BB * CC) / 256, 256>>>(offset, out_cls);
}

// round 15
// speedup vs baseline: 2.2398x; 1.0255x over previous
#include <cuda_runtime.h>
#include <cuda_fp16.h>
#include <cstdint>
#include <cstddef>

#define NPTS 65536
#define BB 4
#define CC 512
#define C3 1536
#define KK 256
#define HH 8
#define DH 64
#define NCH 256   // NPTS/KK

// ---------------- scratch (static device globals; no allocation) ----------------
__device__ __half g_qkv_h[(size_t)NPTS * C3]; // gathered qkv, serialized order (fp16)
__device__ float g_clsqkv[BB * C3];            // cls token qkv (fp32)
__device__ float g_clspart[NCH * CC];          // per-chunk cls attention row
__device__ __half g_Ah[(size_t)NPTS * CC];     // gathered feat (fp16)
__device__ __half g_att_h[(size_t)NPTS * CC];  // attention out (fp16, serialized)
__device__ __half g_WqkvT[(size_t)C3 * CC];    // W^T fp16
__device__ __half g_WprojT[(size_t)CC * CC];

// =============== helpers ===============
__device__ __forceinline__ uint32_t smem_u32(const void* p) {
    uint32_t a;
    asm("{ .reg .u64 t; cvta.to.shared.u64 t, %1; cvt.u32.u64 %0, t; }" : "=r"(a) : "l"(p));
    return a;
}
__device__ __forceinline__ void ldsm_x4(uint32_t* r, uint32_t addr) {
    asm volatile("ldmatrix.sync.aligned.m8n8.x4.shared.b16 {%0,%1,%2,%3}, [%4];"
                 : "=r"(r[0]), "=r"(r[1]), "=r"(r[2]), "=r"(r[3]) : "r"(addr));
}
__device__ __forceinline__ void ldsm_x4_t(uint32_t* r, uint32_t addr) {
    asm volatile("ldmatrix.sync.aligned.m8n8.x4.trans.shared.b16 {%0,%1,%2,%3}, [%4];"
                 : "=r"(r[0]), "=r"(r[1]), "=r"(r[2]), "=r"(r[3]) : "r"(addr));
}
__device__ __forceinline__ void mma_f16(float* c, const uint32_t* a, const uint32_t* b) {
    asm volatile(
        "mma.sync.aligned.m16n8k16.row.col.f32.f16.f16.f32 "
        "{%0,%1,%2,%3}, {%4,%5,%6,%7}, {%8,%9}, {%0,%1,%2,%3};"
        : "+f"(c[0]), "+f"(c[1]), "+f"(c[2]), "+f"(c[3])
        : "r"(a[0]), "r"(a[1]), "r"(a[2]), "r"(a[3]), "r"(b[0]), "r"(b[1]));
}
__device__ __forceinline__ uint32_t pack_h2(float x, float y) {
    __half2 hh = __floats2half2_rn(x, y);
    return *reinterpret_cast<uint32_t*>(&hh);
}
__device__ __forceinline__ void cp_async16(uint32_t dst, const void* src) {
    asm volatile("cp.async.cg.shared.global [%0], [%1], 16;" :: "r"(dst), "l"(src) : "memory");
}
#define CP_COMMIT() asm volatile("cp.async.commit_group;" ::: "memory")
#define CP_WAIT1()  asm volatile("cp.async.wait_group 1;" ::: "memory")

// ================= fused prep kernel =================
// block ranges: [0,48) cls_qkv | [48,816) Wqkv transpose | [816,1072) Wproj transpose
//               [1072, 1072+32768) feat gather
#define PREP_CLS   48
#define PREP_WQ    (48 + 768)
#define PREP_WP    (PREP_WQ + 256)
#define PREP_FEAT  32768
#define PREP_GRID  (PREP_WP + PREP_FEAT)

__device__ void do_conv_wt(const float* __restrict__ W, __half* __restrict__ T,
                           int K, int N, int bx, int by, float* sh)
{
    int n0 = bx * 32, k0 = by * 32;
    int tx = threadIdx.x & 31, ty = threadIdx.x >> 5;
    #pragma unroll
    for (int j = 0; j < 32; j += 8)
        sh[(ty + j) * 33 + tx] = W[(size_t)(k0 + ty + j) * N + n0 + tx];
    __syncthreads();
    #pragma unroll
    for (int j = 0; j < 32; j += 8) {
        int n = n0 + ty + j, k = k0 + tx;
        T[(size_t)n * K + k] = __float2half_rn(sh[tx * 33 + ty + j]);
    }
}

__global__ __launch_bounds__(256)
void prep_kernel(const float* __restrict__ feat, const int* __restrict__ order,
                 const float* __restrict__ cls_tokens, const float* __restrict__ Wqkv,
                 const float* __restrict__ bqkv, const float* __restrict__ Wproj)
{
    __shared__ float sh[3072];   // 12 KB, reused per role
    const int bid = blockIdx.x;
    const int tid = threadIdx.x;

    if (bid < PREP_CLS) {
        // ---- cls qkv: k-split across 8 warp-segments ----
        float* ct  = sh;          // 2048
        float* red = sh + 2048;   // 1024
        const int lane = tid & 31, seg = tid >> 5;
        for (int i = tid; i < BB * CC; i += 256) ct[i] = cls_tokens[i];
        __syncthreads();
        const int n = bid * 32 + lane;
        float acc[BB] = {0.f, 0.f, 0.f, 0.f};
        for (int k = seg * 64; k < seg * 64 + 64; k++) {
            float w = Wqkv[(size_t)k * C3 + n];
            #pragma unroll
            for (int b = 0; b < BB; b++) acc[b] += ct[b * CC + k] * w;
        }
        #pragma unroll
        for (int b = 0; b < BB; b++) red[(seg * BB + b) * 32 + lane] = acc[b];
        __syncthreads();
        if (seg < BB) {
            float s = bqkv[n];
            #pragma unroll
            for (int j = 0; j < 8; j++) s += red[(j * BB + seg) * 32 + lane];
            g_clsqkv[seg * C3 + n] = s;
        }
    } else if (bid < PREP_WQ) {
        int idx = bid - PREP_CLS;           // 768 = 48 x 16
        do_conv_wt(Wqkv, g_WqkvT, CC, C3, idx % 48, idx / 48, sh);
    } else if (bid < PREP_WP) {
        int idx = bid - PREP_WQ;            // 256 = 16 x 16
        do_conv_wt(Wproj, g_WprojT, CC, CC, idx % 16, idx / 16, sh);
    } else {
        // ---- feat gather -> fp16 ----
        size_t idx = (size_t)(bid - PREP_WP) * 256 + tid;
        int m = (int)(idx >> 7);
        int u = (int)(idx & 127);
        const float4 v = *(const float4*)(feat + (size_t)order[m] * CC + u * 4);
        *(uint2*)(g_Ah + (size_t)m * CC + u * 4) =
            make_uint2(pack_h2(v.x, v.y), pack_h2(v.z, v.w));
    }
}

// ---- cp.async GEMM: 128x128 tile, Kc=64, 3 stages, single fp16, 2 CTAs/SM ----
#define QROWB  144
#define QTILE  (128 * QROWB)       // 18432
#define QSTAGE (2 * QTILE)         // 36864 (A | B)
#define SMHDR  1024
#define GSMEM  (SMHDR + 3 * QSTAGE)   // 111616

template<bool SCATTER, bool OUTHALF>
__global__ __launch_bounds__(256, 2)
void gemm_async_kernel(const __half* __restrict__ Ah, const __half* __restrict__ Bh,
                       const float* __restrict__ bias, void* __restrict__ Cv,
                       const int* __restrict__ order, int Ntot)
{
    extern __shared__ char sm[];
    const uint32_t sb = smem_u32(sm);
    const int tid = threadIdx.x, wid = tid >> 5, lane = tid & 31;
    const int n0 = blockIdx.x * 128, m0 = blockIdx.y * 128;
    float* bias_s = (float*)sm;
    int*   rowidx = (int*)(sm + 512);

    auto issue_stage = [&](int c, int stage) {
        const size_t kb = (size_t)c * 128;
        const uint32_t dbase = sb + SMHDR + stage * QSTAGE;
        #pragma unroll
        for (int i = 0; i < 8; i++) {
            const int g = tid + i * 256;
            const int tile = g >> 10;
            const int u = g & 1023;
            const int row = u >> 3, col8 = u & 7;
            const char* src = (const char*)(tile ? Bh + (size_t)(n0 + row) * CC
                                                 : Ah + (size_t)(m0 + row) * CC) + kb;
            cp_async16(dbase + tile * QTILE + row * QROWB + col8 * 16, src + col8 * 16);
        }
    };

    issue_stage(0, 0); CP_COMMIT();
    issue_stage(1, 1); CP_COMMIT();

    if (tid < 128) {
        bias_s[tid] = bias[n0 + tid];
        if (SCATTER) rowidx[tid] = order[m0 + tid];
    }
    __syncthreads();

    const int wm = (wid & 1) * 64;
    const int wn = (wid >> 1) * 32;

    float acc[4][4][4];
    #pragma unroll
    for (int nt = 0; nt < 4; nt++) {
        float b0 = bias_s[wn + nt * 8 + 2 * (lane & 3)];
        float b1 = bias_s[wn + nt * 8 + 2 * (lane & 3) + 1];
        #pragma unroll
        for (int mt = 0; mt < 4; mt++) {
            acc[mt][nt][0] = b0; acc[mt][nt][1] = b1;
            acc[mt][nt][2] = b0; acc[mt][nt][3] = b1;
        }
    }

    const uint32_t a_lm  = sb + SMHDR + (wm + (lane & 15)) * QROWB + ((lane >> 4) & 1) * 16;
    const uint32_t b_lm4 = sb + SMHDR + QTILE
                           + (wn + (lane & 7) + ((lane >> 4) & 1) * 8) * QROWB
                           + ((lane >> 3) & 1) * 16;

    const int NC = CC / 64;   // 8
    #pragma unroll 1
    for (int c = 0; c < NC; c++) {
        CP_WAIT1();
        __syncthreads();
        if (c + 2 < NC) issue_stage(c + 2, (c + 2) % 3);
        CP_COMMIT();

        const uint32_t abase = a_lm  + (c % 3) * QSTAGE;
        const uint32_t bbase = b_lm4 + (c % 3) * QSTAGE;
        #pragma unroll
        for (int ks = 0; ks < 4; ks++) {
            const int ko = ks * 32;
            uint32_t ah[4][4], bh[2][4];
            #pragma unroll
            for (int mt = 0; mt < 4; mt++)
                ldsm_x4(ah[mt], abase + mt * 16 * QROWB + ko);
            #pragma unroll
            for (int p = 0; p < 2; p++)
                ldsm_x4(bh[p], bbase + p * 16 * QROWB + ko);
            #pragma unroll
            for (int mt = 0; mt < 4; mt++)
                #pragma unroll
                for (int nt = 0; nt < 4; nt++)
                    mma_f16(acc[mt][nt], ah[mt], &bh[nt >> 1][(nt & 1) * 2]);
        }
    }

    #pragma unroll
    for (int mt = 0; mt < 4; mt++) {
        int lrow = wm + mt * 16 + (lane >> 2);
        int d0 = SCATTER ? rowidx[lrow]     : (m0 + lrow);
        int d1 = SCATTER ? rowidx[lrow + 8] : (m0 + lrow + 8);
        #pragma unroll
        for (int nt = 0; nt < 4; nt++) {
            int col = n0 + wn + nt * 8 + 2 * (lane & 3);
            if (OUTHALF) {
                __half* C = (__half*)Cv;
                *(uint32_t*)(C + (size_t)d0 * Ntot + col) =
                    pack_h2(acc[mt][nt][0], acc[mt][nt][1]);
                *(uint32_t*)(C + (size_t)d1 * Ntot + col) =
                    pack_h2(acc[mt][nt][2], acc[mt][nt][3]);
            } else {
                float* C = (float*)Cv;
                *(float2*)(C + (size_t)d0 * Ntot + col) =
                    make_float2(acc[mt][nt][0], acc[mt][nt][1]);
                *(float2*)(C + (size_t)d1 * Ntot + col) =
                    make_float2(acc[mt][nt][2], acc[mt][nt][3]);
            }
        }
    }
}

// ------- tensor-core attention (online softmax, 2 KV halves) + fused cls -------
#define NP 272
#define KROWB 144
#define SM_KV   (2 * NP * KROWB)          // 78336
#define SM_QCS  SM_KV                      // 64 floats (cls query, scaled)
#define SM_SC   (SM_QCS + 256)             // 260 floats (cls scores / probs + inv)
#define SM_RED  (SM_SC + 1040)             // 256 floats (PV partials)
#define SM_QST  (SM_RED + 1024)            // 8 warps x 16 rows x 144B Q staging
#define ATT_SMEM (SM_QST + 8 * 16 * KROWB) // 99088

__global__ __launch_bounds__(256, 2)
void attn_mma_kernel(const int* __restrict__ offset)
{
    extern __shared__ char sm[];
    char* KhB = sm;
    char* VhB = sm + NP * KROWB;
    float* qcs = (float*)(sm + SM_QCS);
    float* sc  = (float*)(sm + SM_SC);
    float* red = (float*)(sm + SM_RED);
    const uint32_t sb = smem_u32(sm);
    const uint32_t KhU = sb;
    const uint32_t VhU = sb + NP * KROWB;

    const int ci = blockIdx.x, h = blockIdx.y, tid = threadIdx.x;
    const int wid = tid >> 5, lane = tid & 31;
    const int cs = ci * KK;
    int b = 0;
    #pragma unroll
    for (int j = 0; j < BB; j++) b += (offset[j] <= cs) ? 1 : 0;
    const __half* qkvh   = g_qkv_h + (size_t)cs * C3;
    const float*  clsrow = g_clsqkv + b * C3;
    const int koff = CC + h * DH, voff = 2 * CC + h * DH;

    // load K,V rows -> smem fp16 (pure 16B copies; cls row converted)
    for (int idx = tid; idx < 2 * NP * 8; idx += 256) {
        int kv = idx >= NP * 8;
        int i  = kv ? idx - NP * 8 : idx;
        int t = i >> 3, u = i & 7;
        int off = kv ? voff : koff;
        uint4 val = make_uint4(0u, 0u, 0u, 0u);
        if (t == 0) {
            const float* src = clsrow + off + u * 8;
            val.x = pack_h2(src[0], src[1]);
            val.y = pack_h2(src[2], src[3]);
            val.z = pack_h2(src[4], src[5]);
            val.w = pack_h2(src[6], src[7]);
        } else if (t <= KK) {
            val = *(const uint4*)(qkvh + (size_t)(t - 1) * C3 + off + u * 8);
        }
        *(uint4*)((kv ? VhB : KhB) + t * KROWB + u * 16) = val;
    }
    if (tid < 64) qcs[tid] = clsrow[h * DH + tid] * 0.125f;
    __syncthreads();

    // ===== fused cls-query attention (uses smem K/V) =====
    for (int j = tid; j < 257; j += 256) {
        float s = 0.f;
        #pragma unroll
        for (int u = 0; u < 8; u++) {
            uint4 k4 = *(const uint4*)(KhB + j * KROWB + u * 16);
            const __half2* h2 = (const __half2*)&k4;
            #pragma unroll
            for (int e = 0; e < 4; e++) {
                float2 kf = __half22float2(h2[e]);
                s += qcs[u * 8 + e * 2] * kf.x + qcs[u * 8 + e * 2 + 1] * kf.y;
            }
        }
        sc[j] = s;
    }
    __syncthreads();
    if (wid == 0) {
        float m = -1e30f;
        for (int j = lane; j < 257; j += 32) m = fmaxf(m, sc[j]);
        #pragma unroll
        for (int o = 16; o; o >>= 1) m = fmaxf(m, __shfl_xor_sync(0xffffffffu, m, o));
        float ssum = 0.f;
        for (int j = lane; j < 257; j += 32) {
            float e = __expf(sc[j] - m);
            sc[j] = e;
            ssum += e;
        }
        #pragma unroll
        for (int o = 16; o; o >>= 1) ssum += __shfl_xor_sync(0xffffffffu, ssum, o);
        if (lane == 0) sc[258] = 1.f / ssum;
    }
    __syncthreads();
    {   // PV: 4 key-groups x 64 dims
        const int g = tid >> 6, d = tid & 63;
        const int j0 = g * 64, cnt = (g == 3) ? 65 : 64;
        float acc = 0.f;
        for (int jj = 0; jj < cnt; jj++) {
            int j = j0 + jj;
            acc += sc[j] * __half2float(*(const __half*)(VhB + j * KROWB + d * 2));
        }
        red[g * 64 + d] = acc;
    }
    __syncthreads();
    if (tid < 64) {
        float inv = sc[258];
        float r = (red[tid] + red[64 + tid] + red[128 + tid] + red[192 + tid]) * inv;
        g_clspart[ci * CC + h * DH + tid] = r;
    }

    // ===== token-query attention (online softmax over 2 KV halves) =====
    const int r0 = lane >> 2;
    const int qp = (lane & 3) * 2;
    char* qstB = sm + SM_QST + wid * (16 * KROWB);
    const uint32_t qstU = sb + SM_QST + wid * (16 * KROWB);
    const uint32_t q_lm = qstU + (lane & 15) * KROWB + ((lane >> 4) & 1) * 16;

    #pragma unroll 1
    for (int mt = wid; mt < 16; mt += 8) {
        const __half* qbase = qkvh + (size_t)(mt * 16) * C3 + h * DH;
        __syncwarp();
        #pragma unroll
        for (int u = 0; u < 4; u++) {
            int g = lane + u * 32;
            int row = g >> 3, c8 = g & 7;
            *(uint4*)(qstB + row * KROWB + c8 * 16) =
                *(const uint4*)(qbase + (size_t)row * C3 + c8 * 8);
        }
        __syncwarp();

        float o[8][4];
        #pragma unroll
        for (int nt = 0; nt < 8; nt++)
            o[nt][0] = o[nt][1] = o[nt][2] = o[nt][3] = 0.f;
        float mr0 = -1e30f, mr1 = -1e30f, sr0 = 0.f, sr1 = 0.f;

        #pragma unroll 1
        for (int half = 0; half < 2; half++) {
            float acc[18][4];
            #pragma unroll
            for (int nt = 0; nt < 18; nt++)
                acc[nt][0] = acc[nt][1] = acc[nt][2] = acc[nt][3] = 0.f;

            #pragma unroll
            for (int kt = 0; kt < 4; kt++) {
                uint32_t qh[4];
                ldsm_x4(qh, q_lm + kt * 32);
                const uint32_t kaddr4 = KhU
                    + ((lane & 7) + ((lane >> 4) & 1) * 8) * KROWB
                    + ((lane >> 3) & 1) * 16 + kt * 32
                    + half * (8 * 16 * KROWB);
                #pragma unroll
                for (int p = 0; p < 8; p++) {
                    uint32_t b4[4];
                    ldsm_x4(b4, kaddr4 + p * 16 * KROWB);
                    mma_f16(acc[2 * p],     qh, &b4[0]);
                    mma_f16(acc[2 * p + 1], qh, &b4[2]);
                }
                if (half == 1) {
                    uint32_t b4[4];
                    ldsm_x4(b4, kaddr4 + 8 * 16 * KROWB);
                    mma_f16(acc[16], qh, &b4[0]);
                }
            }

            const int NT = half ? 17 : 16;
            if (half == 1) {
                if (qp != 0) { acc[16][0] = -1e30f; acc[16][2] = -1e30f; }
                acc[16][1] = -1e30f; acc[16][3] = -1e30f;
            }

            float lm0 = -1e30f, lm1 = -1e30f;
            #pragma unroll
            for (int nt = 0; nt < 17; nt++) {
                if (nt >= NT) break;
                lm0 = fmaxf(lm0, fmaxf(acc[nt][0], acc[nt][1]));
                lm1 = fmaxf(lm1, fmaxf(acc[nt][2], acc[nt][3]));
            }
            lm0 = fmaxf(lm0, __shfl_xor_sync(0xffffffffu, lm0, 1));
            lm0 = fmaxf(lm0, __shfl_xor_sync(0xffffffffu, lm0, 2));
            lm1 = fmaxf(lm1, __shfl_xor_sync(0xffffffffu, lm1, 1));
            lm1 = fmaxf(lm1, __shfl_xor_sync(0xffffffffu, lm1, 2));
            const float nm0 = fmaxf(mr0, lm0), nm1 = fmaxf(mr1, lm1);
            const float f0 = __expf(0.125f * (mr0 - nm0));
            const float f1 = __expf(0.125f * (mr1 - nm1));
            mr0 = nm0; mr1 = nm1;
            const float mm0 = nm0 * 0.125f, mm1 = nm1 * 0.125f;
            float ls0 = 0.f, ls1 = 0.f;
            #pragma unroll
            for (int nt = 0; nt < 17; nt++) {
                if (nt >= NT) break;
                acc[nt][0] = __expf(fmaf(acc[nt][0], 0.125f, -mm0));
                acc[nt][1] = __expf(fmaf(acc[nt][1], 0.125f, -mm0));
                acc[nt][2] = __expf(fmaf(acc[nt][2], 0.125f, -mm1));
                acc[nt][3] = __expf(fmaf(acc[nt][3], 0.125f, -mm1));
                ls0 += acc[nt][0] + acc[nt][1];
                ls1 += acc[nt][2] + acc[nt][3];
            }
            acc[17][0] = acc[17][1] = acc[17][2] = acc[17][3] = 0.f;
            if (half == 0) {
                acc[16][0] = acc[16][1] = acc[16][2] = acc[16][3] = 0.f;
            }
            ls0 += __shfl_xor_sync(0xffffffffu, ls0, 1);
            ls0 += __shfl_xor_sync(0xffffffffu, ls0, 2);
            ls1 += __shfl_xor_sync(0xffffffffu, ls1, 1);
            ls1 += __shfl_xor_sync(0xffffffffu, ls1, 2);
            sr0 = sr0 * f0 + ls0;
            sr1 = sr1 * f1 + ls1;
            #pragma unroll
            for (int nt = 0; nt < 8; nt++) {
                o[nt][0] *= f0; o[nt][1] *= f0;
                o[nt][2] *= f1; o[nt][3] *= f1;
            }

            const int NKT = half ? 9 : 8;
            #pragma unroll
            for (int ktl = 0; ktl < 9; ktl++) {
                if (ktl >= NKT) break;
                uint32_t ah[4];
                ah[0] = pack_h2(acc[2*ktl][0],   acc[2*ktl][1]);
                ah[1] = pack_h2(acc[2*ktl][2],   acc[2*ktl][3]);
                ah[2] = pack_h2(acc[2*ktl+1][0], acc[2*ktl+1][1]);
                ah[3] = pack_h2(acc[2*ktl+1][2], acc[2*ktl+1][3]);
                const uint32_t vaddr4 = VhU
                    + ((half * 8 + ktl) * 16 + (lane & 15)) * KROWB
                    + ((lane >> 4) & 1) * 16;
                #pragma unroll
                for (int p = 0; p < 4; p++) {
                    uint32_t b4[4];
                    ldsm_x4_t(b4, vaddr4 + p * 32);
                    mma_f16(o[2 * p],     ah, &b4[0]);
                    mma_f16(o[2 * p + 1], ah, &b4[2]);
                }
            }
        }

        const float inv0 = 1.f / sr0, inv1 = 1.f / sr1;
        const size_t row0 = (size_t)(cs + mt * 16 + r0) * CC + h * DH;
        const size_t row1 = row0 + 8 * CC;
        #pragma unroll
        for (int nt = 0; nt < 8; nt++) {
            *(uint32_t*)(g_att_h + row0 + nt * 8 + qp) =
                pack_h2(o[nt][0] * inv0, o[nt][1] * inv0);
            *(uint32_t*)(g_att_h + row1 + nt * 8 + qp) =
                pack_h2(o[nt][2] * inv1, o[nt][3] * inv1);
        }
    }
}

// ---------------- cls reduce ----------------
__global__ __launch_bounds__(256)
void cls_reduce_kernel(const int* __restrict__ offset, float* __restrict__ out_cls)
{
    int gid = blockIdx.x * 256 + threadIdx.x;
    int b = gid >> 9;
    int c = gid & (CC - 1);
    int start = (b == 0) ? 0 : offset[b - 1];
    int end = offset[b];
    int ch0 = start / KK, ch1 = end / KK;
    float s = 0.f;
    for (int ch = ch0; ch < ch1; ch++) s += g_clspart[ch * CC + c];
    out_cls[gid] = s / (float)(ch1 - ch0);
}

// ---------------- launch ----------------
extern "C" void kernel_launch(void* const* d_in, const int* in_sizes, int n_in,
                              void* d_out, int out_size)
{
    const float* feat       = (const float*)d_in[0];
    const float* cls_tokens = (const float*)d_in[1];
    const float* Wqkv       = (const float*)d_in[2];
    const float* bqkv       = (const float*)d_in[3];
    const float* Wproj      = (const float*)d_in[4];
    const float* bproj      = (const float*)d_in[5];
    const int*   order      = (const int*)d_in[6];
    const int*   offset     = (const int*)d_in[8];

    float* out_feat = (float*)d_out;
    float* out_cls  = out_feat + (size_t)NPTS * CC;

    void *qkvp = nullptr;
    void *ah = nullptr, *ath = nullptr;
    void *wq = nullptr, *wp = nullptr;
    cudaGetSymbolAddress(&qkvp, g_qkv_h);
    cudaGetSymbolAddress(&ah, g_Ah);
    cudaGetSymbolAddress(&ath, g_att_h);
    cudaGetSymbolAddress(&wq, g_WqkvT);
    cudaGetSymbolAddress(&wp, g_WprojT);

    cudaFuncSetAttribute(attn_mma_kernel, cudaFuncAttributeMaxDynamicSharedMemorySize,
                         ATT_SMEM);
    cudaFuncSetAttribute(gemm_async_kernel<false, true>,
                         cudaFuncAttributeMaxDynamicSharedMemorySize, GSMEM);
    cudaFuncSetAttribute(gemm_async_kernel<true, false>,
                         cudaFuncAttributeMaxDynamicSharedMemorySize, GSMEM);

    // 0+1. fused prep: cls_qkv + W transposes + feat gather (one launch)
    prep_kernel<<<PREP_GRID, 256>>>(feat, order, cls_tokens, Wqkv, bqkv, Wproj);
    // 2. qkv GEMM -> fp16 output
    gemm_async_kernel<false, true><<<dim3(C3 / 128, NPTS / 128), 256, GSMEM>>>(
        (const __half*)ah, (const __half*)wq, bqkv, qkvp, order, C3);
    // 3. attention (token queries, online softmax + fused cls query)
    attn_mma_kernel<<<dim3(NCH, HH), 256, ATT_SMEM>>>(offset);
    // 4. proj GEMM with scatter -> fp32 output
    gemm_async_kernel<true, false><<<dim3(CC / 128, NPTS / 128), 256, GSMEM>>>(
        (const __half*)ath, (const __half*)wp, bproj, (void*)out_feat, order, CC);
    // 5. cls reduction
    cls_reduce_kernel<<<(BB * CC) / 256, 256>>>(offset, out_cls);
}

// round 16
// speedup vs baseline: 2.4859x; 1.1099x over previous
#include <cuda_runtime.h>
#include <cuda_fp16.h>
#include <cstdint>
#include <cstddef>

#define NPTS 65536
#define BB 4
#define CC 512
#define C3 1536
#define KK 256
#define HH 8
#define DH 64
#define NCH 256   // NPTS/KK

// ---------------- scratch (static device globals; no allocation) ----------------
__device__ __half g_qkv_h[(size_t)NPTS * C3]; // gathered qkv, serialized order (fp16)
__device__ float g_clsqkv[BB * C3];            // cls token qkv (fp32)
__device__ float g_clspart[NCH * CC];          // per-chunk cls attention row
__device__ __half g_Ah[(size_t)NPTS * CC];     // gathered feat (fp16)
__device__ __half g_att_h[(size_t)NPTS * CC];  // attention out (fp16, serialized)
__device__ __half g_WqkvT[(size_t)C3 * CC];    // W^T fp16
__device__ __half g_WprojT[(size_t)CC * CC];

// =============== helpers ===============
__device__ __forceinline__ uint32_t smem_u32(const void* p) {
    uint32_t a;
    asm("{ .reg .u64 t; cvta.to.shared.u64 t, %1; cvt.u32.u64 %0, t; }" : "=r"(a) : "l"(p));
    return a;
}
__device__ __forceinline__ void ldsm_x4(uint32_t* r, uint32_t addr) {
    asm volatile("ldmatrix.sync.aligned.m8n8.x4.shared.b16 {%0,%1,%2,%3}, [%4];"
                 : "=r"(r[0]), "=r"(r[1]), "=r"(r[2]), "=r"(r[3]) : "r"(addr));
}
__device__ __forceinline__ void ldsm_x4_t(uint32_t* r, uint32_t addr) {
    asm volatile("ldmatrix.sync.aligned.m8n8.x4.trans.shared.b16 {%0,%1,%2,%3}, [%4];"
                 : "=r"(r[0]), "=r"(r[1]), "=r"(r[2]), "=r"(r[3]) : "r"(addr));
}
__device__ __forceinline__ void mma_f16(float* c, const uint32_t* a, const uint32_t* b) {
    asm volatile(
        "mma.sync.aligned.m16n8k16.row.col.f32.f16.f16.f32 "
        "{%0,%1,%2,%3}, {%4,%5,%6,%7}, {%8,%9}, {%0,%1,%2,%3};"
        : "+f"(c[0]), "+f"(c[1]), "+f"(c[2]), "+f"(c[3])
        : "r"(a[0]), "r"(a[1]), "r"(a[2]), "r"(a[3]), "r"(b[0]), "r"(b[1]));
}
__device__ __forceinline__ uint32_t pack_h2(float x, float y) {
    __half2 hh = __floats2half2_rn(x, y);
    return *reinterpret_cast<uint32_t*>(&hh);
}
__device__ __forceinline__ void cp_async16(uint32_t dst, const void* src) {
    asm volatile("cp.async.cg.shared.global [%0], [%1], 16;" :: "r"(dst), "l"(src) : "memory");
}
#define CP_COMMIT() asm volatile("cp.async.commit_group;" ::: "memory")
#define CP_WAIT1()  asm volatile("cp.async.wait_group 1;" ::: "memory")
#define CP_WAIT0()  asm volatile("cp.async.wait_group 0;" ::: "memory")

// ================= fused prep kernel =================
// block ranges: [0,48) cls_qkv | [48,816) Wqkv transpose | [816,1072) Wproj transpose
//               [1072, 1072+8192) feat gather (4 float4 per thread)
#define PREP_CLS   48
#define PREP_WQ    (48 + 768)
#define PREP_WP    (PREP_WQ + 256)
#define PREP_FEAT  8192
#define PREP_GRID  (PREP_WP + PREP_FEAT)

__device__ void do_conv_wt(const float* __restrict__ W, __half* __restrict__ T,
                           int K, int N, int bx, int by, float* sh)
{
    int n0 = bx * 32, k0 = by * 32;
    int tx = threadIdx.x & 31, ty = threadIdx.x >> 5;
    #pragma unroll
    for (int j = 0; j < 32; j += 8)
        sh[(ty + j) * 33 + tx] = W[(size_t)(k0 + ty + j) * N + n0 + tx];
    __syncthreads();
    #pragma unroll
    for (int j = 0; j < 32; j += 8) {
        int n = n0 + ty + j, k = k0 + tx;
        T[(size_t)n * K + k] = __float2half_rn(sh[tx * 33 + ty + j]);
    }
}

__global__ __launch_bounds__(256)
void prep_kernel(const float* __restrict__ feat, const int* __restrict__ order,
                 const float* __restrict__ cls_tokens, const float* __restrict__ Wqkv,
                 const float* __restrict__ bqkv, const float* __restrict__ Wproj)
{
    __shared__ float sh[3072];
    const int bid = blockIdx.x;
    const int tid = threadIdx.x;

    if (bid < PREP_CLS) {
        float* ct  = sh;
        float* red = sh + 2048;
        const int lane = tid & 31, seg = tid >> 5;
        for (int i = tid; i < BB * CC; i += 256) ct[i] = cls_tokens[i];
        __syncthreads();
        const int n = bid * 32 + lane;
        float acc[BB] = {0.f, 0.f, 0.f, 0.f};
        for (int k = seg * 64; k < seg * 64 + 64; k++) {
            float w = Wqkv[(size_t)k * C3 + n];
            #pragma unroll
            for (int b = 0; b < BB; b++) acc[b] += ct[b * CC + k] * w;
        }
        #pragma unroll
        for (int b = 0; b < BB; b++) red[(seg * BB + b) * 32 + lane] = acc[b];
        __syncthreads();
        if (seg < BB) {
            float s = bqkv[n];
            #pragma unroll
            for (int j = 0; j < 8; j++) s += red[(j * BB + seg) * 32 + lane];
            g_clsqkv[seg * C3 + n] = s;
        }
    } else if (bid < PREP_WQ) {
        int idx = bid - PREP_CLS;
        do_conv_wt(Wqkv, g_WqkvT, CC, C3, idx % 48, idx / 48, sh);
    } else if (bid < PREP_WP) {
        int idx = bid - PREP_WQ;
        do_conv_wt(Wproj, g_WprojT, CC, CC, idx % 16, idx / 16, sh);
    } else {
        // ---- feat gather -> fp16 (4 float4 per thread) ----
        size_t base = (size_t)(bid - PREP_WP) * 1024 + tid;
        #pragma unroll
        for (int it = 0; it < 4; it++) {
            size_t idx = base + it * 256;
            int m = (int)(idx >> 7);
            int u = (int)(idx & 127);
            const float4 v = *(const float4*)(feat + (size_t)order[m] * CC + u * 4);
            *(uint2*)(g_Ah + (size_t)m * CC + u * 4) =
                make_uint2(pack_h2(v.x, v.y), pack_h2(v.z, v.w));
        }
    }
}

// ---- cp.async GEMM: 128x128 tile, Kc=64, 3 stages, single fp16, 2 CTAs/SM ----
// proj instantiation (CLSFUSE) carries an extra grid row doing the cls reduction.
#define QROWB  144
#define QTILE  (128 * QROWB)       // 18432
#define QSTAGE (2 * QTILE)         // 36864 (A | B)
#define SMHDR  1024
#define GSMEM  (SMHDR + 3 * QSTAGE)   // 111616

template<bool SCATTER, bool OUTHALF, bool CLSFUSE>
__global__ __launch_bounds__(256, 2)
void gemm_async_kernel(const __half* __restrict__ Ah, const __half* __restrict__ Bh,
                       const float* __restrict__ bias, void* __restrict__ Cv,
                       const int* __restrict__ order, int Ntot,
                       const int* __restrict__ offset, float* __restrict__ out_cls)
{
    extern __shared__ char sm[];
    const uint32_t sb = smem_u32(sm);
    const int tid = threadIdx.x, wid = tid >> 5, lane = tid & 31;

    if (CLSFUSE && blockIdx.y == NPTS / 128) {
        // ---- cls reduce: 4 blocks x 256 threads x 2 items = 2048 ----
        #pragma unroll
        for (int it = 0; it < 2; it++) {
            int gid = blockIdx.x * 512 + it * 256 + tid;
            int b = gid >> 9;
            int c = gid & (CC - 1);
            int start = (b == 0) ? 0 : offset[b - 1];
            int end = offset[b];
            int ch0 = start / KK, ch1 = end / KK;
            float s = 0.f;
            for (int ch = ch0; ch < ch1; ch++) s += g_clspart[ch * CC + c];
            out_cls[gid] = s / (float)(ch1 - ch0);
        }
        return;
    }

    const int n0 = blockIdx.x * 128, m0 = blockIdx.y * 128;
    float* bias_s = (float*)sm;
    int*   rowidx = (int*)(sm + 512);

    auto issue_stage = [&](int c, int stage) {
        const size_t kb = (size_t)c * 128;
        const uint32_t dbase = sb + SMHDR + stage * QSTAGE;
        #pragma unroll
        for (int i = 0; i < 8; i++) {
            const int g = tid + i * 256;
            const int tile = g >> 10;
            const int u = g & 1023;
            const int row = u >> 3, col8 = u & 7;
            const char* src = (const char*)(tile ? Bh + (size_t)(n0 + row) * CC
                                                 : Ah + (size_t)(m0 + row) * CC) + kb;
            cp_async16(dbase + tile * QTILE + row * QROWB + col8 * 16, src + col8 * 16);
        }
    };

    issue_stage(0, 0); CP_COMMIT();
    issue_stage(1, 1); CP_COMMIT();

    if (tid < 128) {
        bias_s[tid] = bias[n0 + tid];
        if (SCATTER) rowidx[tid] = order[m0 + tid];
    }
    __syncthreads();

    const int wm = (wid & 1) * 64;
    const int wn = (wid >> 1) * 32;

    float acc[4][4][4];
    #pragma unroll
    for (int nt = 0; nt < 4; nt++) {
        float b0 = bias_s[wn + nt * 8 + 2 * (lane & 3)];
        float b1 = bias_s[wn + nt * 8 + 2 * (lane & 3) + 1];
        #pragma unroll
        for (int mt = 0; mt < 4; mt++) {
            acc[mt][nt][0] = b0; acc[mt][nt][1] = b1;
            acc[mt][nt][2] = b0; acc[mt][nt][3] = b1;
        }
    }

    const uint32_t a_lm  = sb + SMHDR + (wm + (lane & 15)) * QROWB + ((lane >> 4) & 1) * 16;
    const uint32_t b_lm4 = sb + SMHDR + QTILE
                           + (wn + (lane & 7) + ((lane >> 4) & 1) * 8) * QROWB
                           + ((lane >> 3) & 1) * 16;

    const int NC = CC / 64;   // 8
    #pragma unroll 1
    for (int c = 0; c < NC; c++) {
        CP_WAIT1();
        __syncthreads();
        if (c + 2 < NC) issue_stage(c + 2, (c + 2) % 3);
        CP_COMMIT();

        const uint32_t abase = a_lm  + (c % 3) * QSTAGE;
        const uint32_t bbase = b_lm4 + (c % 3) * QSTAGE;
        #pragma unroll
        for (int ks = 0; ks < 4; ks++) {
            const int ko = ks * 32;
            uint32_t ah[4][4], bh[2][4];
            #pragma unroll
            for (int mt = 0; mt < 4; mt++)
                ldsm_x4(ah[mt], abase + mt * 16 * QROWB + ko);
            #pragma unroll
            for (int p = 0; p < 2; p++)
                ldsm_x4(bh[p], bbase + p * 16 * QROWB + ko);
            #pragma unroll
            for (int mt = 0; mt < 4; mt++)
                #pragma unroll
                for (int nt = 0; nt < 4; nt++)
                    mma_f16(acc[mt][nt], ah[mt], &bh[nt >> 1][(nt & 1) * 2]);
        }
    }

    #pragma unroll
    for (int mt = 0; mt < 4; mt++) {
        int lrow = wm + mt * 16 + (lane >> 2);
        int d0 = SCATTER ? rowidx[lrow]     : (m0 + lrow);
        int d1 = SCATTER ? rowidx[lrow + 8] : (m0 + lrow + 8);
        #pragma unroll
        for (int nt = 0; nt < 4; nt++) {
            int col = n0 + wn + nt * 8 + 2 * (lane & 3);
            if (OUTHALF) {
                __half* C = (__half*)Cv;
                *(uint32_t*)(C + (size_t)d0 * Ntot + col) =
                    pack_h2(acc[mt][nt][0], acc[mt][nt][1]);
                *(uint32_t*)(C + (size_t)d1 * Ntot + col) =
                    pack_h2(acc[mt][nt][2], acc[mt][nt][3]);
            } else {
                float* C = (float*)Cv;
                *(float2*)(C + (size_t)d0 * Ntot + col) =
                    make_float2(acc[mt][nt][0], acc[mt][nt][1]);
                *(float2*)(C + (size_t)d1 * Ntot + col) =
                    make_float2(acc[mt][nt][2], acc[mt][nt][3]);
            }
        }
    }
}

// ------- tensor-core attention (online softmax, 2 KV halves) + fused cls -------
#define NP 272
#define KROWB 144
#define SM_KV   (2 * NP * KROWB)          // 78336
#define SM_QCS  SM_KV                      // 64 floats (cls query, scaled)
#define SM_SC   (SM_QCS + 256)             // 260 floats (cls scores / probs + inv)
#define SM_RED  (SM_SC + 1040)             // 256 floats (PV partials)
#define SM_QST  (SM_RED + 1024)            // 8 warps x 16 rows x 144B Q staging
#define ATT_SMEM (SM_QST + 8 * 16 * KROWB) // 99088

__global__ __launch_bounds__(256, 2)
void attn_mma_kernel(const int* __restrict__ offset)
{
    extern __shared__ char sm[];
    char* KhB = sm;
    char* VhB = sm + NP * KROWB;
    float* qcs = (float*)(sm + SM_QCS);
    float* sc  = (float*)(sm + SM_SC);
    float* red = (float*)(sm + SM_RED);
    const uint32_t sb = smem_u32(sm);
    const uint32_t KhU = sb;
    const uint32_t VhU = sb + NP * KROWB;

    const int ci = blockIdx.x, h = blockIdx.y, tid = threadIdx.x;
    const int wid = tid >> 5, lane = tid & 31;
    const int cs = ci * KK;
    int b = 0;
    #pragma unroll
    for (int j = 0; j < BB; j++) b += (offset[j] <= cs) ? 1 : 0;
    const __half* qkvh   = g_qkv_h + (size_t)cs * C3;
    const float*  clsrow = g_clsqkv + b * C3;
    const int koff = CC + h * DH, voff = 2 * CC + h * DH;

    // load K,V rows -> smem fp16: token rows via cp.async, cls row converted, pad zeroed
    for (int idx = tid; idx < 2 * NP * 8; idx += 256) {
        int kv = idx >= NP * 8;
        int i  = kv ? idx - NP * 8 : idx;
        int t = i >> 3, u = i & 7;
        int off = kv ? voff : koff;
        uint32_t dst = (kv ? VhU : KhU) + t * KROWB + u * 16;
        if (t == 0) {
            const float* src = clsrow + off + u * 8;
            uint4 val;
            val.x = pack_h2(src[0], src[1]);
            val.y = pack_h2(src[2], src[3]);
            val.z = pack_h2(src[4], src[5]);
            val.w = pack_h2(src[6], src[7]);
            *(uint4*)((kv ? VhB : KhB) + t * KROWB + u * 16) = val;
        } else if (t <= KK) {
            cp_async16(dst, qkvh + (size_t)(t - 1) * C3 + off + u * 8);
        } else {
            *(uint4*)((kv ? VhB : KhB) + t * KROWB + u * 16) =
                make_uint4(0u, 0u, 0u, 0u);
        }
    }
    CP_COMMIT();
    if (tid < 64) qcs[tid] = clsrow[h * DH + tid] * 0.125f;
    CP_WAIT0();
    __syncthreads();

    // ===== fused cls-query attention (uses smem K/V) =====
    for (int j = tid; j < 257; j += 256) {
        float s = 0.f;
        #pragma unroll
        for (int u = 0; u < 8; u++) {
            uint4 k4 = *(const uint4*)(KhB + j * KROWB + u * 16);
            const __half2* h2 = (const __half2*)&k4;
            #pragma unroll
            for (int e = 0; e < 4; e++) {
                float2 kf = __half22float2(h2[e]);
                s += qcs[u * 8 + e * 2] * kf.x + qcs[u * 8 + e * 2 + 1] * kf.y;
            }
        }
        sc[j] = s;
    }
    __syncthreads();
    if (wid == 0) {
        float m = -1e30f;
        for (int j = lane; j < 257; j += 32) m = fmaxf(m, sc[j]);
        #pragma unroll
        for (int o = 16; o; o >>= 1) m = fmaxf(m, __shfl_xor_sync(0xffffffffu, m, o));
        float ssum = 0.f;
        for (int j = lane; j < 257; j += 32) {
            float e = __expf(sc[j] - m);
            sc[j] = e;
            ssum += e;
        }
        #pragma unroll
        for (int o = 16; o; o >>= 1) ssum += __shfl_xor_sync(0xffffffffu, ssum, o);
        if (lane == 0) sc[258] = 1.f / ssum;
    }
    __syncthreads();
    {   // PV: 4 key-groups x 64 dims
        const int g = tid >> 6, d = tid & 63;
        const int j0 = g * 64, cnt = (g == 3) ? 65 : 64;
        float acc = 0.f;
        for (int jj = 0; jj < cnt; jj++) {
            int j = j0 + jj;
            acc += sc[j] * __half2float(*(const __half*)(VhB + j * KROWB + d * 2));
        }
        red[g * 64 + d] = acc;
    }
    __syncthreads();
    if (tid < 64) {
        float inv = sc[258];
        float r = (red[tid] + red[64 + tid] + red[128 + tid] + red[192 + tid]) * inv;
        g_clspart[ci * CC + h * DH + tid] = r;
    }

    // ===== token-query attention (online softmax over 2 KV halves) =====
    const int r0 = lane >> 2;
    const int qp = (lane & 3) * 2;
    char* qstB = sm + SM_QST + wid * (16 * KROWB);
    const uint32_t qstU = sb + SM_QST + wid * (16 * KROWB);
    const uint32_t q_lm = qstU + (lane & 15) * KROWB + ((lane >> 4) & 1) * 16;

    #pragma unroll 1
    for (int mt = wid; mt < 16; mt += 8) {
        const __half* qbase = qkvh + (size_t)(mt * 16) * C3 + h * DH;
        __syncwarp();
        #pragma unroll
        for (int u = 0; u < 4; u++) {
            int g = lane + u * 32;
            int row = g >> 3, c8 = g & 7;
            *(uint4*)(qstB + row * KROWB + c8 * 16) =
                *(const uint4*)(qbase + (size_t)row * C3 + c8 * 8);
        }
        __syncwarp();

        float o[8][4];
        #pragma unroll
        for (int nt = 0; nt < 8; nt++)
            o[nt][0] = o[nt][1] = o[nt][2] = o[nt][3] = 0.f;
        float mr0 = -1e30f, mr1 = -1e30f, sr0 = 0.f, sr1 = 0.f;

        #pragma unroll 1
        for (int half = 0; half < 2; half++) {
            float acc[18][4];
            #pragma unroll
            for (int nt = 0; nt < 18; nt++)
                acc[nt][0] = acc[nt][1] = acc[nt][2] = acc[nt][3] = 0.f;

            #pragma unroll
            for (int kt = 0; kt < 4; kt++) {
                uint32_t qh[4];
                ldsm_x4(qh, q_lm + kt * 32);
                const uint32_t kaddr4 = KhU
                    + ((lane & 7) + ((lane >> 4) & 1) * 8) * KROWB
                    + ((lane >> 3) & 1) * 16 + kt * 32
                    + half * (8 * 16 * KROWB);
                #pragma unroll
                for (int p = 0; p < 8; p++) {
                    uint32_t b4[4];
                    ldsm_x4(b4, kaddr4 + p * 16 * KROWB);
                    mma_f16(acc[2 * p],     qh, &b4[0]);
                    mma_f16(acc[2 * p + 1], qh, &b4[2]);
                }
                if (half == 1) {
                    uint32_t b4[4];
                    ldsm_x4(b4, kaddr4 + 8 * 16 * KROWB);
                    mma_f16(acc[16], qh, &b4[0]);
                }
            }

            const int NT = half ? 17 : 16;
            if (half == 1) {
                if (qp != 0) { acc[16][0] = -1e30f; acc[16][2] = -1e30f; }
                acc[16][1] = -1e30f; acc[16][3] = -1e30f;
            }

            float lm0 = -1e30f, lm1 = -1e30f;
            #pragma unroll
            for (int nt = 0; nt < 17; nt++) {
                if (nt >= NT) break;
                lm0 = fmaxf(lm0, fmaxf(acc[nt][0], acc[nt][1]));
                lm1 = fmaxf(lm1, fmaxf(acc[nt][2], acc[nt][3]));
            }
            lm0 = fmaxf(lm0, __shfl_xor_sync(0xffffffffu, lm0, 1));
            lm0 = fmaxf(lm0, __shfl_xor_sync(0xffffffffu, lm0, 2));
            lm1 = fmaxf(lm1, __shfl_xor_sync(0xffffffffu, lm1, 1));
            lm1 = fmaxf(lm1, __shfl_xor_sync(0xffffffffu, lm1, 2));
            const float nm0 = fmaxf(mr0, lm0), nm1 = fmaxf(mr1, lm1);
            const float f0 = __expf(0.125f * (mr0 - nm0));
            const float f1 = __expf(0.125f * (mr1 - nm1));
            mr0 = nm0; mr1 = nm1;
            const float mm0 = nm0 * 0.125f, mm1 = nm1 * 0.125f;
            float ls0 = 0.f, ls1 = 0.f;
            #pragma unroll
            for (int nt = 0; nt < 17; nt++) {
                if (nt >= NT) break;
                acc[nt][0] = __expf(fmaf(acc[nt][0], 0.125f, -mm0));
                acc[nt][1] = __expf(fmaf(acc[nt][1], 0.125f, -mm0));
                acc[nt][2] = __expf(fmaf(acc[nt][2], 0.125f, -mm1));
                acc[nt][3] = __expf(fmaf(acc[nt][3], 0.125f, -mm1));
                ls0 += acc[nt][0] + acc[nt][1];
                ls1 += acc[nt][2] + acc[nt][3];
            }
            acc[17][0] = acc[17][1] = acc[17][2] = acc[17][3] = 0.f;
            if (half == 0) {
                acc[16][0] = acc[16][1] = acc[16][2] = acc[16][3] = 0.f;
            }
            ls0 += __shfl_xor_sync(0xffffffffu, ls0, 1);
            ls0 += __shfl_xor_sync(0xffffffffu, ls0, 2);
            ls1 += __shfl_xor_sync(0xffffffffu, ls1, 1);
            ls1 += __shfl_xor_sync(0xffffffffu, ls1, 2);
            sr0 = sr0 * f0 + ls0;
            sr1 = sr1 * f1 + ls1;
            #pragma unroll
            for (int nt = 0; nt < 8; nt++) {
                o[nt][0] *= f0; o[nt][1] *= f0;
                o[nt][2] *= f1; o[nt][3] *= f1;
            }

            const int NKT = half ? 9 : 8;
            #pragma unroll
            for (int ktl = 0; ktl < 9; ktl++) {
                if (ktl >= NKT) break;
                uint32_t ah[4];
                ah[0] = pack_h2(acc[2*ktl][0],   acc[2*ktl][1]);
                ah[1] = pack_h2(acc[2*ktl][2],   acc[2*ktl][3]);
                ah[2] = pack_h2(acc[2*ktl+1][0], acc[2*ktl+1][1]);
                ah[3] = pack_h2(acc[2*ktl+1][2], acc[2*ktl+1][3]);
                const uint32_t vaddr4 = VhU
                    + ((half * 8 + ktl) * 16 + (lane & 15)) * KROWB
                    + ((lane >> 4) & 1) * 16;
                #pragma unroll
                for (int p = 0; p < 4; p++) {
                    uint32_t b4[4];
                    ldsm_x4_t(b4, vaddr4 + p * 32);
                    mma_f16(o[2 * p],     ah, &b4[0]);
                    mma_f16(o[2 * p + 1], ah, &b4[2]);
                }
            }
        }

        const float inv0 = 1.f / sr0, inv1 = 1.f / sr1;
        const size_t row0 = (size_t)(cs + mt * 16 + r0) * CC + h * DH;
        const size_t row1 = row0 + 8 * CC;
        #pragma unroll
        for (int nt = 0; nt < 8; nt++) {
            *(uint32_t*)(g_att_h + row0 + nt * 8 + qp) =
                pack_h2(o[nt][0] * inv0, o[nt][1] * inv0);
            *(uint32_t*)(g_att_h + row1 + nt * 8 + qp) =
                pack_h2(o[nt][2] * inv1, o[nt][3] * inv1);
        }
    }
}

// ---------------- launch ----------------
extern "C" void kernel_launch(void* const* d_in, const int* in_sizes, int n_in,
                              void* d_out, int out_size)
{
    const float* feat       = (const float*)d_in[0];
    const float* cls_tokens = (const float*)d_in[1];
    const float* Wqkv       = (const float*)d_in[2];
    const float* bqkv       = (const float*)d_in[3];
    const float* Wproj      = (const float*)d_in[4];
    const float* bproj      = (const float*)d_in[5];
    const int*   order      = (const int*)d_in[6];
    const int*   offset     = (const int*)d_in[8];

    float* out_feat = (float*)d_out;
    float* out_cls  = out_feat + (size_t)NPTS * CC;

    void *qkvp = nullptr;
    void *ah = nullptr, *ath = nullptr;
    void *wq = nullptr, *wp = nullptr;
    cudaGetSymbolAddress(&qkvp, g_qkv_h);
    cudaGetSymbolAddress(&ah, g_Ah);
    cudaGetSymbolAddress(&ath, g_att_h);
    cudaGetSymbolAddress(&wq, g_WqkvT);
    cudaGetSymbolAddress(&wp, g_WprojT);

    cudaFuncSetAttribute(attn_mma_kernel, cudaFuncAttributeMaxDynamicSharedMemorySize,
                         ATT_SMEM);
    cudaFuncSetAttribute(gemm_async_kernel<false, true, false>,
                         cudaFuncAttributeMaxDynamicSharedMemorySize, GSMEM);
    cudaFuncSetAttribute(gemm_async_kernel<true, false, true>,
                         cudaFuncAttributeMaxDynamicSharedMemorySize, GSMEM);

    // 0+1. fused prep: cls_qkv + W transposes + feat gather (one launch)
    prep_kernel<<<PREP_GRID, 256>>>(feat, order, cls_tokens, Wqkv, bqkv, Wproj);
    // 2. qkv GEMM -> fp16 output
    gemm_async_kernel<false, true, false><<<dim3(C3 / 128, NPTS / 128), 256, GSMEM>>>(
        (const __half*)ah, (const __half*)wq, bqkv, qkvp, order, C3, nullptr, nullptr);
    // 3. attention (token queries, online softmax + fused cls query)
    attn_mma_kernel<<<dim3(NCH, HH), 256, ATT_SMEM>>>(offset);
    // 4. proj GEMM with scatter -> fp32 output, + fused cls reduction row
    gemm_async_kernel<true, false, true><<<dim3(CC / 128, NPTS / 128 + 1), 256, GSMEM>>>(
        (const __half*)ath, (const __half*)wp, bproj, (void*)out_feat, order, CC,
        offset, out_cls);
}